// round 12
// baseline (speedup 1.0000x reference)
#include <cuda_runtime.h>
#include <math.h>

#define NB   128   // N dialogues
#define LSEQ 64    // L
#define EDIM 300
#define HDIM 300
#define KF   40    // KEFF
#define NQ   127   // N-1
#define NHOPS 3
#define NCLS 6

typedef unsigned long long u64;

// ---------------- scratch (device globals; no allocation) ----------------
__device__ float g_gi_utt[(size_t)LSEQ * NB * 1800];     // [t*128+b, 1800]
__device__ float g_h_utt[2][2 * NB * HDIM];
__device__ float g_maxpool[NB * 2 * HDIM];
__device__ float g_u[NB * HDIM];
__device__ float g_inp0[KF * NQ * HDIM];                 // ctx_t time-major
__device__ float g_gi_ctx[(size_t)KF * NQ * 1800];
__device__ float g_seq_ctx[2 * KF * NQ * HDIM];          // [dir, t, i, j]
__device__ float g_h_ctx[2][2 * NQ * HDIM];
__device__ float g_mem[KF * NQ * HDIM];                  // time-major [k,i,j]
__device__ float g_xr[(size_t)KF * NQ * 1800];
__device__ float g_xw[(size_t)KF * NQ * 1800];
__device__ float g_gates[KF * NQ];
__device__ float g_query[NQ * HDIM];
__device__ float g_h_att[2][2 * NQ * HDIM];

// group barrier state: 4 groups, padded to separate 128B lines
__device__ unsigned g_cnt[128];   // zero-initialized; returns to 0 each use
__device__ unsigned g_gen[128];   // monotonic forever (never reset)

__device__ __forceinline__ float sigf(float x) { return 1.f / (1.f + expf(-x)); }

// ---------------- packed f32x2 helpers ----------------
__device__ __forceinline__ u64 pk2(float x, float y) {
    u64 r; asm("mov.b64 %0, {%1, %2};" : "=l"(r) : "f"(x), "f"(y)); return r;
}
__device__ __forceinline__ float2 unpk(u64 v) {
    float2 f; asm("mov.b64 {%0, %1}, %2;" : "=f"(f.x), "=f"(f.y) : "l"(v)); return f;
}
__device__ __forceinline__ u64 f2fma(u64 a, u64 b, u64 c) {
    u64 d; asm("fma.rn.f32x2 %0, %1, %2, %3;" : "=l"(d) : "l"(a), "l"(b), "l"(c));
    return d;
}
__device__ __forceinline__ u64 f2add(u64 a, u64 b) {
    u64 d; asm("add.rn.f32x2 %0, %1, %2;" : "=l"(d) : "l"(a), "l"(b));
    return d;
}
__device__ __forceinline__ float hsum2(u64 v) {
    float2 f = unpk(v); return f.x + f.y;
}

// 30-block group barrier. gslot = group*32. target = gen0 + barrier_index.
// Writers: every thread fences its own stores, then tid0 arrives; the 30th
// arriver resets cnt and bumps gen; others spin on gen (monotonic, so the
// base captured at kernel entry is race-free: gen can only advance after ALL
// 30 blocks arrive, and each block captures base before its first arrive).
__device__ __forceinline__ void group_barrier(int gslot, unsigned target) {
    __threadfence();
    __syncthreads();
    if (threadIdx.x == 0) {
        unsigned old = atomicAdd(&g_cnt[gslot], 1u);
        if (old == 29u) {
            atomicExch(&g_cnt[gslot], 0u);
            __threadfence();
            atomicAdd(&g_gen[gslot], 1u);
        } else {
            while (atomicAdd(&g_gen[gslot], 0u) < target) __nanosleep(64);
        }
        __threadfence();
    }
    __syncthreads();
}

// ---------------- GEMM (f32x2): C = A(MxK) @ W(NxK)^T + bias ----------------
#define GTM 64
#define GTN 64
#define GTK 16

template<int GATHER>
__global__ __launch_bounds__(256)
void gemm3(const float* __restrict__ A, int lda,
           const float* __restrict__ W,
           const float* __restrict__ bias,
           float* __restrict__ C, int ldc,
           int M, int N, int K,
           const float* __restrict__ emb,
           const int* __restrict__ ids)
{
    __shared__ __align__(16) u64   Ad[GTK][66];   // A dup'd: (a,a) per [kk][mm]
    __shared__ __align__(16) float Bs[GTK][66];
    __shared__ int rowid[GTM];
    const int tid = threadIdx.x;
    const int m0 = blockIdx.y * GTM;
    const int n0 = blockIdx.x * GTN;

    if (GATHER) {
        if (tid < GTM) {
            int m = m0 + tid;
            int t = m >> 7, b = m & 127;          // m = t*128 + b
            rowid[tid] = (m < M) ? ids[b * LSEQ + t] : 0;
        }
        __syncthreads();
    }

    u64 acc[4][2] = {};
    const int mt = tid >> 4;   // 0..15
    const int nt = tid & 15;   // 0..15

    for (int k0 = 0; k0 < K; k0 += GTK) {
#pragma unroll
        for (int i = 0; i < 4; i++) {
            int idx = tid + i * 256;
            int mm = idx >> 4, kk = idx & 15;
            int m = m0 + mm, k = k0 + kk;
            float v = 0.f;
            if (m < M && k < K) {
                if (GATHER) v = emb[(size_t)rowid[mm] * K + k];
                else        v = A[(size_t)m * lda + k];
            }
            Ad[kk][mm] = pk2(v, v);
        }
#pragma unroll
        for (int i = 0; i < 4; i++) {
            int idx = tid + i * 256;
            int nn = idx >> 4, kk = idx & 15;
            int n = n0 + nn, k = k0 + kk;
            Bs[kk][nn] = (n < N && k < K) ? W[(size_t)n * K + k] : 0.f;
        }
        __syncthreads();
#pragma unroll
        for (int kk = 0; kk < GTK; kk++) {
            ulonglong2 a01 = *(const ulonglong2*)&Ad[kk][mt * 4];
            ulonglong2 a23 = *(const ulonglong2*)&Ad[kk][mt * 4 + 2];
            u64 b0 = *(const u64*)&Bs[kk][nt * 4];
            u64 b1 = *(const u64*)&Bs[kk][nt * 4 + 2];
            acc[0][0] = f2fma(a01.x, b0, acc[0][0]);
            acc[0][1] = f2fma(a01.x, b1, acc[0][1]);
            acc[1][0] = f2fma(a01.y, b0, acc[1][0]);
            acc[1][1] = f2fma(a01.y, b1, acc[1][1]);
            acc[2][0] = f2fma(a23.x, b0, acc[2][0]);
            acc[2][1] = f2fma(a23.x, b1, acc[2][1]);
            acc[3][0] = f2fma(a23.y, b0, acc[3][0]);
            acc[3][1] = f2fma(a23.y, b1, acc[3][1]);
        }
        __syncthreads();
    }
#pragma unroll
    for (int i = 0; i < 4; i++) {
        int m = m0 + mt * 4 + i;
        if (m >= M) continue;
#pragma unroll
        for (int p = 0; p < 2; p++) {
            float2 v = unpk(acc[i][p]);
            int n = n0 + nt * 4 + 2 * p;
            if (n < N)     C[(size_t)m * ldc + n]     = v.x + bias[n];
            if (n + 1 < N) C[(size_t)m * ldc + n + 1] = v.y + bias[n + 1];
        }
    }
}

// ---------------- persistent GRU scan v5 ----------------
// Grid (30 jgrp, 2 bgrp, 2 dir) = 120 blocks, 960 thr, 1 block/SM -> all
// resident. Barrier group = 30 jgrp blocks sharing (bgrp,dir). Weights staged
// in smem ONCE; h staged per step via __ldcg (L1 stale inside one kernel!);
// hold read from smem; maxpool held in registers across all steps.
// MODE 0: utt | MODE 1: ctx (seqout)
template<int MODE>
__global__ __launch_bounds__(960, 1)
void gru_scan5(float* __restrict__ h0, float* __restrict__ h1,
               const float* __restrict__ gi,      // [T*B, 1800]
               const float* __restrict__ Whh,     // [2,900,300]
               const float* __restrict__ bhh,     // [2,900]
               const int*   __restrict__ seq_lens,
               float* __restrict__ maxpool,       // [B, 600]
               float* __restrict__ seqout,        // [2,T,B,300]
               int B, int T)
{
    extern __shared__ float sm[];
    float* Ws = sm;                      // 9000 floats (persists across steps)
    float* Hs = sm + 9000;               // 19200 floats
    u64*   red = (u64*)(sm + 28200);     // 3840 u64 (separate scratch)

    const int tid    = threadIdx.x;
    const int brow   = tid & 31;
    const int uu     = (tid >> 5) % 10;
    const int kthird = tid / 320;
    const int jgrp = blockIdx.x, bgrp = blockIdx.y, dir = blockIdx.z;
    const int j = jgrp * 10 + uu;
    const int dirbase = dir * B * HDIM;
    const int b0 = bgrp * 64;
    const int b_lo = b0 + brow, b_hi = b_lo + 32;
    const int gslot = (dir * 2 + bgrp) * 32;

    const unsigned gen0 = atomicAdd(&g_gen[gslot], 0u);   // race-free base

    // stage weights once: 30 rows x 75 float4
    for (int idx = tid; idx < 2250; idx += 960) {
        int row = idx / 75, q = idx % 75;
        int g = row / 10, ju = row % 10;
        ((float4*)Ws)[row * 75 + q] = ((const float4*)(Whh +
            ((size_t)dir * 900 + g * 300 + jgrp * 10 + ju) * 300))[q];
    }
    const float bhr = bhh[dir * 900 + j];
    const float bhz = bhh[dir * 900 + 300 + j];
    const float bhn = bhh[dir * 900 + 600 + j];
    const bool okA = (b_lo < B), okB = (b_hi < B);
    int lenA = T, lenB = T;
    if (MODE == 0) {
        lenA = okA ? seq_lens[b_lo] : 1;
        lenB = okB ? seq_lens[b_hi] : 1;
    }
    float mpA = -1e30f, mpB = -1e30f;

    int cur = 0;
    for (int t = 0; t < T; t++) {
        const float* hp = cur ? h1 : h0;
        float*       hn = cur ? h0 : h1;

        if (t > 0) {
            // stage h: 64 rows x 75 float4, L2 reads (written by other SMs)
            for (int idx = tid; idx < 4800; idx += 960) {
                int bl = idx / 75, q = idx % 75;
                int b = b0 + bl;
                float4 v = make_float4(0.f, 0.f, 0.f, 0.f);
                if (b < B) v = __ldcg(((const float4*)(hp + dirbase + (size_t)b * 300)) + q);
                ((float4*)Hs)[idx] = v;
            }
        }

        // epilogue gi prefetch (kthird==0 threads own the epilogue)
        float grA0 = 0.f, grA1 = 0.f, grA2 = 0.f;
        float grB0 = 0.f, grB1 = 0.f, grB2 = 0.f;
        if (kthird == 0) {
            if (okA) {
                int trow = (MODE == 0) ? ((dir == 0) ? t : max(lenA - 1 - t, 0))
                                       : ((dir == 0) ? t : (T - 1 - t));
                const float* gr = gi + ((size_t)trow * B + b_lo) * 1800 + dir * 900 + j;
                grA0 = gr[0]; grA1 = gr[300]; grA2 = gr[600];
            }
            if (okB) {
                int trow = (MODE == 0) ? ((dir == 0) ? t : max(lenB - 1 - t, 0))
                                       : ((dir == 0) ? t : (T - 1 - t));
                const float* gr = gi + ((size_t)trow * B + b_hi) * 1800 + dir * 900 + j;
                grB0 = gr[0]; grB1 = gr[300]; grB2 = gr[600];
            }
        }
        __syncthreads();

        u64 arA = 0ULL, azA = 0ULL, anA = 0ULL;
        u64 arB = 0ULL, azB = 0ULL, anB = 0ULL;
        float holdA = 0.f, holdB = 0.f;
        if (t > 0) {
            const ulonglong2* wr = (const ulonglong2*)(Ws + uu * 300 + kthird * 100);
            const ulonglong2* hA = (const ulonglong2*)(Hs + brow * 300 + kthird * 100);
#pragma unroll 5
            for (int q = 0; q < 25; q++) {
                ulonglong2 w0 = wr[q], w1 = wr[q + 750], w2 = wr[q + 1500];
                ulonglong2 ha = hA[q], hb = hA[q + 2400];
                arA = f2fma(ha.x, w0.x, arA); arA = f2fma(ha.y, w0.y, arA);
                azA = f2fma(ha.x, w1.x, azA); azA = f2fma(ha.y, w1.y, azA);
                anA = f2fma(ha.x, w2.x, anA); anA = f2fma(ha.y, w2.y, anA);
                arB = f2fma(hb.x, w0.x, arB); arB = f2fma(hb.y, w0.y, arB);
                azB = f2fma(hb.x, w1.x, azB); azB = f2fma(hb.y, w1.y, azB);
                anB = f2fma(hb.x, w2.x, anB); anB = f2fma(hb.y, w2.y, anB);
            }
            if (kthird == 0) {       // hold from smem (already staged)
                holdA = okA ? Hs[brow * 300 + j] : 0.f;
                holdB = okB ? Hs[(brow + 32) * 300 + j] : 0.f;
            }
            __syncthreads();
            if (kthird > 0) {
                int s6 = ((kthird - 1) * 320 + (tid - 320 * kthird)) * 6;
                red[s6 + 0] = arA; red[s6 + 1] = azA; red[s6 + 2] = anA;
                red[s6 + 3] = arB; red[s6 + 4] = azB; red[s6 + 5] = anB;
            }
            __syncthreads();
            if (kthird == 0) {
#pragma unroll
                for (int kt = 0; kt < 2; kt++) {
                    int s6 = (kt * 320 + tid) * 6;
                    arA = f2add(arA, red[s6 + 0]);
                    azA = f2add(azA, red[s6 + 1]);
                    anA = f2add(anA, red[s6 + 2]);
                    arB = f2add(arB, red[s6 + 3]);
                    azB = f2add(azB, red[s6 + 4]);
                    anB = f2add(anB, red[s6 + 5]);
                }
            }
        }

        if (kthird == 0) {
            if (okA) {
                bool mA = (MODE != 0) || (t < lenA);
                float r = sigf(grA0 + hsum2(arA) + bhr);
                float z = sigf(grA1 + hsum2(azA) + bhz);
                float n = tanhf(grA2 + r * (hsum2(anA) + bhn));
                float hnew = (1.f - z) * n + z * holdA;
                if (MODE == 0) {
                    hn[dirbase + (size_t)b_lo * 300 + j] = mA ? hnew : holdA;
                    mpA = fmaxf(mpA, mA ? hnew : 0.f);
                } else {
                    hn[dirbase + (size_t)b_lo * 300 + j] = hnew;
                    seqout[(((size_t)dir * T + t) * B + b_lo) * 300 + j] = hnew;
                }
            }
            if (okB) {
                bool mB = (MODE != 0) || (t < lenB);
                float r = sigf(grB0 + hsum2(arB) + bhr);
                float z = sigf(grB1 + hsum2(azB) + bhz);
                float n = tanhf(grB2 + r * (hsum2(anB) + bhn));
                float hnew = (1.f - z) * n + z * holdB;
                if (MODE == 0) {
                    hn[dirbase + (size_t)b_hi * 300 + j] = mB ? hnew : holdB;
                    mpB = fmaxf(mpB, mB ? hnew : 0.f);
                } else {
                    hn[dirbase + (size_t)b_hi * 300 + j] = hnew;
                    seqout[(((size_t)dir * T + t) * B + b_hi) * 300 + j] = hnew;
                }
            }
        }
        cur ^= 1;
        if (t < T - 1) group_barrier(gslot, gen0 + (unsigned)t + 1u);
    }

    if (MODE == 0 && kthird == 0) {
        if (okA) maxpool[b_lo * (2 * HDIM) + dir * HDIM + j] = mpA;
        if (okB) maxpool[b_hi * (2 * HDIM) + dir * HDIM + j] = mpB;
    }
}

// ---------------- persistent attention-GRU scan v5 (one hop) ----------------
__global__ __launch_bounds__(960, 1)
void att_scan5(float* __restrict__ h0, float* __restrict__ h1,
               const float* __restrict__ xr,   // [40*127, 1800]
               const float* __restrict__ xw,
               const float* __restrict__ Ur,   // [3,2,300,300]
               const float* __restrict__ Uw,
               const float* __restrict__ bur,  // [3,2,300]
               const float* __restrict__ bu,
               const float* __restrict__ gates, // [40*127]
               int hop)
{
    extern __shared__ float sm[];
    float* Ws = sm;                      // 6000 floats (persists)
    float* Hs = sm + 6000;               // 19200 floats
    u64*   red = (u64*)(sm + 25200);     // 2560 u64

    const int tid    = threadIdx.x;
    const int brow   = tid & 31;
    const int uu     = (tid >> 5) % 10;
    const int kthird = tid / 320;
    const int jgrp = blockIdx.x, bgrp = blockIdx.y, dir = blockIdx.z;
    const int j = jgrp * 10 + uu;
    const int wd = hop * 2 + dir;
    const int dirbase = dir * NQ * HDIM;
    const int b0 = bgrp * 64;
    const int b_lo = b0 + brow, b_hi = b_lo + 32;
    const int gslot = (dir * 2 + bgrp) * 32;

    const unsigned gen0 = atomicAdd(&g_gen[gslot], 0u);

    for (int idx = tid; idx < 1500; idx += 960) {
        int row = idx / 75, q = idx % 75;
        int g = row / 10, ju = row % 10;
        const float* Wsrc = g ? Uw : Ur;
        ((float4*)Ws)[row * 75 + q] = ((const float4*)(Wsrc +
            ((size_t)wd * 300 + jgrp * 10 + ju) * 300))[q];
    }
    const float burv = bur[wd * 300 + j];
    const float buv  = bu[wd * 300 + j];
    const bool okA = (b_lo < NQ), okB = (b_hi < NQ);

    int cur = 0;
    for (int t = 0; t < KF; t++) {
        const float* hp = cur ? h1 : h0;
        float*       hn = cur ? h0 : h1;

        if (t > 0) {
            for (int idx = tid; idx < 4800; idx += 960) {
                int bl = idx / 75, q = idx % 75;
                int b = b0 + bl;
                float4 v = make_float4(0.f, 0.f, 0.f, 0.f);
                if (b < NQ) v = __ldcg(((const float4*)(hp + dirbase + (size_t)b * 300)) + q);
                ((float4*)Hs)[idx] = v;
            }
        }

        const int tt = (dir == 0) ? t : (KF - 1 - t);
        float xrA = 0.f, xwA = 0.f, gA = 0.f;
        float xrB = 0.f, xwB = 0.f, gB = 0.f;
        if (kthird == 0) {
            if (okA) {
                size_t xrow = ((size_t)tt * NQ + b_lo) * 1800 + wd * 300 + j;
                xrA = xr[xrow]; xwA = xw[xrow]; gA = gates[tt * NQ + b_lo];
            }
            if (okB) {
                size_t xrow = ((size_t)tt * NQ + b_hi) * 1800 + wd * 300 + j;
                xrB = xr[xrow]; xwB = xw[xrow]; gB = gates[tt * NQ + b_hi];
            }
        }
        __syncthreads();

        u64 arA = 0ULL, awA = 0ULL, arB = 0ULL, awB = 0ULL;
        float holdA = 0.f, holdB = 0.f;
        if (t > 0) {
            const ulonglong2* wr = (const ulonglong2*)(Ws + uu * 300 + kthird * 100);
            const ulonglong2* hA = (const ulonglong2*)(Hs + brow * 300 + kthird * 100);
#pragma unroll 5
            for (int q = 0; q < 25; q++) {
                ulonglong2 w0 = wr[q], w1 = wr[q + 750];
                ulonglong2 ha = hA[q], hb = hA[q + 2400];
                arA = f2fma(ha.x, w0.x, arA); arA = f2fma(ha.y, w0.y, arA);
                awA = f2fma(ha.x, w1.x, awA); awA = f2fma(ha.y, w1.y, awA);
                arB = f2fma(hb.x, w0.x, arB); arB = f2fma(hb.y, w0.y, arB);
                awB = f2fma(hb.x, w1.x, awB); awB = f2fma(hb.y, w1.y, awB);
            }
            if (kthird == 0) {
                holdA = okA ? Hs[brow * 300 + j] : 0.f;
                holdB = okB ? Hs[(brow + 32) * 300 + j] : 0.f;
            }
            __syncthreads();
            if (kthird > 0) {
                int s4 = ((kthird - 1) * 320 + (tid - 320 * kthird)) * 4;
                red[s4 + 0] = arA; red[s4 + 1] = awA;
                red[s4 + 2] = arB; red[s4 + 3] = awB;
            }
            __syncthreads();
            if (kthird == 0) {
#pragma unroll
                for (int kt = 0; kt < 2; kt++) {
                    int s4 = (kt * 320 + tid) * 4;
                    arA = f2add(arA, red[s4 + 0]);
                    awA = f2add(awA, red[s4 + 1]);
                    arB = f2add(arB, red[s4 + 2]);
                    awB = f2add(awB, red[s4 + 3]);
                }
            }
        }

        if (kthird == 0) {
            if (okA) {
                float r  = sigf(xrA + hsum2(arA) + burv);
                float ht = tanhf(xwA + r * (hsum2(awA) + buv));
                hn[dirbase + (size_t)b_lo * 300 + j] = gA * ht + (1.f - gA) * holdA;
            }
            if (okB) {
                float r  = sigf(xrB + hsum2(arB) + burv);
                float ht = tanhf(xwB + r * (hsum2(awB) + buv));
                hn[dirbase + (size_t)b_hi * 300 + j] = gB * ht + (1.f - gB) * holdB;
            }
        }
        cur ^= 1;
        if (t < KF - 1) group_barrier(gslot, gen0 + (unsigned)t + 1u);
    }
}

// ---------------- small kernels ----------------
__global__ __launch_bounds__(256)
void lin_kernel(const float* __restrict__ mp, const float* __restrict__ w,
                const float* __restrict__ bsc, float* __restrict__ u) {
    int b = blockIdx.x;
    __shared__ float m[600];
    for (int i = threadIdx.x; i < 600; i += 256) m[i] = mp[b * 600 + i];
    __syncthreads();
    int wid = threadIdx.x >> 5, lane = threadIdx.x & 31;
    for (int j = wid; j < HDIM; j += 8) {
        float acc = 0.f;
        const float* wr = w + (size_t)j * 600;
        for (int k = lane; k < 600; k += 32) acc += m[k] * wr[k];
        for (int o = 16; o > 0; o >>= 1) acc += __shfl_xor_sync(0xffffffffu, acc, o);
        if (lane == 0) u[b * HDIM + j] = tanhf(acc + bsc[j]);
    }
}

__global__ void build_inp0(const float* __restrict__ u, float* __restrict__ inp0) {
    int idx = blockIdx.x * blockDim.x + threadIdx.x;
    if (idx >= KF * NQ * HDIM) return;
    int j = idx % HDIM;
    int r = idx / HDIM;
    int i = r % NQ;
    int k = r / NQ;
    int src = (i + 1) - KF + k;
    inp0[idx] = (src >= 0) ? u[src * HDIM + j] : 0.f;
}

__global__ void membank_kernel(const float* __restrict__ inp0,
                               const float* __restrict__ seq,
                               float* __restrict__ mem) {
    int idx = blockIdx.x * blockDim.x + threadIdx.x;
    if (idx >= KF * NQ * HDIM) return;
    int j = idx % HDIM;
    int r = idx / HDIM;
    int i = r % NQ;
    int k = r / NQ;
    float f = seq[((size_t)k) * NQ * HDIM + i * HDIM + j];
    float b = seq[((size_t)KF + (KF - 1 - k)) * NQ * HDIM + i * HDIM + j];
    mem[idx] = inp0[idx] + f + b;
}

__global__ void score_kernel(const float* __restrict__ query,
                             const float* __restrict__ mem,
                             float* __restrict__ gates) {
    int b = blockIdx.x;                 // 0..126
    int tid = threadIdx.x;              // 128
    int lane = tid & 31, w = tid >> 5;
    __shared__ float q[HDIM];
    __shared__ float logit[KF];
    for (int i = tid; i < HDIM; i += 128) q[i] = query[b * HDIM + i];
    __syncthreads();
    for (int k = w; k < KF; k += 4) {
        const float* mrow = mem + ((size_t)k * NQ + b) * HDIM;
        float s = 0.f;
        for (int i = lane; i < HDIM; i += 32) s += q[i] * mrow[i];
        for (int o = 16; o > 0; o >>= 1) s += __shfl_xor_sync(0xffffffffu, s, o);
        if (lane == 0) logit[k] = (k >= KF - 1 - b) ? s : -1e10f;
    }
    __syncthreads();
    if (w == 0) {
        float m = -INFINITY;
        for (int k = lane; k < KF; k += 32) m = fmaxf(m, logit[k]);
        for (int o = 16; o > 0; o >>= 1) m = fmaxf(m, __shfl_xor_sync(0xffffffffu, m, o));
        float ssum = 0.f;
        for (int k = lane; k < KF; k += 32) { float e = expf(logit[k] - m); logit[k] = e; ssum += e; }
        for (int o = 16; o > 0; o >>= 1) ssum += __shfl_xor_sync(0xffffffffu, ssum, o);
        for (int k = lane; k < KF; k += 32) gates[k * NQ + b] = logit[k] / ssum;
    }
}

__global__ void add2_kernel(float* __restrict__ q,
                            const float* __restrict__ hf,
                            const float* __restrict__ hb, int n) {
    int i = blockIdx.x * blockDim.x + threadIdx.x;
    if (i < n) q[i] += hf[i] + hb[i];
}

__global__ void cls_kernel(const float* __restrict__ u,
                           const float* __restrict__ query,
                           const float* __restrict__ cls_w,
                           const float* __restrict__ cls_b,
                           float* __restrict__ out) {
    int row = blockIdx.x;               // 0..127
    int w = threadIdx.x >> 5, lane = threadIdx.x & 31;   // 192 threads = 6 warps
    const float* s = (row == 0) ? u : (query + (row - 1) * HDIM);
    float acc = 0.f;
    for (int i = lane; i < HDIM; i += 32) acc += s[i] * cls_w[w * HDIM + i];
    for (int o = 16; o > 0; o >>= 1) acc += __shfl_xor_sync(0xffffffffu, acc, o);
    if (lane == 0) out[row * NCLS + w] = acc + cls_b[w];
}

// ---------------- host orchestration ----------------
extern "C" void kernel_launch(void* const* d_in, const int* in_sizes, int n_in,
                              void* d_out, int out_size) {
    const int*   ids      = (const int*)d_in[0];
    const int*   seq_lens = (const int*)d_in[1];
    const float* emb      = (const float*)d_in[2];
    const float* utt_Wih  = (const float*)d_in[3];
    const float* utt_Whh  = (const float*)d_in[4];
    const float* utt_bih  = (const float*)d_in[5];
    const float* utt_bhh  = (const float*)d_in[6];
    const float* lin_w    = (const float*)d_in[7];
    const float* lin_b    = (const float*)d_in[8];
    const float* ctx_Wih  = (const float*)d_in[9];
    const float* ctx_Whh  = (const float*)d_in[10];
    const float* ctx_bih  = (const float*)d_in[11];
    const float* ctx_bhh  = (const float*)d_in[12];
    const float* aWr_w    = (const float*)d_in[13];
    const float* aWr_b    = (const float*)d_in[14];
    const float* aUr_w    = (const float*)d_in[15];
    const float* aUr_b    = (const float*)d_in[16];
    const float* aW_w     = (const float*)d_in[17];
    const float* aW_b     = (const float*)d_in[18];
    const float* aU_w     = (const float*)d_in[19];
    const float* aU_b     = (const float*)d_in[20];
    const float* cls_w    = (const float*)d_in[21];
    const float* cls_b    = (const float*)d_in[22];
    float* out = (float*)d_out;

    float *gi_utt, *h_utt, *maxpool, *u, *inp0, *gi_ctx, *seq_ctx, *h_ctx;
    float *mem, *xr, *xw, *gates, *query, *h_att;
    cudaGetSymbolAddress((void**)&gi_utt,  g_gi_utt);
    cudaGetSymbolAddress((void**)&h_utt,   g_h_utt);
    cudaGetSymbolAddress((void**)&maxpool, g_maxpool);
    cudaGetSymbolAddress((void**)&u,       g_u);
    cudaGetSymbolAddress((void**)&inp0,    g_inp0);
    cudaGetSymbolAddress((void**)&gi_ctx,  g_gi_ctx);
    cudaGetSymbolAddress((void**)&seq_ctx, g_seq_ctx);
    cudaGetSymbolAddress((void**)&h_ctx,   g_h_ctx);
    cudaGetSymbolAddress((void**)&mem,     g_mem);
    cudaGetSymbolAddress((void**)&xr,      g_xr);
    cudaGetSymbolAddress((void**)&xw,      g_xw);
    cudaGetSymbolAddress((void**)&gates,   g_gates);
    cudaGetSymbolAddress((void**)&query,   g_query);
    cudaGetSymbolAddress((void**)&h_att,   g_h_att);

    float* hU0 = h_utt;  float* hU1 = h_utt + 2 * NB * HDIM;
    float* hC0 = h_ctx;  float* hC1 = h_ctx + 2 * NQ * HDIM;
    float* hA0 = h_att;  float* hA1 = h_att + 2 * NQ * HDIM;

    const int GRU_SMEM5 = (28200 + 3840 * 2) * 4;   // 143520 B
    const int ATT_SMEM5 = (25200 + 2560 * 2) * 4;   // 121280 B
    cudaFuncSetAttribute(gru_scan5<0>, cudaFuncAttributeMaxDynamicSharedMemorySize, GRU_SMEM5);
    cudaFuncSetAttribute(gru_scan5<1>, cudaFuncAttributeMaxDynamicSharedMemorySize, GRU_SMEM5);
    cudaFuncSetAttribute(att_scan5,    cudaFuncAttributeMaxDynamicSharedMemorySize, ATT_SMEM5);

    cudaStream_t s = 0;
    dim3 sg(30, 2, 2);

    // ---- utterance GRU input projection (gathered emb) ----
    {
        dim3 g((1800 + GTN - 1) / GTN, (LSEQ * NB + GTM - 1) / GTM);
        gemm3<1><<<g, 256, 0, s>>>(nullptr, 0, utt_Wih, utt_bih,
                                   gi_utt, 1800, LSEQ * NB, 1800, EDIM, emb, ids);
    }
    // ---- utterance GRU scan (ONE persistent launch) ----
    gru_scan5<0><<<sg, 960, GRU_SMEM5, s>>>(hU0, hU1, gi_utt, utt_Whh, utt_bhh,
                                            seq_lens, maxpool, nullptr, NB, LSEQ);

    // ---- u = tanh(maxpool @ lin_w^T + lin_b) ----
    lin_kernel<<<NB, 256, 0, s>>>(maxpool, lin_w, lin_b, u);

    // ---- context windows + ctx GRU ----
    build_inp0<<<(KF * NQ * HDIM + 255) / 256, 256, 0, s>>>(u, inp0);
    {
        dim3 g((1800 + GTN - 1) / GTN, (KF * NQ + GTM - 1) / GTM);
        gemm3<0><<<g, 256, 0, s>>>(inp0, HDIM, ctx_Wih, ctx_bih,
                                   gi_ctx, 1800, KF * NQ, 1800, HDIM, nullptr, nullptr);
    }
    gru_scan5<1><<<sg, 960, GRU_SMEM5, s>>>(hC0, hC1, gi_ctx, ctx_Whh, ctx_bhh,
                                            nullptr, nullptr, seq_ctx, NQ, KF);

    membank_kernel<<<(KF * NQ * HDIM + 255) / 256, 256, 0, s>>>(inp0, seq_ctx, mem);

    // ---- attention x-projections (hop-invariant; one GEMM each) ----
    {
        dim3 g((1800 + GTN - 1) / GTN, (KF * NQ + GTM - 1) / GTM);
        gemm3<0><<<g, 256, 0, s>>>(mem, HDIM, aWr_w, aWr_b,
                                   xr, 1800, KF * NQ, 1800, HDIM, nullptr, nullptr);
        gemm3<0><<<g, 256, 0, s>>>(mem, HDIM, aW_w, aW_b,
                                   xw, 1800, KF * NQ, 1800, HDIM, nullptr, nullptr);
    }

    // ---- query init + hops ----
    cudaMemcpyAsync(query, u + HDIM, NQ * HDIM * sizeof(float),
                    cudaMemcpyDeviceToDevice, s);
    for (int hop = 0; hop < NHOPS; hop++) {
        score_kernel<<<NQ, 128, 0, s>>>(query, mem, gates);
        att_scan5<<<sg, 960, ATT_SMEM5, s>>>(hA0, hA1, xr, xw,
                                             aUr_w, aU_w, aUr_b, aU_b, gates, hop);
        // KF=40 even: final state lands in hA0
        add2_kernel<<<(NQ * HDIM + 255) / 256, 256, 0, s>>>(
            query, hA0, hA0 + NQ * HDIM, NQ * HDIM);
    }

    // ---- classifier ----
    cls_kernel<<<NB, 192, 0, s>>>(u, query, cls_w, cls_b, out);
}

// round 13
// speedup vs baseline: 1.1355x; 1.1355x over previous
#include <cuda_runtime.h>
#include <math.h>

#define NB   128   // N dialogues
#define LSEQ 64    // L
#define EDIM 300
#define HDIM 300
#define KF   40    // KEFF
#define NQ   127   // N-1
#define NHOPS 3
#define NCLS 6

typedef unsigned long long u64;

// ---------------- scratch (device globals; no allocation) ----------------
__device__ float g_gi_utt[(size_t)LSEQ * NB * 1800];     // [t*128+b, 1800]
__device__ float g_h_utt[2][2 * NB * HDIM];
__device__ float g_maxpool[NB * 2 * HDIM];
__device__ float g_u[NB * HDIM];
__device__ float g_inp0[KF * NQ * HDIM];                 // ctx_t time-major
__device__ float g_gi_ctx[(size_t)KF * NQ * 1800];
__device__ float g_seq_ctx[2 * KF * NQ * HDIM];          // [dir, t, i, j]
__device__ float g_h_ctx[2][2 * NQ * HDIM];
__device__ float g_mem[KF * NQ * HDIM];                  // time-major [k,i,j]
__device__ float g_xr[(size_t)KF * NQ * 1800];
__device__ float g_xw[(size_t)KF * NQ * 1800];
__device__ float g_gates[KF * NQ];
__device__ float g_query[NQ * HDIM];
__device__ float g_h_att[2][2 * NQ * HDIM];

// group barrier state: 4 groups, padded to separate 128B lines
__device__ unsigned g_cnt[128];   // zero-initialized; returns to 0 each use
__device__ unsigned g_gen[128];   // monotonic forever (never reset)

__device__ __forceinline__ float sigf(float x) { return 1.f / (1.f + expf(-x)); }

// ---------------- packed f32x2 helpers ----------------
__device__ __forceinline__ u64 pk2(float x, float y) {
    u64 r; asm("mov.b64 %0, {%1, %2};" : "=l"(r) : "f"(x), "f"(y)); return r;
}
__device__ __forceinline__ float2 unpk(u64 v) {
    float2 f; asm("mov.b64 {%0, %1}, %2;" : "=f"(f.x), "=f"(f.y) : "l"(v)); return f;
}
__device__ __forceinline__ u64 f2fma(u64 a, u64 b, u64 c) {
    u64 d; asm("fma.rn.f32x2 %0, %1, %2, %3;" : "=l"(d) : "l"(a), "l"(b), "l"(c));
    return d;
}
__device__ __forceinline__ u64 f2add(u64 a, u64 b) {
    u64 d; asm("add.rn.f32x2 %0, %1, %2;" : "=l"(d) : "l"(a), "l"(b));
    return d;
}
__device__ __forceinline__ float hsum2(u64 v) {
    float2 f = unpk(v); return f.x + f.y;
}

// 30-block group barrier; leader resets cnt BEFORE bumping gen (others can't
// re-arrive until gen bumps). Spin on volatile load (no atomic RMW per poll).
__device__ __forceinline__ void group_barrier(int gslot, unsigned target) {
    __threadfence();
    __syncthreads();
    if (threadIdx.x == 0) {
        unsigned old = atomicAdd(&g_cnt[gslot], 1u);
        if (old == 29u) {
            atomicExch(&g_cnt[gslot], 0u);
            __threadfence();
            atomicAdd(&g_gen[gslot], 1u);
        } else {
            while (*(volatile unsigned*)&g_gen[gslot] < target) __nanosleep(32);
        }
        __threadfence();
    }
    __syncthreads();
}

// ---------------- GEMM (f32x2): C = A(MxK) @ W(NxK)^T + bias ----------------
#define GTM 64
#define GTN 64
#define GTK 16

template<int GATHER>
__global__ __launch_bounds__(256)
void gemm3(const float* __restrict__ A, int lda,
           const float* __restrict__ W,
           const float* __restrict__ bias,
           float* __restrict__ C, int ldc,
           int M, int N, int K,
           const float* __restrict__ emb,
           const int* __restrict__ ids)
{
    __shared__ __align__(16) u64   Ad[GTK][66];   // A dup'd: (a,a) per [kk][mm]
    __shared__ __align__(16) float Bs[GTK][66];
    __shared__ int rowid[GTM];
    const int tid = threadIdx.x;
    const int m0 = blockIdx.y * GTM;
    const int n0 = blockIdx.x * GTN;

    if (GATHER) {
        if (tid < GTM) {
            int m = m0 + tid;
            int t = m >> 7, b = m & 127;          // m = t*128 + b
            rowid[tid] = (m < M) ? ids[b * LSEQ + t] : 0;
        }
        __syncthreads();
    }

    u64 acc[4][2] = {};
    const int mt = tid >> 4;   // 0..15
    const int nt = tid & 15;   // 0..15

    for (int k0 = 0; k0 < K; k0 += GTK) {
#pragma unroll
        for (int i = 0; i < 4; i++) {
            int idx = tid + i * 256;
            int mm = idx >> 4, kk = idx & 15;
            int m = m0 + mm, k = k0 + kk;
            float v = 0.f;
            if (m < M && k < K) {
                if (GATHER) v = emb[(size_t)rowid[mm] * K + k];
                else        v = A[(size_t)m * lda + k];
            }
            Ad[kk][mm] = pk2(v, v);
        }
#pragma unroll
        for (int i = 0; i < 4; i++) {
            int idx = tid + i * 256;
            int nn = idx >> 4, kk = idx & 15;
            int n = n0 + nn, k = k0 + kk;
            Bs[kk][nn] = (n < N && k < K) ? W[(size_t)n * K + k] : 0.f;
        }
        __syncthreads();
#pragma unroll
        for (int kk = 0; kk < GTK; kk++) {
            ulonglong2 a01 = *(const ulonglong2*)&Ad[kk][mt * 4];
            ulonglong2 a23 = *(const ulonglong2*)&Ad[kk][mt * 4 + 2];
            u64 b0 = *(const u64*)&Bs[kk][nt * 4];
            u64 b1 = *(const u64*)&Bs[kk][nt * 4 + 2];
            acc[0][0] = f2fma(a01.x, b0, acc[0][0]);
            acc[0][1] = f2fma(a01.x, b1, acc[0][1]);
            acc[1][0] = f2fma(a01.y, b0, acc[1][0]);
            acc[1][1] = f2fma(a01.y, b1, acc[1][1]);
            acc[2][0] = f2fma(a23.x, b0, acc[2][0]);
            acc[2][1] = f2fma(a23.x, b1, acc[2][1]);
            acc[3][0] = f2fma(a23.y, b0, acc[3][0]);
            acc[3][1] = f2fma(a23.y, b1, acc[3][1]);
        }
        __syncthreads();
    }
#pragma unroll
    for (int i = 0; i < 4; i++) {
        int m = m0 + mt * 4 + i;
        if (m >= M) continue;
#pragma unroll
        for (int p = 0; p < 2; p++) {
            float2 v = unpk(acc[i][p]);
            int n = n0 + nt * 4 + 2 * p;
            if (n < N)     C[(size_t)m * ldc + n]     = v.x + bias[n];
            if (n + 1 < N) C[(size_t)m * ldc + n + 1] = v.y + bias[n + 1];
        }
    }
}

// ---------------- persistent GRU scan v6 (n_j=2, 480 thr, gi prefetch) -----
// Grid (30 jgrp, 2 bgrp, 2 dir) = 120 blocks, 1/SM. Thread = (brow 32, upair
// 5, kthird 3): units j0=jgrp*10+uu, j1=j0+5; batches b_lo=b0+brow, b_hi=+32;
// k range [kthird*100, +100). Weights staged once; h restaged per step via
// __ldcg; gi prefetched across the barrier.
template<int MODE>
__global__ __launch_bounds__(480, 1)
void gru_scan6(float* __restrict__ h0, float* __restrict__ h1,
               const float* __restrict__ gi,      // [T*B, 1800]
               const float* __restrict__ Whh,     // [2,900,300]
               const float* __restrict__ bhh,     // [2,900]
               const int*   __restrict__ seq_lens,
               float* __restrict__ maxpool,       // [B, 600]
               float* __restrict__ seqout,        // [2,T,B,300]
               int B, int T)
{
    extern __shared__ float sm[];
    float* Ws = sm;                      // 9000 floats (persists)
    float* Hs = sm + 9000;               // 19200 floats
    u64*   red = (u64*)(sm + 28200);     // 3840 u64

    const int tid    = threadIdx.x;
    const int brow   = tid & 31;
    const int uu     = (tid >> 5) % 5;
    const int kthird = tid / 160;
    const int lig    = tid - kthird * 160;
    const int jgrp = blockIdx.x, bgrp = blockIdx.y, dir = blockIdx.z;
    const int j0 = jgrp * 10 + uu;
    const int j1 = j0 + 5;
    const int dirbase = dir * B * HDIM;
    const int b0 = bgrp * 64;
    const int b_lo = b0 + brow, b_hi = b_lo + 32;
    const int gslot = (dir * 2 + bgrp) * 32;

    const unsigned gen0 = *(volatile unsigned*)&g_gen[gslot];

    // stage weights once: 30 rows x 75 float4
    for (int idx = tid; idx < 2250; idx += 480) {
        int row = idx / 75, q = idx % 75;
        int g = row / 10, ju = row % 10;
        ((float4*)Ws)[row * 75 + q] = ((const float4*)(Whh +
            ((size_t)dir * 900 + g * 300 + jgrp * 10 + ju) * 300))[q];
    }
    // biases for 2 units x 3 gates
    float bh[3][2];
#pragma unroll
    for (int g = 0; g < 3; g++) {
        bh[g][0] = bhh[dir * 900 + g * 300 + j0];
        bh[g][1] = bhh[dir * 900 + g * 300 + j1];
    }
    const bool okA = (b_lo < B), okB = (b_hi < B);
    int lenA = T, lenB = T;
    if (MODE == 0) {
        lenA = okA ? seq_lens[b_lo] : 1;
        lenB = okB ? seq_lens[b_hi] : 1;
    }
    float mpA[2] = { -1e30f, -1e30f }, mpB[2] = { -1e30f, -1e30f };

    // gi prefetch regs: gr[half][unit][gate]
    float gr[2][2][3];
    if (kthird == 0) {
#pragma unroll
        for (int h = 0; h < 2; h++) {
            int b = h ? b_hi : b_lo;
            bool ok = h ? okB : okA;
            int len = h ? lenB : lenA;
            if (ok) {
                int trow = (MODE == 0) ? ((dir == 0) ? 0 : max(len - 1, 0))
                                       : ((dir == 0) ? 0 : (T - 1));
                const float* grp = gi + ((size_t)trow * B + b) * 1800 + dir * 900;
#pragma unroll
                for (int g = 0; g < 3; g++) {
                    gr[h][0][g] = grp[g * 300 + j0];
                    gr[h][1][g] = grp[g * 300 + j1];
                }
            }
        }
    }

    int cur = 0;
    for (int t = 0; t < T; t++) {
        const float* hp = cur ? h1 : h0;
        float*       hn = cur ? h0 : h1;

        if (t > 0) {
            for (int idx = tid; idx < 4800; idx += 480) {
                int bl = idx / 75, q = idx % 75;
                int b = b0 + bl;
                float4 v = make_float4(0.f, 0.f, 0.f, 0.f);
                if (b < B) v = __ldcg(((const float4*)(hp + dirbase + (size_t)b * 300)) + q);
                ((float4*)Hs)[idx] = v;
            }
        }
        __syncthreads();

        u64 acc[3][2][2] = {};   // [gate][unit][half]
        float holdA[2] = {0.f, 0.f}, holdB[2] = {0.f, 0.f};
        if (t > 0) {
            const ulonglong2* w0p = (const ulonglong2*)(Ws + (0  + uu) * 300 + kthird * 100);
            const ulonglong2* w1p = (const ulonglong2*)(Ws + (0  + uu + 5) * 300 + kthird * 100);
            const ulonglong2* z0p = (const ulonglong2*)(Ws + (10 + uu) * 300 + kthird * 100);
            const ulonglong2* z1p = (const ulonglong2*)(Ws + (10 + uu + 5) * 300 + kthird * 100);
            const ulonglong2* n0p = (const ulonglong2*)(Ws + (20 + uu) * 300 + kthird * 100);
            const ulonglong2* n1p = (const ulonglong2*)(Ws + (20 + uu + 5) * 300 + kthird * 100);
            const ulonglong2* hA = (const ulonglong2*)(Hs + brow * 300 + kthird * 100);
#pragma unroll 5
            for (int q = 0; q < 25; q++) {
                ulonglong2 ha = hA[q], hb = hA[q + 2400];
                ulonglong2 w;
                w = w0p[q];
                acc[0][0][0] = f2fma(ha.x, w.x, acc[0][0][0]); acc[0][0][0] = f2fma(ha.y, w.y, acc[0][0][0]);
                acc[0][0][1] = f2fma(hb.x, w.x, acc[0][0][1]); acc[0][0][1] = f2fma(hb.y, w.y, acc[0][0][1]);
                w = w1p[q];
                acc[0][1][0] = f2fma(ha.x, w.x, acc[0][1][0]); acc[0][1][0] = f2fma(ha.y, w.y, acc[0][1][0]);
                acc[0][1][1] = f2fma(hb.x, w.x, acc[0][1][1]); acc[0][1][1] = f2fma(hb.y, w.y, acc[0][1][1]);
                w = z0p[q];
                acc[1][0][0] = f2fma(ha.x, w.x, acc[1][0][0]); acc[1][0][0] = f2fma(ha.y, w.y, acc[1][0][0]);
                acc[1][0][1] = f2fma(hb.x, w.x, acc[1][0][1]); acc[1][0][1] = f2fma(hb.y, w.y, acc[1][0][1]);
                w = z1p[q];
                acc[1][1][0] = f2fma(ha.x, w.x, acc[1][1][0]); acc[1][1][0] = f2fma(ha.y, w.y, acc[1][1][0]);
                acc[1][1][1] = f2fma(hb.x, w.x, acc[1][1][1]); acc[1][1][1] = f2fma(hb.y, w.y, acc[1][1][1]);
                w = n0p[q];
                acc[2][0][0] = f2fma(ha.x, w.x, acc[2][0][0]); acc[2][0][0] = f2fma(ha.y, w.y, acc[2][0][0]);
                acc[2][0][1] = f2fma(hb.x, w.x, acc[2][0][1]); acc[2][0][1] = f2fma(hb.y, w.y, acc[2][0][1]);
                w = n1p[q];
                acc[2][1][0] = f2fma(ha.x, w.x, acc[2][1][0]); acc[2][1][0] = f2fma(ha.y, w.y, acc[2][1][0]);
                acc[2][1][1] = f2fma(hb.x, w.x, acc[2][1][1]); acc[2][1][1] = f2fma(hb.y, w.y, acc[2][1][1]);
            }
            if (kthird == 0) {
                holdA[0] = okA ? Hs[brow * 300 + j0] : 0.f;
                holdA[1] = okA ? Hs[brow * 300 + j1] : 0.f;
                holdB[0] = okB ? Hs[(brow + 32) * 300 + j0] : 0.f;
                holdB[1] = okB ? Hs[(brow + 32) * 300 + j1] : 0.f;
            }
            __syncthreads();
            if (kthird > 0) {
                u64* rp = red + ((size_t)(kthird - 1) * 160 + lig) * 12;
#pragma unroll
                for (int g = 0; g < 3; g++)
#pragma unroll
                    for (int uq = 0; uq < 2; uq++) {
                        rp[(g * 2 + uq) * 2 + 0] = acc[g][uq][0];
                        rp[(g * 2 + uq) * 2 + 1] = acc[g][uq][1];
                    }
            }
            __syncthreads();
            if (kthird == 0) {
#pragma unroll
                for (int kt = 0; kt < 2; kt++) {
                    const u64* rp = red + ((size_t)kt * 160 + lig) * 12;
#pragma unroll
                    for (int g = 0; g < 3; g++)
#pragma unroll
                        for (int uq = 0; uq < 2; uq++) {
                            acc[g][uq][0] = f2add(acc[g][uq][0], rp[(g * 2 + uq) * 2 + 0]);
                            acc[g][uq][1] = f2add(acc[g][uq][1], rp[(g * 2 + uq) * 2 + 1]);
                        }
                }
            }
        }

        if (kthird == 0) {
#pragma unroll
            for (int h = 0; h < 2; h++) {
                int b = h ? b_hi : b_lo;
                bool ok = h ? okB : okA;
                if (!ok) continue;
                int len = h ? lenB : lenA;
                bool msk = (MODE != 0) || (t < len);
#pragma unroll
                for (int uq = 0; uq < 2; uq++) {
                    int jj = uq ? j1 : j0;
                    float hold = h ? holdB[uq] : holdA[uq];
                    float r = sigf(gr[h][uq][0] + hsum2(acc[0][uq][h]) + bh[0][uq]);
                    float z = sigf(gr[h][uq][1] + hsum2(acc[1][uq][h]) + bh[1][uq]);
                    float n = tanhf(gr[h][uq][2] + r * (hsum2(acc[2][uq][h]) + bh[2][uq]));
                    float hnew = (1.f - z) * n + z * hold;
                    if (MODE == 0) {
                        hn[dirbase + (size_t)b * 300 + jj] = msk ? hnew : hold;
                        float mp = msk ? hnew : 0.f;
                        if (h) mpB[uq] = fmaxf(mpB[uq], mp);
                        else   mpA[uq] = fmaxf(mpA[uq], mp);
                    } else {
                        hn[dirbase + (size_t)b * 300 + jj] = hnew;
                        seqout[(((size_t)dir * T + t) * B + b) * 300 + jj] = hnew;
                    }
                }
            }
            // prefetch gi for t+1 (independent of h; overlaps the barrier)
            if (t + 1 < T) {
#pragma unroll
                for (int h = 0; h < 2; h++) {
                    int b = h ? b_hi : b_lo;
                    bool ok = h ? okB : okA;
                    int len = h ? lenB : lenA;
                    if (ok) {
                        int tn = t + 1;
                        int trow = (MODE == 0) ? ((dir == 0) ? tn : max(len - 1 - tn, 0))
                                               : ((dir == 0) ? tn : (T - 1 - tn));
                        const float* grp = gi + ((size_t)trow * B + b) * 1800 + dir * 900;
#pragma unroll
                        for (int g = 0; g < 3; g++) {
                            gr[h][0][g] = grp[g * 300 + j0];
                            gr[h][1][g] = grp[g * 300 + j1];
                        }
                    }
                }
            }
        }
        cur ^= 1;
        if (t < T - 1) group_barrier(gslot, gen0 + (unsigned)t + 1u);
    }

    if (MODE == 0 && kthird == 0) {
#pragma unroll
        for (int uq = 0; uq < 2; uq++) {
            int jj = uq ? j1 : j0;
            if (okA) maxpool[b_lo * (2 * HDIM) + dir * HDIM + jj] = mpA[uq];
            if (okB) maxpool[b_hi * (2 * HDIM) + dir * HDIM + jj] = mpB[uq];
        }
    }
}

// ---------------- persistent attention-GRU scan v6 (one hop) ----------------
__global__ __launch_bounds__(480, 1)
void att_scan6(float* __restrict__ h0, float* __restrict__ h1,
               const float* __restrict__ xr,   // [40*127, 1800]
               const float* __restrict__ xw,
               const float* __restrict__ Ur,   // [3,2,300,300]
               const float* __restrict__ Uw,
               const float* __restrict__ bur,  // [3,2,300]
               const float* __restrict__ bu,
               const float* __restrict__ gates, // [40*127]
               int hop)
{
    extern __shared__ float sm[];
    float* Ws = sm;                      // 6000 floats (persists)
    float* Hs = sm + 6000;               // 19200 floats
    u64*   red = (u64*)(sm + 25200);     // 2560 u64

    const int tid    = threadIdx.x;
    const int brow   = tid & 31;
    const int uu     = (tid >> 5) % 5;
    const int kthird = tid / 160;
    const int lig    = tid - kthird * 160;
    const int jgrp = blockIdx.x, bgrp = blockIdx.y, dir = blockIdx.z;
    const int j0 = jgrp * 10 + uu;
    const int j1 = j0 + 5;
    const int wd = hop * 2 + dir;
    const int dirbase = dir * NQ * HDIM;
    const int b0 = bgrp * 64;
    const int b_lo = b0 + brow, b_hi = b_lo + 32;
    const int gslot = (dir * 2 + bgrp) * 32;

    const unsigned gen0 = *(volatile unsigned*)&g_gen[gslot];

    for (int idx = tid; idx < 1500; idx += 480) {
        int row = idx / 75, q = idx % 75;
        int g = row / 10, ju = row % 10;
        const float* Wsrc = g ? Uw : Ur;
        ((float4*)Ws)[row * 75 + q] = ((const float4*)(Wsrc +
            ((size_t)wd * 300 + jgrp * 10 + ju) * 300))[q];
    }
    float bv[2][2];  // [gate r/w][unit]
    bv[0][0] = bur[wd * 300 + j0]; bv[0][1] = bur[wd * 300 + j1];
    bv[1][0] = bu[wd * 300 + j0];  bv[1][1] = bu[wd * 300 + j1];
    const bool okA = (b_lo < NQ), okB = (b_hi < NQ);

    // prefetch regs: xrv/xwv [half][unit], gv[half]
    float xrv[2][2], xwv[2][2], gv[2];
    if (kthird == 0) {
        int tt0 = (dir == 0) ? 0 : (KF - 1);
#pragma unroll
        for (int h = 0; h < 2; h++) {
            int b = h ? b_hi : b_lo;
            bool ok = h ? okB : okA;
            if (ok) {
                size_t base = ((size_t)tt0 * NQ + b) * 1800 + wd * 300;
                xrv[h][0] = xr[base + j0]; xrv[h][1] = xr[base + j1];
                xwv[h][0] = xw[base + j0]; xwv[h][1] = xw[base + j1];
                gv[h] = gates[tt0 * NQ + b];
            }
        }
    }

    int cur = 0;
    for (int t = 0; t < KF; t++) {
        const float* hp = cur ? h1 : h0;
        float*       hn = cur ? h0 : h1;

        if (t > 0) {
            for (int idx = tid; idx < 4800; idx += 480) {
                int bl = idx / 75, q = idx % 75;
                int b = b0 + bl;
                float4 v = make_float4(0.f, 0.f, 0.f, 0.f);
                if (b < NQ) v = __ldcg(((const float4*)(hp + dirbase + (size_t)b * 300)) + q);
                ((float4*)Hs)[idx] = v;
            }
        }
        __syncthreads();

        u64 acc[2][2][2] = {};  // [gate][unit][half]
        float holdA[2] = {0.f, 0.f}, holdB[2] = {0.f, 0.f};
        if (t > 0) {
            const ulonglong2* r0p = (const ulonglong2*)(Ws + (0  + uu) * 300 + kthird * 100);
            const ulonglong2* r1p = (const ulonglong2*)(Ws + (0  + uu + 5) * 300 + kthird * 100);
            const ulonglong2* w0p = (const ulonglong2*)(Ws + (10 + uu) * 300 + kthird * 100);
            const ulonglong2* w1p = (const ulonglong2*)(Ws + (10 + uu + 5) * 300 + kthird * 100);
            const ulonglong2* hA = (const ulonglong2*)(Hs + brow * 300 + kthird * 100);
#pragma unroll 5
            for (int q = 0; q < 25; q++) {
                ulonglong2 ha = hA[q], hb = hA[q + 2400];
                ulonglong2 w;
                w = r0p[q];
                acc[0][0][0] = f2fma(ha.x, w.x, acc[0][0][0]); acc[0][0][0] = f2fma(ha.y, w.y, acc[0][0][0]);
                acc[0][0][1] = f2fma(hb.x, w.x, acc[0][0][1]); acc[0][0][1] = f2fma(hb.y, w.y, acc[0][0][1]);
                w = r1p[q];
                acc[0][1][0] = f2fma(ha.x, w.x, acc[0][1][0]); acc[0][1][0] = f2fma(ha.y, w.y, acc[0][1][0]);
                acc[0][1][1] = f2fma(hb.x, w.x, acc[0][1][1]); acc[0][1][1] = f2fma(hb.y, w.y, acc[0][1][1]);
                w = w0p[q];
                acc[1][0][0] = f2fma(ha.x, w.x, acc[1][0][0]); acc[1][0][0] = f2fma(ha.y, w.y, acc[1][0][0]);
                acc[1][0][1] = f2fma(hb.x, w.x, acc[1][0][1]); acc[1][0][1] = f2fma(hb.y, w.y, acc[1][0][1]);
                w = w1p[q];
                acc[1][1][0] = f2fma(ha.x, w.x, acc[1][1][0]); acc[1][1][0] = f2fma(ha.y, w.y, acc[1][1][0]);
                acc[1][1][1] = f2fma(hb.x, w.x, acc[1][1][1]); acc[1][1][1] = f2fma(hb.y, w.y, acc[1][1][1]);
            }
            if (kthird == 0) {
                holdA[0] = okA ? Hs[brow * 300 + j0] : 0.f;
                holdA[1] = okA ? Hs[brow * 300 + j1] : 0.f;
                holdB[0] = okB ? Hs[(brow + 32) * 300 + j0] : 0.f;
                holdB[1] = okB ? Hs[(brow + 32) * 300 + j1] : 0.f;
            }
            __syncthreads();
            if (kthird > 0) {
                u64* rp = red + ((size_t)(kthird - 1) * 160 + lig) * 8;
#pragma unroll
                for (int g = 0; g < 2; g++)
#pragma unroll
                    for (int uq = 0; uq < 2; uq++) {
                        rp[(g * 2 + uq) * 2 + 0] = acc[g][uq][0];
                        rp[(g * 2 + uq) * 2 + 1] = acc[g][uq][1];
                    }
            }
            __syncthreads();
            if (kthird == 0) {
#pragma unroll
                for (int kt = 0; kt < 2; kt++) {
                    const u64* rp = red + ((size_t)kt * 160 + lig) * 8;
#pragma unroll
                    for (int g = 0; g < 2; g++)
#pragma unroll
                        for (int uq = 0; uq < 2; uq++) {
                            acc[g][uq][0] = f2add(acc[g][uq][0], rp[(g * 2 + uq) * 2 + 0]);
                            acc[g][uq][1] = f2add(acc[g][uq][1], rp[(g * 2 + uq) * 2 + 1]);
                        }
                }
            }
        }

        if (kthird == 0) {
#pragma unroll
            for (int h = 0; h < 2; h++) {
                int b = h ? b_hi : b_lo;
                bool ok = h ? okB : okA;
                if (!ok) continue;
#pragma unroll
                for (int uq = 0; uq < 2; uq++) {
                    int jj = uq ? j1 : j0;
                    float hold = h ? holdB[uq] : holdA[uq];
                    float r  = sigf(xrv[h][uq] + hsum2(acc[0][uq][h]) + bv[0][uq]);
                    float ht = tanhf(xwv[h][uq] + r * (hsum2(acc[1][uq][h]) + bv[1][uq]));
                    hn[dirbase + (size_t)b * 300 + jj] = gv[h] * ht + (1.f - gv[h]) * hold;
                }
            }
            if (t + 1 < KF) {
                int tn = (dir == 0) ? (t + 1) : (KF - 2 - t);
#pragma unroll
                for (int h = 0; h < 2; h++) {
                    int b = h ? b_hi : b_lo;
                    bool ok = h ? okB : okA;
                    if (ok) {
                        size_t base = ((size_t)tn * NQ + b) * 1800 + wd * 300;
                        xrv[h][0] = xr[base + j0]; xrv[h][1] = xr[base + j1];
                        xwv[h][0] = xw[base + j0]; xwv[h][1] = xw[base + j1];
                        gv[h] = gates[tn * NQ + b];
                    }
                }
            }
        }
        cur ^= 1;
        if (t < KF - 1) group_barrier(gslot, gen0 + (unsigned)t + 1u);
    }
}

// ---------------- small kernels ----------------
__global__ __launch_bounds__(256)
void lin_kernel(const float* __restrict__ mp, const float* __restrict__ w,
                const float* __restrict__ bsc, float* __restrict__ u) {
    int b = blockIdx.x;
    __shared__ float m[600];
    for (int i = threadIdx.x; i < 600; i += 256) m[i] = mp[b * 600 + i];
    __syncthreads();
    int wid = threadIdx.x >> 5, lane = threadIdx.x & 31;
    for (int j = wid; j < HDIM; j += 8) {
        float acc = 0.f;
        const float* wr = w + (size_t)j * 600;
        for (int k = lane; k < 600; k += 32) acc += m[k] * wr[k];
        for (int o = 16; o > 0; o >>= 1) acc += __shfl_xor_sync(0xffffffffu, acc, o);
        if (lane == 0) u[b * HDIM + j] = tanhf(acc + bsc[j]);
    }
}

__global__ void build_inp0(const float* __restrict__ u, float* __restrict__ inp0) {
    int idx = blockIdx.x * blockDim.x + threadIdx.x;
    if (idx >= KF * NQ * HDIM) return;
    int j = idx % HDIM;
    int r = idx / HDIM;
    int i = r % NQ;
    int k = r / NQ;
    int src = (i + 1) - KF + k;
    inp0[idx] = (src >= 0) ? u[src * HDIM + j] : 0.f;
}

__global__ void membank_kernel(const float* __restrict__ inp0,
                               const float* __restrict__ seq,
                               float* __restrict__ mem) {
    int idx = blockIdx.x * blockDim.x + threadIdx.x;
    if (idx >= KF * NQ * HDIM) return;
    int j = idx % HDIM;
    int r = idx / HDIM;
    int i = r % NQ;
    int k = r / NQ;
    float f = seq[((size_t)k) * NQ * HDIM + i * HDIM + j];
    float b = seq[((size_t)KF + (KF - 1 - k)) * NQ * HDIM + i * HDIM + j];
    mem[idx] = inp0[idx] + f + b;
}

__global__ void score_kernel(const float* __restrict__ query,
                             const float* __restrict__ mem,
                             float* __restrict__ gates) {
    int b = blockIdx.x;                 // 0..126
    int tid = threadIdx.x;              // 128
    int lane = tid & 31, w = tid >> 5;
    __shared__ float q[HDIM];
    __shared__ float logit[KF];
    for (int i = tid; i < HDIM; i += 128) q[i] = query[b * HDIM + i];
    __syncthreads();
    for (int k = w; k < KF; k += 4) {
        const float* mrow = mem + ((size_t)k * NQ + b) * HDIM;
        float s = 0.f;
        for (int i = lane; i < HDIM; i += 32) s += q[i] * mrow[i];
        for (int o = 16; o > 0; o >>= 1) s += __shfl_xor_sync(0xffffffffu, s, o);
        if (lane == 0) logit[k] = (k >= KF - 1 - b) ? s : -1e10f;
    }
    __syncthreads();
    if (w == 0) {
        float m = -INFINITY;
        for (int k = lane; k < KF; k += 32) m = fmaxf(m, logit[k]);
        for (int o = 16; o > 0; o >>= 1) m = fmaxf(m, __shfl_xor_sync(0xffffffffu, m, o));
        float ssum = 0.f;
        for (int k = lane; k < KF; k += 32) { float e = expf(logit[k] - m); logit[k] = e; ssum += e; }
        for (int o = 16; o > 0; o >>= 1) ssum += __shfl_xor_sync(0xffffffffu, ssum, o);
        for (int k = lane; k < KF; k += 32) gates[k * NQ + b] = logit[k] / ssum;
    }
}

__global__ void add2_kernel(float* __restrict__ q,
                            const float* __restrict__ hf,
                            const float* __restrict__ hb, int n) {
    int i = blockIdx.x * blockDim.x + threadIdx.x;
    if (i < n) q[i] += hf[i] + hb[i];
}

__global__ void cls_kernel(const float* __restrict__ u,
                           const float* __restrict__ query,
                           const float* __restrict__ cls_w,
                           const float* __restrict__ cls_b,
                           float* __restrict__ out) {
    int row = blockIdx.x;               // 0..127
    int w = threadIdx.x >> 5, lane = threadIdx.x & 31;   // 192 threads = 6 warps
    const float* s = (row == 0) ? u : (query + (row - 1) * HDIM);
    float acc = 0.f;
    for (int i = lane; i < HDIM; i += 32) acc += s[i] * cls_w[w * HDIM + i];
    for (int o = 16; o > 0; o >>= 1) acc += __shfl_xor_sync(0xffffffffu, acc, o);
    if (lane == 0) out[row * NCLS + w] = acc + cls_b[w];
}

// ---------------- host orchestration ----------------
extern "C" void kernel_launch(void* const* d_in, const int* in_sizes, int n_in,
                              void* d_out, int out_size) {
    const int*   ids      = (const int*)d_in[0];
    const int*   seq_lens = (const int*)d_in[1];
    const float* emb      = (const float*)d_in[2];
    const float* utt_Wih  = (const float*)d_in[3];
    const float* utt_Whh  = (const float*)d_in[4];
    const float* utt_bih  = (const float*)d_in[5];
    const float* utt_bhh  = (const float*)d_in[6];
    const float* lin_w    = (const float*)d_in[7];
    const float* lin_b    = (const float*)d_in[8];
    const float* ctx_Wih  = (const float*)d_in[9];
    const float* ctx_Whh  = (const float*)d_in[10];
    const float* ctx_bih  = (const float*)d_in[11];
    const float* ctx_bhh  = (const float*)d_in[12];
    const float* aWr_w    = (const float*)d_in[13];
    const float* aWr_b    = (const float*)d_in[14];
    const float* aUr_w    = (const float*)d_in[15];
    const float* aUr_b    = (const float*)d_in[16];
    const float* aW_w     = (const float*)d_in[17];
    const float* aW_b     = (const float*)d_in[18];
    const float* aU_w     = (const float*)d_in[19];
    const float* aU_b     = (const float*)d_in[20];
    const float* cls_w    = (const float*)d_in[21];
    const float* cls_b    = (const float*)d_in[22];
    float* out = (float*)d_out;

    float *gi_utt, *h_utt, *maxpool, *u, *inp0, *gi_ctx, *seq_ctx, *h_ctx;
    float *mem, *xr, *xw, *gates, *query, *h_att;
    cudaGetSymbolAddress((void**)&gi_utt,  g_gi_utt);
    cudaGetSymbolAddress((void**)&h_utt,   g_h_utt);
    cudaGetSymbolAddress((void**)&maxpool, g_maxpool);
    cudaGetSymbolAddress((void**)&u,       g_u);
    cudaGetSymbolAddress((void**)&inp0,    g_inp0);
    cudaGetSymbolAddress((void**)&gi_ctx,  g_gi_ctx);
    cudaGetSymbolAddress((void**)&seq_ctx, g_seq_ctx);
    cudaGetSymbolAddress((void**)&h_ctx,   g_h_ctx);
    cudaGetSymbolAddress((void**)&mem,     g_mem);
    cudaGetSymbolAddress((void**)&xr,      g_xr);
    cudaGetSymbolAddress((void**)&xw,      g_xw);
    cudaGetSymbolAddress((void**)&gates,   g_gates);
    cudaGetSymbolAddress((void**)&query,   g_query);
    cudaGetSymbolAddress((void**)&h_att,   g_h_att);

    float* hU0 = h_utt;  float* hU1 = h_utt + 2 * NB * HDIM;
    float* hC0 = h_ctx;  float* hC1 = h_ctx + 2 * NQ * HDIM;
    float* hA0 = h_att;  float* hA1 = h_att + 2 * NQ * HDIM;

    const int GRU_SMEM6 = 28200 * 4 + 3840 * 8;   // 143520 B
    const int ATT_SMEM6 = 25200 * 4 + 2560 * 8;   // 121280 B
    cudaFuncSetAttribute(gru_scan6<0>, cudaFuncAttributeMaxDynamicSharedMemorySize, GRU_SMEM6);
    cudaFuncSetAttribute(gru_scan6<1>, cudaFuncAttributeMaxDynamicSharedMemorySize, GRU_SMEM6);
    cudaFuncSetAttribute(att_scan6,    cudaFuncAttributeMaxDynamicSharedMemorySize, ATT_SMEM6);

    cudaStream_t s = 0;
    dim3 sg(30, 2, 2);

    // ---- utterance GRU input projection (gathered emb) ----
    {
        dim3 g((1800 + GTN - 1) / GTN, (LSEQ * NB + GTM - 1) / GTM);
        gemm3<1><<<g, 256, 0, s>>>(nullptr, 0, utt_Wih, utt_bih,
                                   gi_utt, 1800, LSEQ * NB, 1800, EDIM, emb, ids);
    }
    // ---- utterance GRU scan (ONE persistent launch) ----
    gru_scan6<0><<<sg, 480, GRU_SMEM6, s>>>(hU0, hU1, gi_utt, utt_Whh, utt_bhh,
                                            seq_lens, maxpool, nullptr, NB, LSEQ);

    // ---- u = tanh(maxpool @ lin_w^T + lin_b) ----
    lin_kernel<<<NB, 256, 0, s>>>(maxpool, lin_w, lin_b, u);

    // ---- context windows + ctx GRU ----
    build_inp0<<<(KF * NQ * HDIM + 255) / 256, 256, 0, s>>>(u, inp0);
    {
        dim3 g((1800 + GTN - 1) / GTN, (KF * NQ + GTM - 1) / GTM);
        gemm3<0><<<g, 256, 0, s>>>(inp0, HDIM, ctx_Wih, ctx_bih,
                                   gi_ctx, 1800, KF * NQ, 1800, HDIM, nullptr, nullptr);
    }
    gru_scan6<1><<<sg, 480, GRU_SMEM6, s>>>(hC0, hC1, gi_ctx, ctx_Whh, ctx_bhh,
                                            nullptr, nullptr, seq_ctx, NQ, KF);

    membank_kernel<<<(KF * NQ * HDIM + 255) / 256, 256, 0, s>>>(inp0, seq_ctx, mem);

    // ---- attention x-projections (hop-invariant; one GEMM each) ----
    {
        dim3 g((1800 + GTN - 1) / GTN, (KF * NQ + GTM - 1) / GTM);
        gemm3<0><<<g, 256, 0, s>>>(mem, HDIM, aWr_w, aWr_b,
                                   xr, 1800, KF * NQ, 1800, HDIM, nullptr, nullptr);
        gemm3<0><<<g, 256, 0, s>>>(mem, HDIM, aW_w, aW_b,
                                   xw, 1800, KF * NQ, 1800, HDIM, nullptr, nullptr);
    }

    // ---- query init + hops ----
    cudaMemcpyAsync(query, u + HDIM, NQ * HDIM * sizeof(float),
                    cudaMemcpyDeviceToDevice, s);
    for (int hop = 0; hop < NHOPS; hop++) {
        score_kernel<<<NQ, 128, 0, s>>>(query, mem, gates);
        att_scan6<<<sg, 480, ATT_SMEM6, s>>>(hA0, hA1, xr, xw,
                                             aUr_w, aU_w, aUr_b, aU_b, gates, hop);
        // KF=40 even: final state lands in hA0
        add2_kernel<<<(NQ * HDIM + 255) / 256, 256, 0, s>>>(
            query, hA0, hA0 + NQ * HDIM, NQ * HDIM);
    }

    // ---- classifier ----
    cls_kernel<<<NB, 192, 0, s>>>(u, query, cls_w, cls_b, out);
}

// round 14
// speedup vs baseline: 1.2216x; 1.0759x over previous
#include <cuda_runtime.h>
#include <math.h>

#define NB   128   // N dialogues
#define LSEQ 64    // L
#define EDIM 300
#define HDIM 300
#define KF   40    // KEFF
#define NQ   127   // N-1
#define NHOPS 3
#define NCLS 6

typedef unsigned long long u64;

// ---------------- scratch (device globals; no allocation) ----------------
__device__ float g_gi_utt[(size_t)LSEQ * NB * 1800];     // [t*128+b, 1800]
__device__ float g_h_utt[2][2 * NB * HDIM];
__device__ float g_maxpool[NB * 2 * HDIM];
__device__ float g_u[NB * HDIM];
__device__ float g_inp0[KF * NQ * HDIM];                 // ctx_t time-major
__device__ float g_proj[NQ * 1800];                      // u[0:127] @ ctx_Wih^T + bih
__device__ float g_seq_ctx[2 * KF * NQ * HDIM];          // [dir, t, i, j]
__device__ float g_h_ctx[2][2 * NQ * HDIM];
__device__ float g_mem[KF * NQ * HDIM];                  // time-major [k,i,j]
__device__ float g_xr[(size_t)KF * NQ * 1800];
__device__ float g_xw[(size_t)KF * NQ * 1800];
__device__ float g_gates[KF * NQ];
__device__ float g_query[NQ * HDIM];
__device__ float g_h_att[2][2 * NQ * HDIM];

// group barrier state: 4 groups, padded to separate 128B lines
__device__ unsigned g_cnt[128];   // zero-initialized; returns to 0 each use
__device__ unsigned g_gen[128];   // monotonic forever (never reset)

__device__ __forceinline__ float sigf(float x) { return 1.f / (1.f + expf(-x)); }

// ---------------- packed f32x2 helpers ----------------
__device__ __forceinline__ u64 pk2(float x, float y) {
    u64 r; asm("mov.b64 %0, {%1, %2};" : "=l"(r) : "f"(x), "f"(y)); return r;
}
__device__ __forceinline__ float2 unpk(u64 v) {
    float2 f; asm("mov.b64 {%0, %1}, %2;" : "=f"(f.x), "=f"(f.y) : "l"(v)); return f;
}
__device__ __forceinline__ u64 f2fma(u64 a, u64 b, u64 c) {
    u64 d; asm("fma.rn.f32x2 %0, %1, %2, %3;" : "=l"(d) : "l"(a), "l"(b), "l"(c));
    return d;
}
__device__ __forceinline__ u64 f2add(u64 a, u64 b) {
    u64 d; asm("add.rn.f32x2 %0, %1, %2;" : "=l"(d) : "l"(a), "l"(b));
    return d;
}
__device__ __forceinline__ float hsum2(u64 v) {
    float2 f = unpk(v); return f.x + f.y;
}

// 30-block group barrier; leader resets cnt BEFORE bumping gen.
__device__ __forceinline__ void group_barrier(int gslot, unsigned target) {
    __threadfence();
    __syncthreads();
    if (threadIdx.x == 0) {
        unsigned old = atomicAdd(&g_cnt[gslot], 1u);
        if (old == 29u) {
            atomicExch(&g_cnt[gslot], 0u);
            __threadfence();
            atomicAdd(&g_gen[gslot], 1u);
        } else {
            while (*(volatile unsigned*)&g_gen[gslot] < target) __nanosleep(32);
        }
        __threadfence();
    }
    __syncthreads();
}

// ---------------- GEMM (f32x2): C = A(MxK) @ W(NxK)^T + bias ----------------
#define GTM 64
#define GTN 64
#define GTK 16

template<int GATHER>
__global__ __launch_bounds__(256)
void gemm3(const float* __restrict__ A, int lda,
           const float* __restrict__ W,
           const float* __restrict__ bias,
           float* __restrict__ C, int ldc,
           int M, int N, int K,
           const float* __restrict__ emb,
           const int* __restrict__ ids)
{
    __shared__ __align__(16) u64   Ad[GTK][66];   // A dup'd: (a,a) per [kk][mm]
    __shared__ __align__(16) float Bs[GTK][66];
    __shared__ int rowid[GTM];
    const int tid = threadIdx.x;
    const int m0 = blockIdx.y * GTM;
    const int n0 = blockIdx.x * GTN;

    if (GATHER) {
        if (tid < GTM) {
            int m = m0 + tid;
            int t = m >> 7, b = m & 127;          // m = t*128 + b
            rowid[tid] = (m < M) ? ids[b * LSEQ + t] : 0;
        }
        __syncthreads();
    }

    u64 acc[4][2] = {};
    const int mt = tid >> 4;   // 0..15
    const int nt = tid & 15;   // 0..15

    for (int k0 = 0; k0 < K; k0 += GTK) {
#pragma unroll
        for (int i = 0; i < 4; i++) {
            int idx = tid + i * 256;
            int mm = idx >> 4, kk = idx & 15;
            int m = m0 + mm, k = k0 + kk;
            float v = 0.f;
            if (m < M && k < K) {
                if (GATHER) v = emb[(size_t)rowid[mm] * K + k];
                else        v = A[(size_t)m * lda + k];
            }
            Ad[kk][mm] = pk2(v, v);
        }
#pragma unroll
        for (int i = 0; i < 4; i++) {
            int idx = tid + i * 256;
            int nn = idx >> 4, kk = idx & 15;
            int n = n0 + nn, k = k0 + kk;
            Bs[kk][nn] = (n < N && k < K) ? W[(size_t)n * K + k] : 0.f;
        }
        __syncthreads();
#pragma unroll
        for (int kk = 0; kk < GTK; kk++) {
            ulonglong2 a01 = *(const ulonglong2*)&Ad[kk][mt * 4];
            ulonglong2 a23 = *(const ulonglong2*)&Ad[kk][mt * 4 + 2];
            u64 b0 = *(const u64*)&Bs[kk][nt * 4];
            u64 b1 = *(const u64*)&Bs[kk][nt * 4 + 2];
            acc[0][0] = f2fma(a01.x, b0, acc[0][0]);
            acc[0][1] = f2fma(a01.x, b1, acc[0][1]);
            acc[1][0] = f2fma(a01.y, b0, acc[1][0]);
            acc[1][1] = f2fma(a01.y, b1, acc[1][1]);
            acc[2][0] = f2fma(a23.x, b0, acc[2][0]);
            acc[2][1] = f2fma(a23.x, b1, acc[2][1]);
            acc[3][0] = f2fma(a23.y, b0, acc[3][0]);
            acc[3][1] = f2fma(a23.y, b1, acc[3][1]);
        }
        __syncthreads();
    }
#pragma unroll
    for (int i = 0; i < 4; i++) {
        int m = m0 + mt * 4 + i;
        if (m >= M) continue;
#pragma unroll
        for (int p = 0; p < 2; p++) {
            float2 v = unpk(acc[i][p]);
            int n = n0 + nt * 4 + 2 * p;
            if (n < N)     C[(size_t)m * ldc + n]     = v.x + bias[n];
            if (n + 1 < N) C[(size_t)m * ldc + n + 1] = v.y + bias[n + 1];
        }
    }
}

// ---------------- persistent GRU scan v7 (n_j=2, 480 thr, gi prefetch) -----
// Grid (30 jgrp, 2 bgrp, 2 dir) = 120 blocks, 1/SM.
// MODE 0: utt — gi indexed [trow*B+b]*1800 (per-step rows)
// MODE 1: ctx — gi = proj127 [src*1800], src = b+1-KF+trow; bih when src<0
template<int MODE>
__global__ __launch_bounds__(480, 1)
void gru_scan7(float* __restrict__ h0, float* __restrict__ h1,
               const float* __restrict__ gi,
               const float* __restrict__ Whh,     // [2,900,300]
               const float* __restrict__ bhh,     // [2,900]
               const float* __restrict__ bih,     // [2,900] (MODE 1 only)
               const int*   __restrict__ seq_lens,
               float* __restrict__ maxpool,       // [B, 600]
               float* __restrict__ seqout,        // [2,T,B,300]
               int B, int T)
{
    extern __shared__ float sm[];
    float* Ws = sm;                      // 9000 floats (persists)
    float* Hs = sm + 9000;               // 19200 floats
    u64*   red = (u64*)(sm + 28200);     // 3840 u64

    const int tid    = threadIdx.x;
    const int brow   = tid & 31;
    const int uu     = (tid >> 5) % 5;
    const int kthird = tid / 160;
    const int lig    = tid - kthird * 160;
    const int jgrp = blockIdx.x, bgrp = blockIdx.y, dir = blockIdx.z;
    const int j0 = jgrp * 10 + uu;
    const int j1 = j0 + 5;
    const int dirbase = dir * B * HDIM;
    const int b0 = bgrp * 64;
    const int b_lo = b0 + brow, b_hi = b_lo + 32;
    const int gslot = (dir * 2 + bgrp) * 32;

    const unsigned gen0 = *(volatile unsigned*)&g_gen[gslot];

    // stage weights once: 30 rows x 75 float4
    for (int idx = tid; idx < 2250; idx += 480) {
        int row = idx / 75, q = idx % 75;
        int g = row / 10, ju = row % 10;
        ((float4*)Ws)[row * 75 + q] = ((const float4*)(Whh +
            ((size_t)dir * 900 + g * 300 + jgrp * 10 + ju) * 300))[q];
    }
    // biases for 2 units x 3 gates
    float bh[3][2], bi[3][2];
#pragma unroll
    for (int g = 0; g < 3; g++) {
        bh[g][0] = bhh[dir * 900 + g * 300 + j0];
        bh[g][1] = bhh[dir * 900 + g * 300 + j1];
        if (MODE == 1) {
            bi[g][0] = bih[dir * 900 + g * 300 + j0];
            bi[g][1] = bih[dir * 900 + g * 300 + j1];
        }
    }
    const bool okA = (b_lo < B), okB = (b_hi < B);
    int lenA = T, lenB = T;
    if (MODE == 0) {
        lenA = okA ? seq_lens[b_lo] : 1;
        lenB = okB ? seq_lens[b_hi] : 1;
    }
    float mpA[2] = { -1e30f, -1e30f }, mpB[2] = { -1e30f, -1e30f };

    // gi prefetch regs: gr[half][unit][gate]
    float gr[2][2][3];
    if (kthird == 0) {
#pragma unroll
        for (int h = 0; h < 2; h++) {
            int b = h ? b_hi : b_lo;
            bool ok = h ? okB : okA;
            int len = h ? lenB : lenA;
            if (!ok) continue;
            if (MODE == 0) {
                int trow = (dir == 0) ? 0 : max(len - 1, 0);
                const float* grp = gi + ((size_t)trow * B + b) * 1800 + dir * 900;
#pragma unroll
                for (int g = 0; g < 3; g++) {
                    gr[h][0][g] = grp[g * 300 + j0];
                    gr[h][1][g] = grp[g * 300 + j1];
                }
            } else {
                int trow = (dir == 0) ? 0 : (T - 1);
                int src = b + 1 - KF + trow;
                if (src >= 0) {
                    const float* grp = gi + (size_t)src * 1800 + dir * 900;
#pragma unroll
                    for (int g = 0; g < 3; g++) {
                        gr[h][0][g] = grp[g * 300 + j0];
                        gr[h][1][g] = grp[g * 300 + j1];
                    }
                } else {
#pragma unroll
                    for (int g = 0; g < 3; g++) {
                        gr[h][0][g] = bi[g][0];
                        gr[h][1][g] = bi[g][1];
                    }
                }
            }
        }
    }

    int cur = 0;
    for (int t = 0; t < T; t++) {
        const float* hp = cur ? h1 : h0;
        float*       hn = cur ? h0 : h1;

        if (t > 0) {
            for (int idx = tid; idx < 4800; idx += 480) {
                int bl = idx / 75, q = idx % 75;
                int b = b0 + bl;
                float4 v = make_float4(0.f, 0.f, 0.f, 0.f);
                if (b < B) v = __ldcg(((const float4*)(hp + dirbase + (size_t)b * 300)) + q);
                ((float4*)Hs)[idx] = v;
            }
        }
        __syncthreads();

        u64 acc[3][2][2] = {};   // [gate][unit][half]
        float holdA[2] = {0.f, 0.f}, holdB[2] = {0.f, 0.f};
        if (t > 0) {
            const ulonglong2* w0p = (const ulonglong2*)(Ws + (0  + uu) * 300 + kthird * 100);
            const ulonglong2* w1p = (const ulonglong2*)(Ws + (0  + uu + 5) * 300 + kthird * 100);
            const ulonglong2* z0p = (const ulonglong2*)(Ws + (10 + uu) * 300 + kthird * 100);
            const ulonglong2* z1p = (const ulonglong2*)(Ws + (10 + uu + 5) * 300 + kthird * 100);
            const ulonglong2* n0p = (const ulonglong2*)(Ws + (20 + uu) * 300 + kthird * 100);
            const ulonglong2* n1p = (const ulonglong2*)(Ws + (20 + uu + 5) * 300 + kthird * 100);
            const ulonglong2* hA = (const ulonglong2*)(Hs + brow * 300 + kthird * 100);
#pragma unroll 5
            for (int q = 0; q < 25; q++) {
                ulonglong2 ha = hA[q], hb = hA[q + 2400];
                ulonglong2 w;
                w = w0p[q];
                acc[0][0][0] = f2fma(ha.x, w.x, acc[0][0][0]); acc[0][0][0] = f2fma(ha.y, w.y, acc[0][0][0]);
                acc[0][0][1] = f2fma(hb.x, w.x, acc[0][0][1]); acc[0][0][1] = f2fma(hb.y, w.y, acc[0][0][1]);
                w = w1p[q];
                acc[0][1][0] = f2fma(ha.x, w.x, acc[0][1][0]); acc[0][1][0] = f2fma(ha.y, w.y, acc[0][1][0]);
                acc[0][1][1] = f2fma(hb.x, w.x, acc[0][1][1]); acc[0][1][1] = f2fma(hb.y, w.y, acc[0][1][1]);
                w = z0p[q];
                acc[1][0][0] = f2fma(ha.x, w.x, acc[1][0][0]); acc[1][0][0] = f2fma(ha.y, w.y, acc[1][0][0]);
                acc[1][0][1] = f2fma(hb.x, w.x, acc[1][0][1]); acc[1][0][1] = f2fma(hb.y, w.y, acc[1][0][1]);
                w = z1p[q];
                acc[1][1][0] = f2fma(ha.x, w.x, acc[1][1][0]); acc[1][1][0] = f2fma(ha.y, w.y, acc[1][1][0]);
                acc[1][1][1] = f2fma(hb.x, w.x, acc[1][1][1]); acc[1][1][1] = f2fma(hb.y, w.y, acc[1][1][1]);
                w = n0p[q];
                acc[2][0][0] = f2fma(ha.x, w.x, acc[2][0][0]); acc[2][0][0] = f2fma(ha.y, w.y, acc[2][0][0]);
                acc[2][0][1] = f2fma(hb.x, w.x, acc[2][0][1]); acc[2][0][1] = f2fma(hb.y, w.y, acc[2][0][1]);
                w = n1p[q];
                acc[2][1][0] = f2fma(ha.x, w.x, acc[2][1][0]); acc[2][1][0] = f2fma(ha.y, w.y, acc[2][1][0]);
                acc[2][1][1] = f2fma(hb.x, w.x, acc[2][1][1]); acc[2][1][1] = f2fma(hb.y, w.y, acc[2][1][1]);
            }
            if (kthird == 0) {
                holdA[0] = okA ? Hs[brow * 300 + j0] : 0.f;
                holdA[1] = okA ? Hs[brow * 300 + j1] : 0.f;
                holdB[0] = okB ? Hs[(brow + 32) * 300 + j0] : 0.f;
                holdB[1] = okB ? Hs[(brow + 32) * 300 + j1] : 0.f;
            }
            __syncthreads();
            if (kthird > 0) {
                u64* rp = red + ((size_t)(kthird - 1) * 160 + lig) * 12;
#pragma unroll
                for (int g = 0; g < 3; g++)
#pragma unroll
                    for (int uq = 0; uq < 2; uq++) {
                        rp[(g * 2 + uq) * 2 + 0] = acc[g][uq][0];
                        rp[(g * 2 + uq) * 2 + 1] = acc[g][uq][1];
                    }
            }
            __syncthreads();
            if (kthird == 0) {
#pragma unroll
                for (int kt = 0; kt < 2; kt++) {
                    const u64* rp = red + ((size_t)kt * 160 + lig) * 12;
#pragma unroll
                    for (int g = 0; g < 3; g++)
#pragma unroll
                        for (int uq = 0; uq < 2; uq++) {
                            acc[g][uq][0] = f2add(acc[g][uq][0], rp[(g * 2 + uq) * 2 + 0]);
                            acc[g][uq][1] = f2add(acc[g][uq][1], rp[(g * 2 + uq) * 2 + 1]);
                        }
                }
            }
        }

        if (kthird == 0) {
#pragma unroll
            for (int h = 0; h < 2; h++) {
                int b = h ? b_hi : b_lo;
                bool ok = h ? okB : okA;
                if (!ok) continue;
                int len = h ? lenB : lenA;
                bool msk = (MODE != 0) || (t < len);
#pragma unroll
                for (int uq = 0; uq < 2; uq++) {
                    int jj = uq ? j1 : j0;
                    float hold = h ? holdB[uq] : holdA[uq];
                    float r = sigf(gr[h][uq][0] + hsum2(acc[0][uq][h]) + bh[0][uq]);
                    float z = sigf(gr[h][uq][1] + hsum2(acc[1][uq][h]) + bh[1][uq]);
                    float n = tanhf(gr[h][uq][2] + r * (hsum2(acc[2][uq][h]) + bh[2][uq]));
                    float hnew = (1.f - z) * n + z * hold;
                    if (MODE == 0) {
                        hn[dirbase + (size_t)b * 300 + jj] = msk ? hnew : hold;
                        float mp = msk ? hnew : 0.f;
                        if (h) mpB[uq] = fmaxf(mpB[uq], mp);
                        else   mpA[uq] = fmaxf(mpA[uq], mp);
                    } else {
                        hn[dirbase + (size_t)b * 300 + jj] = hnew;
                        seqout[(((size_t)dir * T + t) * B + b) * 300 + jj] = hnew;
                    }
                }
            }
            // prefetch gi for t+1 (independent of h; overlaps the barrier)
            if (t + 1 < T) {
                int tn = t + 1;
#pragma unroll
                for (int h = 0; h < 2; h++) {
                    int b = h ? b_hi : b_lo;
                    bool ok = h ? okB : okA;
                    int len = h ? lenB : lenA;
                    if (!ok) continue;
                    if (MODE == 0) {
                        int trow = (dir == 0) ? tn : max(len - 1 - tn, 0);
                        const float* grp = gi + ((size_t)trow * B + b) * 1800 + dir * 900;
#pragma unroll
                        for (int g = 0; g < 3; g++) {
                            gr[h][0][g] = grp[g * 300 + j0];
                            gr[h][1][g] = grp[g * 300 + j1];
                        }
                    } else {
                        int trow = (dir == 0) ? tn : (T - 1 - tn);
                        int src = b + 1 - KF + trow;
                        if (src >= 0) {
                            const float* grp = gi + (size_t)src * 1800 + dir * 900;
#pragma unroll
                            for (int g = 0; g < 3; g++) {
                                gr[h][0][g] = grp[g * 300 + j0];
                                gr[h][1][g] = grp[g * 300 + j1];
                            }
                        } else {
#pragma unroll
                            for (int g = 0; g < 3; g++) {
                                gr[h][0][g] = bi[g][0];
                                gr[h][1][g] = bi[g][1];
                            }
                        }
                    }
                }
            }
        }
        cur ^= 1;
        if (t < T - 1) group_barrier(gslot, gen0 + (unsigned)t + 1u);
    }

    if (MODE == 0 && kthird == 0) {
#pragma unroll
        for (int uq = 0; uq < 2; uq++) {
            int jj = uq ? j1 : j0;
            if (okA) maxpool[b_lo * (2 * HDIM) + dir * HDIM + jj] = mpA[uq];
            if (okB) maxpool[b_hi * (2 * HDIM) + dir * HDIM + jj] = mpB[uq];
        }
    }
}

// ---------------- persistent attention-GRU scan v6 (one hop) ----------------
__global__ __launch_bounds__(480, 1)
void att_scan6(float* __restrict__ h0, float* __restrict__ h1,
               const float* __restrict__ xr,   // [40*127, 1800]
               const float* __restrict__ xw,
               const float* __restrict__ Ur,   // [3,2,300,300]
               const float* __restrict__ Uw,
               const float* __restrict__ bur,  // [3,2,300]
               const float* __restrict__ bu,
               const float* __restrict__ gates, // [40*127]
               int hop)
{
    extern __shared__ float sm[];
    float* Ws = sm;                      // 6000 floats (persists)
    float* Hs = sm + 6000;               // 19200 floats
    u64*   red = (u64*)(sm + 25200);     // 2560 u64

    const int tid    = threadIdx.x;
    const int brow   = tid & 31;
    const int uu     = (tid >> 5) % 5;
    const int kthird = tid / 160;
    const int lig    = tid - kthird * 160;
    const int jgrp = blockIdx.x, bgrp = blockIdx.y, dir = blockIdx.z;
    const int j0 = jgrp * 10 + uu;
    const int j1 = j0 + 5;
    const int wd = hop * 2 + dir;
    const int dirbase = dir * NQ * HDIM;
    const int b0 = bgrp * 64;
    const int b_lo = b0 + brow, b_hi = b_lo + 32;
    const int gslot = (dir * 2 + bgrp) * 32;

    const unsigned gen0 = *(volatile unsigned*)&g_gen[gslot];

    for (int idx = tid; idx < 1500; idx += 480) {
        int row = idx / 75, q = idx % 75;
        int g = row / 10, ju = row % 10;
        const float* Wsrc = g ? Uw : Ur;
        ((float4*)Ws)[row * 75 + q] = ((const float4*)(Wsrc +
            ((size_t)wd * 300 + jgrp * 10 + ju) * 300))[q];
    }
    float bv[2][2];  // [gate r/w][unit]
    bv[0][0] = bur[wd * 300 + j0]; bv[0][1] = bur[wd * 300 + j1];
    bv[1][0] = bu[wd * 300 + j0];  bv[1][1] = bu[wd * 300 + j1];
    const bool okA = (b_lo < NQ), okB = (b_hi < NQ);

    float xrv[2][2], xwv[2][2], gv[2];
    if (kthird == 0) {
        int tt0 = (dir == 0) ? 0 : (KF - 1);
#pragma unroll
        for (int h = 0; h < 2; h++) {
            int b = h ? b_hi : b_lo;
            bool ok = h ? okB : okA;
            if (ok) {
                size_t base = ((size_t)tt0 * NQ + b) * 1800 + wd * 300;
                xrv[h][0] = xr[base + j0]; xrv[h][1] = xr[base + j1];
                xwv[h][0] = xw[base + j0]; xwv[h][1] = xw[base + j1];
                gv[h] = gates[tt0 * NQ + b];
            }
        }
    }

    int cur = 0;
    for (int t = 0; t < KF; t++) {
        const float* hp = cur ? h1 : h0;
        float*       hn = cur ? h0 : h1;

        if (t > 0) {
            for (int idx = tid; idx < 4800; idx += 480) {
                int bl = idx / 75, q = idx % 75;
                int b = b0 + bl;
                float4 v = make_float4(0.f, 0.f, 0.f, 0.f);
                if (b < NQ) v = __ldcg(((const float4*)(hp + dirbase + (size_t)b * 300)) + q);
                ((float4*)Hs)[idx] = v;
            }
        }
        __syncthreads();

        u64 acc[2][2][2] = {};  // [gate][unit][half]
        float holdA[2] = {0.f, 0.f}, holdB[2] = {0.f, 0.f};
        if (t > 0) {
            const ulonglong2* r0p = (const ulonglong2*)(Ws + (0  + uu) * 300 + kthird * 100);
            const ulonglong2* r1p = (const ulonglong2*)(Ws + (0  + uu + 5) * 300 + kthird * 100);
            const ulonglong2* w0p = (const ulonglong2*)(Ws + (10 + uu) * 300 + kthird * 100);
            const ulonglong2* w1p = (const ulonglong2*)(Ws + (10 + uu + 5) * 300 + kthird * 100);
            const ulonglong2* hA = (const ulonglong2*)(Hs + brow * 300 + kthird * 100);
#pragma unroll 5
            for (int q = 0; q < 25; q++) {
                ulonglong2 ha = hA[q], hb = hA[q + 2400];
                ulonglong2 w;
                w = r0p[q];
                acc[0][0][0] = f2fma(ha.x, w.x, acc[0][0][0]); acc[0][0][0] = f2fma(ha.y, w.y, acc[0][0][0]);
                acc[0][0][1] = f2fma(hb.x, w.x, acc[0][0][1]); acc[0][0][1] = f2fma(hb.y, w.y, acc[0][0][1]);
                w = r1p[q];
                acc[0][1][0] = f2fma(ha.x, w.x, acc[0][1][0]); acc[0][1][0] = f2fma(ha.y, w.y, acc[0][1][0]);
                acc[0][1][1] = f2fma(hb.x, w.x, acc[0][1][1]); acc[0][1][1] = f2fma(hb.y, w.y, acc[0][1][1]);
                w = w0p[q];
                acc[1][0][0] = f2fma(ha.x, w.x, acc[1][0][0]); acc[1][0][0] = f2fma(ha.y, w.y, acc[1][0][0]);
                acc[1][0][1] = f2fma(hb.x, w.x, acc[1][0][1]); acc[1][0][1] = f2fma(hb.y, w.y, acc[1][0][1]);
                w = w1p[q];
                acc[1][1][0] = f2fma(ha.x, w.x, acc[1][1][0]); acc[1][1][0] = f2fma(ha.y, w.y, acc[1][1][0]);
                acc[1][1][1] = f2fma(hb.x, w.x, acc[1][1][1]); acc[1][1][1] = f2fma(hb.y, w.y, acc[1][1][1]);
            }
            if (kthird == 0) {
                holdA[0] = okA ? Hs[brow * 300 + j0] : 0.f;
                holdA[1] = okA ? Hs[brow * 300 + j1] : 0.f;
                holdB[0] = okB ? Hs[(brow + 32) * 300 + j0] : 0.f;
                holdB[1] = okB ? Hs[(brow + 32) * 300 + j1] : 0.f;
            }
            __syncthreads();
            if (kthird > 0) {
                u64* rp = red + ((size_t)(kthird - 1) * 160 + lig) * 8;
#pragma unroll
                for (int g = 0; g < 2; g++)
#pragma unroll
                    for (int uq = 0; uq < 2; uq++) {
                        rp[(g * 2 + uq) * 2 + 0] = acc[g][uq][0];
                        rp[(g * 2 + uq) * 2 + 1] = acc[g][uq][1];
                    }
            }
            __syncthreads();
            if (kthird == 0) {
#pragma unroll
                for (int kt = 0; kt < 2; kt++) {
                    const u64* rp = red + ((size_t)kt * 160 + lig) * 8;
#pragma unroll
                    for (int g = 0; g < 2; g++)
#pragma unroll
                        for (int uq = 0; uq < 2; uq++) {
                            acc[g][uq][0] = f2add(acc[g][uq][0], rp[(g * 2 + uq) * 2 + 0]);
                            acc[g][uq][1] = f2add(acc[g][uq][1], rp[(g * 2 + uq) * 2 + 1]);
                        }
                }
            }
        }

        if (kthird == 0) {
#pragma unroll
            for (int h = 0; h < 2; h++) {
                int b = h ? b_hi : b_lo;
                bool ok = h ? okB : okA;
                if (!ok) continue;
#pragma unroll
                for (int uq = 0; uq < 2; uq++) {
                    int jj = uq ? j1 : j0;
                    float hold = h ? holdB[uq] : holdA[uq];
                    float r  = sigf(xrv[h][uq] + hsum2(acc[0][uq][h]) + bv[0][uq]);
                    float ht = tanhf(xwv[h][uq] + r * (hsum2(acc[1][uq][h]) + bv[1][uq]));
                    hn[dirbase + (size_t)b * 300 + jj] = gv[h] * ht + (1.f - gv[h]) * hold;
                }
            }
            if (t + 1 < KF) {
                int tn = (dir == 0) ? (t + 1) : (KF - 2 - t);
#pragma unroll
                for (int h = 0; h < 2; h++) {
                    int b = h ? b_hi : b_lo;
                    bool ok = h ? okB : okA;
                    if (ok) {
                        size_t base = ((size_t)tn * NQ + b) * 1800 + wd * 300;
                        xrv[h][0] = xr[base + j0]; xrv[h][1] = xr[base + j1];
                        xwv[h][0] = xw[base + j0]; xwv[h][1] = xw[base + j1];
                        gv[h] = gates[tn * NQ + b];
                    }
                }
            }
        }
        cur ^= 1;
        if (t < KF - 1) group_barrier(gslot, gen0 + (unsigned)t + 1u);
    }
}

// ---------------- small kernels ----------------
__global__ __launch_bounds__(256)
void lin_kernel(const float* __restrict__ mp, const float* __restrict__ w,
                const float* __restrict__ bsc, float* __restrict__ u) {
    int b = blockIdx.x;
    __shared__ float m[600];
    for (int i = threadIdx.x; i < 600; i += 256) m[i] = mp[b * 600 + i];
    __syncthreads();
    int wid = threadIdx.x >> 5, lane = threadIdx.x & 31;
    for (int j = wid; j < HDIM; j += 8) {
        float acc = 0.f;
        const float* wr = w + (size_t)j * 600;
        for (int k = lane; k < 600; k += 32) acc += m[k] * wr[k];
        for (int o = 16; o > 0; o >>= 1) acc += __shfl_xor_sync(0xffffffffu, acc, o);
        if (lane == 0) u[b * HDIM + j] = tanhf(acc + bsc[j]);
    }
}

__global__ void build_inp0(const float* __restrict__ u, float* __restrict__ inp0) {
    int idx = blockIdx.x * blockDim.x + threadIdx.x;
    if (idx >= KF * NQ * HDIM) return;
    int j = idx % HDIM;
    int r = idx / HDIM;
    int i = r % NQ;
    int k = r / NQ;
    int src = (i + 1) - KF + k;
    inp0[idx] = (src >= 0) ? u[src * HDIM + j] : 0.f;
}

__global__ void membank_kernel(const float* __restrict__ inp0,
                               const float* __restrict__ seq,
                               float* __restrict__ mem) {
    int idx = blockIdx.x * blockDim.x + threadIdx.x;
    if (idx >= KF * NQ * HDIM) return;
    int j = idx % HDIM;
    int r = idx / HDIM;
    int i = r % NQ;
    int k = r / NQ;
    float f = seq[((size_t)k) * NQ * HDIM + i * HDIM + j];
    float b = seq[((size_t)KF + (KF - 1 - k)) * NQ * HDIM + i * HDIM + j];
    mem[idx] = inp0[idx] + f + b;
}

__global__ void score_kernel(const float* __restrict__ query,
                             const float* __restrict__ mem,
                             float* __restrict__ gates) {
    int b = blockIdx.x;                 // 0..126
    int tid = threadIdx.x;              // 128
    int lane = tid & 31, w = tid >> 5;
    __shared__ float q[HDIM];
    __shared__ float logit[KF];
    for (int i = tid; i < HDIM; i += 128) q[i] = query[b * HDIM + i];
    __syncthreads();
    for (int k = w; k < KF; k += 4) {
        const float* mrow = mem + ((size_t)k * NQ + b) * HDIM;
        float s = 0.f;
        for (int i = lane; i < HDIM; i += 32) s += q[i] * mrow[i];
        for (int o = 16; o > 0; o >>= 1) s += __shfl_xor_sync(0xffffffffu, s, o);
        if (lane == 0) logit[k] = (k >= KF - 1 - b) ? s : -1e10f;
    }
    __syncthreads();
    if (w == 0) {
        float m = -INFINITY;
        for (int k = lane; k < KF; k += 32) m = fmaxf(m, logit[k]);
        for (int o = 16; o > 0; o >>= 1) m = fmaxf(m, __shfl_xor_sync(0xffffffffu, m, o));
        float ssum = 0.f;
        for (int k = lane; k < KF; k += 32) { float e = expf(logit[k] - m); logit[k] = e; ssum += e; }
        for (int o = 16; o > 0; o >>= 1) ssum += __shfl_xor_sync(0xffffffffu, ssum, o);
        for (int k = lane; k < KF; k += 32) gates[k * NQ + b] = logit[k] / ssum;
    }
}

__global__ void add2_kernel(float* __restrict__ q,
                            const float* __restrict__ hf,
                            const float* __restrict__ hb, int n) {
    int i = blockIdx.x * blockDim.x + threadIdx.x;
    if (i < n) q[i] += hf[i] + hb[i];
}

__global__ void cls_kernel(const float* __restrict__ u,
                           const float* __restrict__ query,
                           const float* __restrict__ cls_w,
                           const float* __restrict__ cls_b,
                           float* __restrict__ out) {
    int row = blockIdx.x;               // 0..127
    int w = threadIdx.x >> 5, lane = threadIdx.x & 31;   // 192 threads = 6 warps
    const float* s = (row == 0) ? u : (query + (row - 1) * HDIM);
    float acc = 0.f;
    for (int i = lane; i < HDIM; i += 32) acc += s[i] * cls_w[w * HDIM + i];
    for (int o = 16; o > 0; o >>= 1) acc += __shfl_xor_sync(0xffffffffu, acc, o);
    if (lane == 0) out[row * NCLS + w] = acc + cls_b[w];
}

// ---------------- host orchestration ----------------
extern "C" void kernel_launch(void* const* d_in, const int* in_sizes, int n_in,
                              void* d_out, int out_size) {
    const int*   ids      = (const int*)d_in[0];
    const int*   seq_lens = (const int*)d_in[1];
    const float* emb      = (const float*)d_in[2];
    const float* utt_Wih  = (const float*)d_in[3];
    const float* utt_Whh  = (const float*)d_in[4];
    const float* utt_bih  = (const float*)d_in[5];
    const float* utt_bhh  = (const float*)d_in[6];
    const float* lin_w    = (const float*)d_in[7];
    const float* lin_b    = (const float*)d_in[8];
    const float* ctx_Wih  = (const float*)d_in[9];
    const float* ctx_Whh  = (const float*)d_in[10];
    const float* ctx_bih  = (const float*)d_in[11];
    const float* ctx_bhh  = (const float*)d_in[12];
    const float* aWr_w    = (const float*)d_in[13];
    const float* aWr_b    = (const float*)d_in[14];
    const float* aUr_w    = (const float*)d_in[15];
    const float* aUr_b    = (const float*)d_in[16];
    const float* aW_w     = (const float*)d_in[17];
    const float* aW_b     = (const float*)d_in[18];
    const float* aU_w     = (const float*)d_in[19];
    const float* aU_b     = (const float*)d_in[20];
    const float* cls_w    = (const float*)d_in[21];
    const float* cls_b    = (const float*)d_in[22];
    float* out = (float*)d_out;

    float *gi_utt, *h_utt, *maxpool, *u, *inp0, *proj, *seq_ctx, *h_ctx;
    float *mem, *xr, *xw, *gates, *query, *h_att;
    cudaGetSymbolAddress((void**)&gi_utt,  g_gi_utt);
    cudaGetSymbolAddress((void**)&h_utt,   g_h_utt);
    cudaGetSymbolAddress((void**)&maxpool, g_maxpool);
    cudaGetSymbolAddress((void**)&u,       g_u);
    cudaGetSymbolAddress((void**)&inp0,    g_inp0);
    cudaGetSymbolAddress((void**)&proj,    g_proj);
    cudaGetSymbolAddress((void**)&seq_ctx, g_seq_ctx);
    cudaGetSymbolAddress((void**)&h_ctx,   g_h_ctx);
    cudaGetSymbolAddress((void**)&mem,     g_mem);
    cudaGetSymbolAddress((void**)&xr,      g_xr);
    cudaGetSymbolAddress((void**)&xw,      g_xw);
    cudaGetSymbolAddress((void**)&gates,   g_gates);
    cudaGetSymbolAddress((void**)&query,   g_query);
    cudaGetSymbolAddress((void**)&h_att,   g_h_att);

    float* hU0 = h_utt;  float* hU1 = h_utt + 2 * NB * HDIM;
    float* hC0 = h_ctx;  float* hC1 = h_ctx + 2 * NQ * HDIM;
    float* hA0 = h_att;  float* hA1 = h_att + 2 * NQ * HDIM;

    const int GRU_SMEM = 28200 * 4 + 3840 * 8;   // 143520 B
    const int ATT_SMEM = 25200 * 4 + 2560 * 8;   // 121280 B
    cudaFuncSetAttribute(gru_scan7<0>, cudaFuncAttributeMaxDynamicSharedMemorySize, GRU_SMEM);
    cudaFuncSetAttribute(gru_scan7<1>, cudaFuncAttributeMaxDynamicSharedMemorySize, GRU_SMEM);
    cudaFuncSetAttribute(att_scan6,    cudaFuncAttributeMaxDynamicSharedMemorySize, ATT_SMEM);

    cudaStream_t s = 0;
    dim3 sg(30, 2, 2);

    // ---- utterance GRU input projection (gathered emb) ----
    {
        dim3 g((1800 + GTN - 1) / GTN, (LSEQ * NB + GTM - 1) / GTM);
        gemm3<1><<<g, 256, 0, s>>>(nullptr, 0, utt_Wih, utt_bih,
                                   gi_utt, 1800, LSEQ * NB, 1800, EDIM, emb, ids);
    }
    // ---- utterance GRU scan (ONE persistent launch) ----
    gru_scan7<0><<<sg, 480, GRU_SMEM, s>>>(hU0, hU1, gi_utt, utt_Whh, utt_bhh,
                                           nullptr, seq_lens, maxpool, nullptr,
                                           NB, LSEQ);

    // ---- u = tanh(maxpool @ lin_w^T + lin_b) ----
    lin_kernel<<<NB, 256, 0, s>>>(maxpool, lin_w, lin_b, u);

    // ---- ctx projection DEDUPED: proj127 = u[0:127] @ ctx_Wih^T + ctx_bih ----
    {
        dim3 g((1800 + GTN - 1) / GTN, (NQ + GTM - 1) / GTM);   // 29 x 2 blocks
        gemm3<0><<<g, 256, 0, s>>>(u, HDIM, ctx_Wih, ctx_bih,
                                   proj, 1800, NQ, 1800, HDIM, nullptr, nullptr);
    }
    // inp0 still needed for membank
    build_inp0<<<(KF * NQ * HDIM + 255) / 256, 256, 0, s>>>(u, inp0);

    // ---- ctx GRU scan (gi gathered from proj127 inside the kernel) ----
    gru_scan7<1><<<sg, 480, GRU_SMEM, s>>>(hC0, hC1, proj, ctx_Whh, ctx_bhh,
                                           ctx_bih, nullptr, nullptr, seq_ctx,
                                           NQ, KF);

    membank_kernel<<<(KF * NQ * HDIM + 255) / 256, 256, 0, s>>>(inp0, seq_ctx, mem);

    // ---- attention x-projections (hop-invariant; one GEMM each) ----
    {
        dim3 g((1800 + GTN - 1) / GTN, (KF * NQ + GTM - 1) / GTM);
        gemm3<0><<<g, 256, 0, s>>>(mem, HDIM, aWr_w, aWr_b,
                                   xr, 1800, KF * NQ, 1800, HDIM, nullptr, nullptr);
        gemm3<0><<<g, 256, 0, s>>>(mem, HDIM, aW_w, aW_b,
                                   xw, 1800, KF * NQ, 1800, HDIM, nullptr, nullptr);
    }

    // ---- query init + hops ----
    cudaMemcpyAsync(query, u + HDIM, NQ * HDIM * sizeof(float),
                    cudaMemcpyDeviceToDevice, s);
    for (int hop = 0; hop < NHOPS; hop++) {
        score_kernel<<<NQ, 128, 0, s>>>(query, mem, gates);
        att_scan6<<<sg, 480, ATT_SMEM, s>>>(hA0, hA1, xr, xw,
                                            aUr_w, aU_w, aUr_b, aU_b, gates, hop);
        // KF=40 even: final state lands in hA0
        add2_kernel<<<(NQ * HDIM + 255) / 256, 256, 0, s>>>(
            query, hA0, hA0 + NQ * HDIM, NQ * HDIM);
    }

    // ---- classifier ----
    cls_kernel<<<NB, 192, 0, s>>>(u, query, cls_w, cls_b, out);
}

// round 15
// speedup vs baseline: 1.2339x; 1.0100x over previous
#include <cuda_runtime.h>
#include <math.h>

#define NB   128   // N dialogues
#define LSEQ 64    // L
#define EDIM 300
#define HDIM 300
#define KF   40    // KEFF
#define NQ   127   // N-1
#define NHOPS 3
#define NCLS 6

typedef unsigned long long u64;

// ---------------- scratch (device globals; no allocation) ----------------
__device__ float g_gi_utt[(size_t)LSEQ * NB * 1800];     // [t*128+b, 1800]
__device__ float g_h_utt[2][2 * NB * HDIM];
__device__ float g_maxpool[NB * 2 * HDIM];
__device__ float g_u[NB * HDIM];
__device__ float g_inp0[KF * NQ * HDIM];                 // ctx_t time-major
__device__ float g_proj[NQ * 1800];                      // u[0:127] @ ctx_Wih^T + bih
__device__ float g_seq_ctx[2 * KF * NQ * HDIM];          // [dir, t, i, j]
__device__ float g_h_ctx[2][2 * NQ * HDIM];
__device__ float g_mem[KF * NQ * HDIM];                  // time-major [k,i,j]
__device__ float g_xr[(size_t)KF * NQ * 1800];
__device__ float g_xw[(size_t)KF * NQ * 1800];
__device__ float g_gates[KF * NQ];
__device__ float g_query[NQ * HDIM];
__device__ float g_h_att[2][2 * NQ * HDIM];

// group barrier state: 4 groups, padded to separate 128B lines
__device__ unsigned g_cnt[128];   // zero-initialized; returns to 0 each use
__device__ unsigned g_gen[128];   // monotonic forever (never reset)

__device__ __forceinline__ float sigf(float x) { return 1.f / (1.f + expf(-x)); }

// ---------------- packed f32x2 helpers ----------------
__device__ __forceinline__ u64 pk2(float x, float y) {
    u64 r; asm("mov.b64 %0, {%1, %2};" : "=l"(r) : "f"(x), "f"(y)); return r;
}
__device__ __forceinline__ float2 unpk(u64 v) {
    float2 f; asm("mov.b64 {%0, %1}, %2;" : "=f"(f.x), "=f"(f.y) : "l"(v)); return f;
}
__device__ __forceinline__ u64 f2fma(u64 a, u64 b, u64 c) {
    u64 d; asm("fma.rn.f32x2 %0, %1, %2, %3;" : "=l"(d) : "l"(a), "l"(b), "l"(c));
    return d;
}
__device__ __forceinline__ u64 f2add(u64 a, u64 b) {
    u64 d; asm("add.rn.f32x2 %0, %1, %2;" : "=l"(d) : "l"(a), "l"(b));
    return d;
}
__device__ __forceinline__ float hsum2(u64 v) {
    float2 f = unpk(v); return f.x + f.y;
}

// 30-block group barrier; leader resets cnt BEFORE bumping gen.
__device__ __forceinline__ void group_barrier(int gslot, unsigned target) {
    __threadfence();
    __syncthreads();
    if (threadIdx.x == 0) {
        unsigned old = atomicAdd(&g_cnt[gslot], 1u);
        if (old == 29u) {
            atomicExch(&g_cnt[gslot], 0u);
            __threadfence();
            atomicAdd(&g_gen[gslot], 1u);
        } else {
            while (*(volatile unsigned*)&g_gen[gslot] < target) __nanosleep(32);
        }
        __threadfence();
    }
    __syncthreads();
}

// ---------------- GEMM v4 (f32x2, register double-buffered) ----------------
// C = A(MxK) @ W(NxK)^T + bias
#define GTM 64
#define GTN 64
#define GTK 16

template<int GATHER>
__global__ __launch_bounds__(256)
void gemm4(const float* __restrict__ A, int lda,
           const float* __restrict__ W,
           const float* __restrict__ bias,
           float* __restrict__ C, int ldc,
           int M, int N, int K,
           const float* __restrict__ emb,
           const int* __restrict__ ids)
{
    __shared__ __align__(16) u64   Ad[GTK][66];   // A dup'd: (a,a) per [kk][mm]
    __shared__ __align__(16) float Bs[GTK][66];
    __shared__ int rowid[GTM];
    const int tid = threadIdx.x;
    const int m0 = blockIdx.y * GTM;
    const int n0 = blockIdx.x * GTN;

    if (GATHER) {
        if (tid < GTM) {
            int m = m0 + tid;
            int t = m >> 7, b = m & 127;          // m = t*128 + b
            rowid[tid] = (m < M) ? ids[b * LSEQ + t] : 0;
        }
        __syncthreads();
    }

    // per-thread staging coordinates (fixed across k0)
    int amm[4], akk[4], bnn[4], bkk[4];
#pragma unroll
    for (int i = 0; i < 4; i++) {
        int idx = tid + i * 256;
        amm[i] = idx >> 4; akk[i] = idx & 15;
        bnn[i] = idx >> 4; bkk[i] = idx & 15;
    }

    float aReg[4], bReg[4];
    // preload tile k0 = 0
#pragma unroll
    for (int i = 0; i < 4; i++) {
        int m = m0 + amm[i], k = akk[i];
        float v = 0.f;
        if (m < M && k < K)
            v = GATHER ? emb[(size_t)rowid[amm[i]] * K + k] : A[(size_t)m * lda + k];
        aReg[i] = v;
        int n = n0 + bnn[i], kb = bkk[i];
        bReg[i] = (n < N && kb < K) ? W[(size_t)n * K + kb] : 0.f;
    }

    u64 acc[4][2] = {};
    const int mt = tid >> 4;   // 0..15
    const int nt = tid & 15;   // 0..15

    for (int k0 = 0; k0 < K; k0 += GTK) {
        // commit staged regs to smem
#pragma unroll
        for (int i = 0; i < 4; i++) {
            Ad[akk[i]][amm[i]] = pk2(aReg[i], aReg[i]);
            Bs[bkk[i]][bnn[i]] = bReg[i];
        }
        __syncthreads();

        // prefetch next tile into regs (overlaps the FFMA2 block below)
        int kn = k0 + GTK;
        if (kn < K) {
#pragma unroll
            for (int i = 0; i < 4; i++) {
                int m = m0 + amm[i], k = kn + akk[i];
                float v = 0.f;
                if (m < M && k < K)
                    v = GATHER ? emb[(size_t)rowid[amm[i]] * K + k]
                               : A[(size_t)m * lda + k];
                aReg[i] = v;
                int n = n0 + bnn[i], kb = kn + bkk[i];
                bReg[i] = (n < N && kb < K) ? W[(size_t)n * K + kb] : 0.f;
            }
        }

#pragma unroll
        for (int kk = 0; kk < GTK; kk++) {
            ulonglong2 a01 = *(const ulonglong2*)&Ad[kk][mt * 4];
            ulonglong2 a23 = *(const ulonglong2*)&Ad[kk][mt * 4 + 2];
            u64 b0 = *(const u64*)&Bs[kk][nt * 4];
            u64 b1 = *(const u64*)&Bs[kk][nt * 4 + 2];
            acc[0][0] = f2fma(a01.x, b0, acc[0][0]);
            acc[0][1] = f2fma(a01.x, b1, acc[0][1]);
            acc[1][0] = f2fma(a01.y, b0, acc[1][0]);
            acc[1][1] = f2fma(a01.y, b1, acc[1][1]);
            acc[2][0] = f2fma(a23.x, b0, acc[2][0]);
            acc[2][1] = f2fma(a23.x, b1, acc[2][1]);
            acc[3][0] = f2fma(a23.y, b0, acc[3][0]);
            acc[3][1] = f2fma(a23.y, b1, acc[3][1]);
        }
        __syncthreads();
    }
#pragma unroll
    for (int i = 0; i < 4; i++) {
        int m = m0 + mt * 4 + i;
        if (m >= M) continue;
#pragma unroll
        for (int p = 0; p < 2; p++) {
            float2 v = unpk(acc[i][p]);
            int n = n0 + nt * 4 + 2 * p;
            if (n < N)     C[(size_t)m * ldc + n]     = v.x + bias[n];
            if (n + 1 < N) C[(size_t)m * ldc + n + 1] = v.y + bias[n + 1];
        }
    }
}

// ---------------- persistent GRU scan v7 (n_j=2, 480 thr, gi prefetch) -----
// Grid (30 jgrp, 2 bgrp, 2 dir) = 120 blocks, 1/SM.
// MODE 0: utt — gi indexed [trow*B+b]*1800 (per-step rows)
// MODE 1: ctx — gi = proj127 [src*1800], src = b+1-KF+trow; bih when src<0
template<int MODE>
__global__ __launch_bounds__(480, 1)
void gru_scan7(float* __restrict__ h0, float* __restrict__ h1,
               const float* __restrict__ gi,
               const float* __restrict__ Whh,     // [2,900,300]
               const float* __restrict__ bhh,     // [2,900]
               const float* __restrict__ bih,     // [2,900] (MODE 1 only)
               const int*   __restrict__ seq_lens,
               float* __restrict__ maxpool,       // [B, 600]
               float* __restrict__ seqout,        // [2,T,B,300]
               int B, int T)
{
    extern __shared__ float sm[];
    float* Ws = sm;                      // 9000 floats (persists)
    float* Hs = sm + 9000;               // 19200 floats
    u64*   red = (u64*)(sm + 28200);     // 3840 u64

    const int tid    = threadIdx.x;
    const int brow   = tid & 31;
    const int uu     = (tid >> 5) % 5;
    const int kthird = tid / 160;
    const int lig    = tid - kthird * 160;
    const int jgrp = blockIdx.x, bgrp = blockIdx.y, dir = blockIdx.z;
    const int j0 = jgrp * 10 + uu;
    const int j1 = j0 + 5;
    const int dirbase = dir * B * HDIM;
    const int b0 = bgrp * 64;
    const int b_lo = b0 + brow, b_hi = b_lo + 32;
    const int gslot = (dir * 2 + bgrp) * 32;

    const unsigned gen0 = *(volatile unsigned*)&g_gen[gslot];

    // stage weights once: 30 rows x 75 float4
    for (int idx = tid; idx < 2250; idx += 480) {
        int row = idx / 75, q = idx % 75;
        int g = row / 10, ju = row % 10;
        ((float4*)Ws)[row * 75 + q] = ((const float4*)(Whh +
            ((size_t)dir * 900 + g * 300 + jgrp * 10 + ju) * 300))[q];
    }
    // biases for 2 units x 3 gates
    float bh[3][2], bi[3][2];
#pragma unroll
    for (int g = 0; g < 3; g++) {
        bh[g][0] = bhh[dir * 900 + g * 300 + j0];
        bh[g][1] = bhh[dir * 900 + g * 300 + j1];
        if (MODE == 1) {
            bi[g][0] = bih[dir * 900 + g * 300 + j0];
            bi[g][1] = bih[dir * 900 + g * 300 + j1];
        }
    }
    const bool okA = (b_lo < B), okB = (b_hi < B);
    int lenA = T, lenB = T;
    if (MODE == 0) {
        lenA = okA ? seq_lens[b_lo] : 1;
        lenB = okB ? seq_lens[b_hi] : 1;
    }
    float mpA[2] = { -1e30f, -1e30f }, mpB[2] = { -1e30f, -1e30f };

    // gi prefetch regs: gr[half][unit][gate]
    float gr[2][2][3];
    if (kthird == 0) {
#pragma unroll
        for (int h = 0; h < 2; h++) {
            int b = h ? b_hi : b_lo;
            bool ok = h ? okB : okA;
            int len = h ? lenB : lenA;
            if (!ok) continue;
            if (MODE == 0) {
                int trow = (dir == 0) ? 0 : max(len - 1, 0);
                const float* grp = gi + ((size_t)trow * B + b) * 1800 + dir * 900;
#pragma unroll
                for (int g = 0; g < 3; g++) {
                    gr[h][0][g] = grp[g * 300 + j0];
                    gr[h][1][g] = grp[g * 300 + j1];
                }
            } else {
                int trow = (dir == 0) ? 0 : (T - 1);
                int src = b + 1 - KF + trow;
                if (src >= 0) {
                    const float* grp = gi + (size_t)src * 1800 + dir * 900;
#pragma unroll
                    for (int g = 0; g < 3; g++) {
                        gr[h][0][g] = grp[g * 300 + j0];
                        gr[h][1][g] = grp[g * 300 + j1];
                    }
                } else {
#pragma unroll
                    for (int g = 0; g < 3; g++) {
                        gr[h][0][g] = bi[g][0];
                        gr[h][1][g] = bi[g][1];
                    }
                }
            }
        }
    }

    int cur = 0;
    for (int t = 0; t < T; t++) {
        const float* hp = cur ? h1 : h0;
        float*       hn = cur ? h0 : h1;

        if (t > 0) {
            for (int idx = tid; idx < 4800; idx += 480) {
                int bl = idx / 75, q = idx % 75;
                int b = b0 + bl;
                float4 v = make_float4(0.f, 0.f, 0.f, 0.f);
                if (b < B) v = __ldcg(((const float4*)(hp + dirbase + (size_t)b * 300)) + q);
                ((float4*)Hs)[idx] = v;
            }
        }
        __syncthreads();

        u64 acc[3][2][2] = {};   // [gate][unit][half]
        float holdA[2] = {0.f, 0.f}, holdB[2] = {0.f, 0.f};
        if (t > 0) {
            const ulonglong2* w0p = (const ulonglong2*)(Ws + (0  + uu) * 300 + kthird * 100);
            const ulonglong2* w1p = (const ulonglong2*)(Ws + (0  + uu + 5) * 300 + kthird * 100);
            const ulonglong2* z0p = (const ulonglong2*)(Ws + (10 + uu) * 300 + kthird * 100);
            const ulonglong2* z1p = (const ulonglong2*)(Ws + (10 + uu + 5) * 300 + kthird * 100);
            const ulonglong2* n0p = (const ulonglong2*)(Ws + (20 + uu) * 300 + kthird * 100);
            const ulonglong2* n1p = (const ulonglong2*)(Ws + (20 + uu + 5) * 300 + kthird * 100);
            const ulonglong2* hA = (const ulonglong2*)(Hs + brow * 300 + kthird * 100);
#pragma unroll 5
            for (int q = 0; q < 25; q++) {
                ulonglong2 ha = hA[q], hb = hA[q + 2400];
                ulonglong2 w;
                w = w0p[q];
                acc[0][0][0] = f2fma(ha.x, w.x, acc[0][0][0]); acc[0][0][0] = f2fma(ha.y, w.y, acc[0][0][0]);
                acc[0][0][1] = f2fma(hb.x, w.x, acc[0][0][1]); acc[0][0][1] = f2fma(hb.y, w.y, acc[0][0][1]);
                w = w1p[q];
                acc[0][1][0] = f2fma(ha.x, w.x, acc[0][1][0]); acc[0][1][0] = f2fma(ha.y, w.y, acc[0][1][0]);
                acc[0][1][1] = f2fma(hb.x, w.x, acc[0][1][1]); acc[0][1][1] = f2fma(hb.y, w.y, acc[0][1][1]);
                w = z0p[q];
                acc[1][0][0] = f2fma(ha.x, w.x, acc[1][0][0]); acc[1][0][0] = f2fma(ha.y, w.y, acc[1][0][0]);
                acc[1][0][1] = f2fma(hb.x, w.x, acc[1][0][1]); acc[1][0][1] = f2fma(hb.y, w.y, acc[1][0][1]);
                w = z1p[q];
                acc[1][1][0] = f2fma(ha.x, w.x, acc[1][1][0]); acc[1][1][0] = f2fma(ha.y, w.y, acc[1][1][0]);
                acc[1][1][1] = f2fma(hb.x, w.x, acc[1][1][1]); acc[1][1][1] = f2fma(hb.y, w.y, acc[1][1][1]);
                w = n0p[q];
                acc[2][0][0] = f2fma(ha.x, w.x, acc[2][0][0]); acc[2][0][0] = f2fma(ha.y, w.y, acc[2][0][0]);
                acc[2][0][1] = f2fma(hb.x, w.x, acc[2][0][1]); acc[2][0][1] = f2fma(hb.y, w.y, acc[2][0][1]);
                w = n1p[q];
                acc[2][1][0] = f2fma(ha.x, w.x, acc[2][1][0]); acc[2][1][0] = f2fma(ha.y, w.y, acc[2][1][0]);
                acc[2][1][1] = f2fma(hb.x, w.x, acc[2][1][1]); acc[2][1][1] = f2fma(hb.y, w.y, acc[2][1][1]);
            }
            if (kthird == 0) {
                holdA[0] = okA ? Hs[brow * 300 + j0] : 0.f;
                holdA[1] = okA ? Hs[brow * 300 + j1] : 0.f;
                holdB[0] = okB ? Hs[(brow + 32) * 300 + j0] : 0.f;
                holdB[1] = okB ? Hs[(brow + 32) * 300 + j1] : 0.f;
            }
            __syncthreads();
            if (kthird > 0) {
                u64* rp = red + ((size_t)(kthird - 1) * 160 + lig) * 12;
#pragma unroll
                for (int g = 0; g < 3; g++)
#pragma unroll
                    for (int uq = 0; uq < 2; uq++) {
                        rp[(g * 2 + uq) * 2 + 0] = acc[g][uq][0];
                        rp[(g * 2 + uq) * 2 + 1] = acc[g][uq][1];
                    }
            }
            __syncthreads();
            if (kthird == 0) {
#pragma unroll
                for (int kt = 0; kt < 2; kt++) {
                    const u64* rp = red + ((size_t)kt * 160 + lig) * 12;
#pragma unroll
                    for (int g = 0; g < 3; g++)
#pragma unroll
                        for (int uq = 0; uq < 2; uq++) {
                            acc[g][uq][0] = f2add(acc[g][uq][0], rp[(g * 2 + uq) * 2 + 0]);
                            acc[g][uq][1] = f2add(acc[g][uq][1], rp[(g * 2 + uq) * 2 + 1]);
                        }
                }
            }
        }

        if (kthird == 0) {
#pragma unroll
            for (int h = 0; h < 2; h++) {
                int b = h ? b_hi : b_lo;
                bool ok = h ? okB : okA;
                if (!ok) continue;
                int len = h ? lenB : lenA;
                bool msk = (MODE != 0) || (t < len);
#pragma unroll
                for (int uq = 0; uq < 2; uq++) {
                    int jj = uq ? j1 : j0;
                    float hold = h ? holdB[uq] : holdA[uq];
                    float r = sigf(gr[h][uq][0] + hsum2(acc[0][uq][h]) + bh[0][uq]);
                    float z = sigf(gr[h][uq][1] + hsum2(acc[1][uq][h]) + bh[1][uq]);
                    float n = tanhf(gr[h][uq][2] + r * (hsum2(acc[2][uq][h]) + bh[2][uq]));
                    float hnew = (1.f - z) * n + z * hold;
                    if (MODE == 0) {
                        hn[dirbase + (size_t)b * 300 + jj] = msk ? hnew : hold;
                        float mp = msk ? hnew : 0.f;
                        if (h) mpB[uq] = fmaxf(mpB[uq], mp);
                        else   mpA[uq] = fmaxf(mpA[uq], mp);
                    } else {
                        hn[dirbase + (size_t)b * 300 + jj] = hnew;
                        seqout[(((size_t)dir * T + t) * B + b) * 300 + jj] = hnew;
                    }
                }
            }
            // prefetch gi for t+1 (independent of h; overlaps the barrier)
            if (t + 1 < T) {
                int tn = t + 1;
#pragma unroll
                for (int h = 0; h < 2; h++) {
                    int b = h ? b_hi : b_lo;
                    bool ok = h ? okB : okA;
                    int len = h ? lenB : lenA;
                    if (!ok) continue;
                    if (MODE == 0) {
                        int trow = (dir == 0) ? tn : max(len - 1 - tn, 0);
                        const float* grp = gi + ((size_t)trow * B + b) * 1800 + dir * 900;
#pragma unroll
                        for (int g = 0; g < 3; g++) {
                            gr[h][0][g] = grp[g * 300 + j0];
                            gr[h][1][g] = grp[g * 300 + j1];
                        }
                    } else {
                        int trow = (dir == 0) ? tn : (T - 1 - tn);
                        int src = b + 1 - KF + trow;
                        if (src >= 0) {
                            const float* grp = gi + (size_t)src * 1800 + dir * 900;
#pragma unroll
                            for (int g = 0; g < 3; g++) {
                                gr[h][0][g] = grp[g * 300 + j0];
                                gr[h][1][g] = grp[g * 300 + j1];
                            }
                        } else {
#pragma unroll
                            for (int g = 0; g < 3; g++) {
                                gr[h][0][g] = bi[g][0];
                                gr[h][1][g] = bi[g][1];
                            }
                        }
                    }
                }
            }
        }
        cur ^= 1;
        if (t < T - 1) group_barrier(gslot, gen0 + (unsigned)t + 1u);
    }

    if (MODE == 0 && kthird == 0) {
#pragma unroll
        for (int uq = 0; uq < 2; uq++) {
            int jj = uq ? j1 : j0;
            if (okA) maxpool[b_lo * (2 * HDIM) + dir * HDIM + jj] = mpA[uq];
            if (okB) maxpool[b_hi * (2 * HDIM) + dir * HDIM + jj] = mpB[uq];
        }
    }
}

// ---------------- persistent attention-GRU scan v6 (one hop) ----------------
__global__ __launch_bounds__(480, 1)
void att_scan6(float* __restrict__ h0, float* __restrict__ h1,
               const float* __restrict__ xr,   // [40*127, 1800]
               const float* __restrict__ xw,
               const float* __restrict__ Ur,   // [3,2,300,300]
               const float* __restrict__ Uw,
               const float* __restrict__ bur,  // [3,2,300]
               const float* __restrict__ bu,
               const float* __restrict__ gates, // [40*127]
               int hop)
{
    extern __shared__ float sm[];
    float* Ws = sm;                      // 6000 floats (persists)
    float* Hs = sm + 6000;               // 19200 floats
    u64*   red = (u64*)(sm + 25200);     // 2560 u64

    const int tid    = threadIdx.x;
    const int brow   = tid & 31;
    const int uu     = (tid >> 5) % 5;
    const int kthird = tid / 160;
    const int lig    = tid - kthird * 160;
    const int jgrp = blockIdx.x, bgrp = blockIdx.y, dir = blockIdx.z;
    const int j0 = jgrp * 10 + uu;
    const int j1 = j0 + 5;
    const int wd = hop * 2 + dir;
    const int dirbase = dir * NQ * HDIM;
    const int b0 = bgrp * 64;
    const int b_lo = b0 + brow, b_hi = b_lo + 32;
    const int gslot = (dir * 2 + bgrp) * 32;

    const unsigned gen0 = *(volatile unsigned*)&g_gen[gslot];

    for (int idx = tid; idx < 1500; idx += 480) {
        int row = idx / 75, q = idx % 75;
        int g = row / 10, ju = row % 10;
        const float* Wsrc = g ? Uw : Ur;
        ((float4*)Ws)[row * 75 + q] = ((const float4*)(Wsrc +
            ((size_t)wd * 300 + jgrp * 10 + ju) * 300))[q];
    }
    float bv[2][2];  // [gate r/w][unit]
    bv[0][0] = bur[wd * 300 + j0]; bv[0][1] = bur[wd * 300 + j1];
    bv[1][0] = bu[wd * 300 + j0];  bv[1][1] = bu[wd * 300 + j1];
    const bool okA = (b_lo < NQ), okB = (b_hi < NQ);

    float xrv[2][2], xwv[2][2], gv[2];
    if (kthird == 0) {
        int tt0 = (dir == 0) ? 0 : (KF - 1);
#pragma unroll
        for (int h = 0; h < 2; h++) {
            int b = h ? b_hi : b_lo;
            bool ok = h ? okB : okA;
            if (ok) {
                size_t base = ((size_t)tt0 * NQ + b) * 1800 + wd * 300;
                xrv[h][0] = xr[base + j0]; xrv[h][1] = xr[base + j1];
                xwv[h][0] = xw[base + j0]; xwv[h][1] = xw[base + j1];
                gv[h] = gates[tt0 * NQ + b];
            }
        }
    }

    int cur = 0;
    for (int t = 0; t < KF; t++) {
        const float* hp = cur ? h1 : h0;
        float*       hn = cur ? h0 : h1;

        if (t > 0) {
            for (int idx = tid; idx < 4800; idx += 480) {
                int bl = idx / 75, q = idx % 75;
                int b = b0 + bl;
                float4 v = make_float4(0.f, 0.f, 0.f, 0.f);
                if (b < NQ) v = __ldcg(((const float4*)(hp + dirbase + (size_t)b * 300)) + q);
                ((float4*)Hs)[idx] = v;
            }
        }
        __syncthreads();

        u64 acc[2][2][2] = {};  // [gate][unit][half]
        float holdA[2] = {0.f, 0.f}, holdB[2] = {0.f, 0.f};
        if (t > 0) {
            const ulonglong2* r0p = (const ulonglong2*)(Ws + (0  + uu) * 300 + kthird * 100);
            const ulonglong2* r1p = (const ulonglong2*)(Ws + (0  + uu + 5) * 300 + kthird * 100);
            const ulonglong2* w0p = (const ulonglong2*)(Ws + (10 + uu) * 300 + kthird * 100);
            const ulonglong2* w1p = (const ulonglong2*)(Ws + (10 + uu + 5) * 300 + kthird * 100);
            const ulonglong2* hA = (const ulonglong2*)(Hs + brow * 300 + kthird * 100);
#pragma unroll 5
            for (int q = 0; q < 25; q++) {
                ulonglong2 ha = hA[q], hb = hA[q + 2400];
                ulonglong2 w;
                w = r0p[q];
                acc[0][0][0] = f2fma(ha.x, w.x, acc[0][0][0]); acc[0][0][0] = f2fma(ha.y, w.y, acc[0][0][0]);
                acc[0][0][1] = f2fma(hb.x, w.x, acc[0][0][1]); acc[0][0][1] = f2fma(hb.y, w.y, acc[0][0][1]);
                w = r1p[q];
                acc[0][1][0] = f2fma(ha.x, w.x, acc[0][1][0]); acc[0][1][0] = f2fma(ha.y, w.y, acc[0][1][0]);
                acc[0][1][1] = f2fma(hb.x, w.x, acc[0][1][1]); acc[0][1][1] = f2fma(hb.y, w.y, acc[0][1][1]);
                w = w0p[q];
                acc[1][0][0] = f2fma(ha.x, w.x, acc[1][0][0]); acc[1][0][0] = f2fma(ha.y, w.y, acc[1][0][0]);
                acc[1][0][1] = f2fma(hb.x, w.x, acc[1][0][1]); acc[1][0][1] = f2fma(hb.y, w.y, acc[1][0][1]);
                w = w1p[q];
                acc[1][1][0] = f2fma(ha.x, w.x, acc[1][1][0]); acc[1][1][0] = f2fma(ha.y, w.y, acc[1][1][0]);
                acc[1][1][1] = f2fma(hb.x, w.x, acc[1][1][1]); acc[1][1][1] = f2fma(hb.y, w.y, acc[1][1][1]);
            }
            if (kthird == 0) {
                holdA[0] = okA ? Hs[brow * 300 + j0] : 0.f;
                holdA[1] = okA ? Hs[brow * 300 + j1] : 0.f;
                holdB[0] = okB ? Hs[(brow + 32) * 300 + j0] : 0.f;
                holdB[1] = okB ? Hs[(brow + 32) * 300 + j1] : 0.f;
            }
            __syncthreads();
            if (kthird > 0) {
                u64* rp = red + ((size_t)(kthird - 1) * 160 + lig) * 8;
#pragma unroll
                for (int g = 0; g < 2; g++)
#pragma unroll
                    for (int uq = 0; uq < 2; uq++) {
                        rp[(g * 2 + uq) * 2 + 0] = acc[g][uq][0];
                        rp[(g * 2 + uq) * 2 + 1] = acc[g][uq][1];
                    }
            }
            __syncthreads();
            if (kthird == 0) {
#pragma unroll
                for (int kt = 0; kt < 2; kt++) {
                    const u64* rp = red + ((size_t)kt * 160 + lig) * 8;
#pragma unroll
                    for (int g = 0; g < 2; g++)
#pragma unroll
                        for (int uq = 0; uq < 2; uq++) {
                            acc[g][uq][0] = f2add(acc[g][uq][0], rp[(g * 2 + uq) * 2 + 0]);
                            acc[g][uq][1] = f2add(acc[g][uq][1], rp[(g * 2 + uq) * 2 + 1]);
                        }
                }
            }
        }

        if (kthird == 0) {
#pragma unroll
            for (int h = 0; h < 2; h++) {
                int b = h ? b_hi : b_lo;
                bool ok = h ? okB : okA;
                if (!ok) continue;
#pragma unroll
                for (int uq = 0; uq < 2; uq++) {
                    int jj = uq ? j1 : j0;
                    float hold = h ? holdB[uq] : holdA[uq];
                    float r  = sigf(xrv[h][uq] + hsum2(acc[0][uq][h]) + bv[0][uq]);
                    float ht = tanhf(xwv[h][uq] + r * (hsum2(acc[1][uq][h]) + bv[1][uq]));
                    hn[dirbase + (size_t)b * 300 + jj] = gv[h] * ht + (1.f - gv[h]) * hold;
                }
            }
            if (t + 1 < KF) {
                int tn = (dir == 0) ? (t + 1) : (KF - 2 - t);
#pragma unroll
                for (int h = 0; h < 2; h++) {
                    int b = h ? b_hi : b_lo;
                    bool ok = h ? okB : okA;
                    if (ok) {
                        size_t base = ((size_t)tn * NQ + b) * 1800 + wd * 300;
                        xrv[h][0] = xr[base + j0]; xrv[h][1] = xr[base + j1];
                        xwv[h][0] = xw[base + j0]; xwv[h][1] = xw[base + j1];
                        gv[h] = gates[tn * NQ + b];
                    }
                }
            }
        }
        cur ^= 1;
        if (t < KF - 1) group_barrier(gslot, gen0 + (unsigned)t + 1u);
    }
}

// ---------------- small kernels ----------------
__global__ __launch_bounds__(256)
void lin_kernel(const float* __restrict__ mp, const float* __restrict__ w,
                const float* __restrict__ bsc, float* __restrict__ u) {
    int b = blockIdx.x;
    __shared__ float m[600];
    for (int i = threadIdx.x; i < 600; i += 256) m[i] = mp[b * 600 + i];
    __syncthreads();
    int wid = threadIdx.x >> 5, lane = threadIdx.x & 31;
    for (int j = wid; j < HDIM; j += 8) {
        float acc = 0.f;
        const float* wr = w + (size_t)j * 600;
        for (int k = lane; k < 600; k += 32) acc += m[k] * wr[k];
        for (int o = 16; o > 0; o >>= 1) acc += __shfl_xor_sync(0xffffffffu, acc, o);
        if (lane == 0) u[b * HDIM + j] = tanhf(acc + bsc[j]);
    }
}

__global__ void build_inp0(const float* __restrict__ u, float* __restrict__ inp0) {
    int idx = blockIdx.x * blockDim.x + threadIdx.x;
    if (idx >= KF * NQ * HDIM) return;
    int j = idx % HDIM;
    int r = idx / HDIM;
    int i = r % NQ;
    int k = r / NQ;
    int src = (i + 1) - KF + k;
    inp0[idx] = (src >= 0) ? u[src * HDIM + j] : 0.f;
}

__global__ void membank_kernel(const float* __restrict__ inp0,
                               const float* __restrict__ seq,
                               float* __restrict__ mem) {
    int idx = blockIdx.x * blockDim.x + threadIdx.x;
    if (idx >= KF * NQ * HDIM) return;
    int j = idx % HDIM;
    int r = idx / HDIM;
    int i = r % NQ;
    int k = r / NQ;
    float f = seq[((size_t)k) * NQ * HDIM + i * HDIM + j];
    float b = seq[((size_t)KF + (KF - 1 - k)) * NQ * HDIM + i * HDIM + j];
    mem[idx] = inp0[idx] + f + b;
}

__global__ void score_kernel(const float* __restrict__ query,
                             const float* __restrict__ mem,
                             float* __restrict__ gates) {
    int b = blockIdx.x;                 // 0..126
    int tid = threadIdx.x;              // 128
    int lane = tid & 31, w = tid >> 5;
    __shared__ float q[HDIM];
    __shared__ float logit[KF];
    for (int i = tid; i < HDIM; i += 128) q[i] = query[b * HDIM + i];
    __syncthreads();
    for (int k = w; k < KF; k += 4) {
        const float* mrow = mem + ((size_t)k * NQ + b) * HDIM;
        float s = 0.f;
        for (int i = lane; i < HDIM; i += 32) s += q[i] * mrow[i];
        for (int o = 16; o > 0; o >>= 1) s += __shfl_xor_sync(0xffffffffu, s, o);
        if (lane == 0) logit[k] = (k >= KF - 1 - b) ? s : -1e10f;
    }
    __syncthreads();
    if (w == 0) {
        float m = -INFINITY;
        for (int k = lane; k < KF; k += 32) m = fmaxf(m, logit[k]);
        for (int o = 16; o > 0; o >>= 1) m = fmaxf(m, __shfl_xor_sync(0xffffffffu, m, o));
        float ssum = 0.f;
        for (int k = lane; k < KF; k += 32) { float e = expf(logit[k] - m); logit[k] = e; ssum += e; }
        for (int o = 16; o > 0; o >>= 1) ssum += __shfl_xor_sync(0xffffffffu, ssum, o);
        for (int k = lane; k < KF; k += 32) gates[k * NQ + b] = logit[k] / ssum;
    }
}

__global__ void add2_kernel(float* __restrict__ q,
                            const float* __restrict__ hf,
                            const float* __restrict__ hb, int n) {
    int i = blockIdx.x * blockDim.x + threadIdx.x;
    if (i < n) q[i] += hf[i] + hb[i];
}

__global__ void cls_kernel(const float* __restrict__ u,
                           const float* __restrict__ query,
                           const float* __restrict__ cls_w,
                           const float* __restrict__ cls_b,
                           float* __restrict__ out) {
    int row = blockIdx.x;               // 0..127
    int w = threadIdx.x >> 5, lane = threadIdx.x & 31;   // 192 threads = 6 warps
    const float* s = (row == 0) ? u : (query + (row - 1) * HDIM);
    float acc = 0.f;
    for (int i = lane; i < HDIM; i += 32) acc += s[i] * cls_w[w * HDIM + i];
    for (int o = 16; o > 0; o >>= 1) acc += __shfl_xor_sync(0xffffffffu, acc, o);
    if (lane == 0) out[row * NCLS + w] = acc + cls_b[w];
}

// ---------------- host orchestration ----------------
extern "C" void kernel_launch(void* const* d_in, const int* in_sizes, int n_in,
                              void* d_out, int out_size) {
    const int*   ids      = (const int*)d_in[0];
    const int*   seq_lens = (const int*)d_in[1];
    const float* emb      = (const float*)d_in[2];
    const float* utt_Wih  = (const float*)d_in[3];
    const float* utt_Whh  = (const float*)d_in[4];
    const float* utt_bih  = (const float*)d_in[5];
    const float* utt_bhh  = (const float*)d_in[6];
    const float* lin_w    = (const float*)d_in[7];
    const float* lin_b    = (const float*)d_in[8];
    const float* ctx_Wih  = (const float*)d_in[9];
    const float* ctx_Whh  = (const float*)d_in[10];
    const float* ctx_bih  = (const float*)d_in[11];
    const float* ctx_bhh  = (const float*)d_in[12];
    const float* aWr_w    = (const float*)d_in[13];
    const float* aWr_b    = (const float*)d_in[14];
    const float* aUr_w    = (const float*)d_in[15];
    const float* aUr_b    = (const float*)d_in[16];
    const float* aW_w     = (const float*)d_in[17];
    const float* aW_b     = (const float*)d_in[18];
    const float* aU_w     = (const float*)d_in[19];
    const float* aU_b     = (const float*)d_in[20];
    const float* cls_w    = (const float*)d_in[21];
    const float* cls_b    = (const float*)d_in[22];
    float* out = (float*)d_out;

    float *gi_utt, *h_utt, *maxpool, *u, *inp0, *proj, *seq_ctx, *h_ctx;
    float *mem, *xr, *xw, *gates, *query, *h_att;
    cudaGetSymbolAddress((void**)&gi_utt,  g_gi_utt);
    cudaGetSymbolAddress((void**)&h_utt,   g_h_utt);
    cudaGetSymbolAddress((void**)&maxpool, g_maxpool);
    cudaGetSymbolAddress((void**)&u,       g_u);
    cudaGetSymbolAddress((void**)&inp0,    g_inp0);
    cudaGetSymbolAddress((void**)&proj,    g_proj);
    cudaGetSymbolAddress((void**)&seq_ctx, g_seq_ctx);
    cudaGetSymbolAddress((void**)&h_ctx,   g_h_ctx);
    cudaGetSymbolAddress((void**)&mem,     g_mem);
    cudaGetSymbolAddress((void**)&xr,      g_xr);
    cudaGetSymbolAddress((void**)&xw,      g_xw);
    cudaGetSymbolAddress((void**)&gates,   g_gates);
    cudaGetSymbolAddress((void**)&query,   g_query);
    cudaGetSymbolAddress((void**)&h_att,   g_h_att);

    float* hU0 = h_utt;  float* hU1 = h_utt + 2 * NB * HDIM;
    float* hC0 = h_ctx;  float* hC1 = h_ctx + 2 * NQ * HDIM;
    float* hA0 = h_att;  float* hA1 = h_att + 2 * NQ * HDIM;

    const int GRU_SMEM = 28200 * 4 + 3840 * 8;   // 143520 B
    const int ATT_SMEM = 25200 * 4 + 2560 * 8;   // 121280 B
    cudaFuncSetAttribute(gru_scan7<0>, cudaFuncAttributeMaxDynamicSharedMemorySize, GRU_SMEM);
    cudaFuncSetAttribute(gru_scan7<1>, cudaFuncAttributeMaxDynamicSharedMemorySize, GRU_SMEM);
    cudaFuncSetAttribute(att_scan6,    cudaFuncAttributeMaxDynamicSharedMemorySize, ATT_SMEM);

    cudaStream_t s = 0;
    dim3 sg(30, 2, 2);

    // ---- utterance GRU input projection (gathered emb) ----
    {
        dim3 g((1800 + GTN - 1) / GTN, (LSEQ * NB + GTM - 1) / GTM);
        gemm4<1><<<g, 256, 0, s>>>(nullptr, 0, utt_Wih, utt_bih,
                                   gi_utt, 1800, LSEQ * NB, 1800, EDIM, emb, ids);
    }
    // ---- utterance GRU scan (ONE persistent launch) ----
    gru_scan7<0><<<sg, 480, GRU_SMEM, s>>>(hU0, hU1, gi_utt, utt_Whh, utt_bhh,
                                           nullptr, seq_lens, maxpool, nullptr,
                                           NB, LSEQ);

    // ---- u = tanh(maxpool @ lin_w^T + lin_b) ----
    lin_kernel<<<NB, 256, 0, s>>>(maxpool, lin_w, lin_b, u);

    // ---- ctx projection DEDUPED: proj127 = u[0:127] @ ctx_Wih^T + ctx_bih ----
    {
        dim3 g((1800 + GTN - 1) / GTN, (NQ + GTM - 1) / GTM);   // 29 x 2 blocks
        gemm4<0><<<g, 256, 0, s>>>(u, HDIM, ctx_Wih, ctx_bih,
                                   proj, 1800, NQ, 1800, HDIM, nullptr, nullptr);
    }
    // inp0 still needed for membank
    build_inp0<<<(KF * NQ * HDIM + 255) / 256, 256, 0, s>>>(u, inp0);

    // ---- ctx GRU scan (gi gathered from proj127 inside the kernel) ----
    gru_scan7<1><<<sg, 480, GRU_SMEM, s>>>(hC0, hC1, proj, ctx_Whh, ctx_bhh,
                                           ctx_bih, nullptr, nullptr, seq_ctx,
                                           NQ, KF);

    membank_kernel<<<(KF * NQ * HDIM + 255) / 256, 256, 0, s>>>(inp0, seq_ctx, mem);

    // ---- attention x-projections (hop-invariant; one GEMM each) ----
    {
        dim3 g((1800 + GTN - 1) / GTN, (KF * NQ + GTM - 1) / GTM);
        gemm4<0><<<g, 256, 0, s>>>(mem, HDIM, aWr_w, aWr_b,
                                   xr, 1800, KF * NQ, 1800, HDIM, nullptr, nullptr);
        gemm4<0><<<g, 256, 0, s>>>(mem, HDIM, aW_w, aW_b,
                                   xw, 1800, KF * NQ, 1800, HDIM, nullptr, nullptr);
    }

    // ---- query init + hops ----
    cudaMemcpyAsync(query, u + HDIM, NQ * HDIM * sizeof(float),
                    cudaMemcpyDeviceToDevice, s);
    for (int hop = 0; hop < NHOPS; hop++) {
        score_kernel<<<NQ, 128, 0, s>>>(query, mem, gates);
        att_scan6<<<sg, 480, ATT_SMEM, s>>>(hA0, hA1, xr, xw,
                                            aUr_w, aU_w, aUr_b, aU_b, gates, hop);
        // KF=40 even: final state lands in hA0
        add2_kernel<<<(NQ * HDIM + 255) / 256, 256, 0, s>>>(
            query, hA0, hA0 + NQ * HDIM, NQ * HDIM);
    }

    // ---- classifier ----
    cls_kernel<<<NB, 192, 0, s>>>(u, query, cls_w, cls_b, out);
}

// round 16
// speedup vs baseline: 1.3092x; 1.0610x over previous
#include <cuda_runtime.h>
#include <math.h>

#define NB   128   // N dialogues
#define LSEQ 64    // L
#define EDIM 300
#define HDIM 300
#define KF   40    // KEFF
#define NQ   127   // N-1
#define NHOPS 3
#define NCLS 6

typedef unsigned long long u64;

// ---------------- scratch (device globals; no allocation) ----------------
__device__ float g_gi_utt[(size_t)LSEQ * NB * 1800];     // [t*128+b, 1800]
__device__ float g_h_utt[2][2 * NB * HDIM];
__device__ float g_maxpool[NB * 2 * HDIM];
__device__ float g_u[NB * HDIM];
__device__ float g_inp0[KF * NQ * HDIM];                 // ctx_t time-major
__device__ float g_proj[NQ * 1800];                      // u[0:127] @ ctx_Wih^T + bih
__device__ float g_seq_ctx[2 * KF * NQ * HDIM];          // [dir, t, i, j]
__device__ float g_h_ctx[2][2 * NQ * HDIM];
__device__ float g_mem[KF * NQ * HDIM];                  // time-major [k,i,j]
__device__ float g_xr[(size_t)KF * NQ * 1800];
__device__ float g_xw[(size_t)KF * NQ * 1800];
__device__ float g_gates[KF * NQ];
__device__ float g_query[NQ * HDIM];
__device__ float g_h_att[2][2 * NQ * HDIM];

// group barrier state: 4 groups, padded to separate 128B lines
__device__ unsigned g_cnt[128];   // zero-initialized; returns to 0 each use
__device__ unsigned g_gen[128];   // monotonic forever (never reset)

__device__ __forceinline__ float sigf(float x) { return 1.f / (1.f + expf(-x)); }

// ---------------- packed f32x2 helpers ----------------
__device__ __forceinline__ u64 pk2(float x, float y) {
    u64 r; asm("mov.b64 %0, {%1, %2};" : "=l"(r) : "f"(x), "f"(y)); return r;
}
__device__ __forceinline__ float2 unpk(u64 v) {
    float2 f; asm("mov.b64 {%0, %1}, %2;" : "=f"(f.x), "=f"(f.y) : "l"(v)); return f;
}
__device__ __forceinline__ u64 f2fma(u64 a, u64 b, u64 c) {
    u64 d; asm("fma.rn.f32x2 %0, %1, %2, %3;" : "=l"(d) : "l"(a), "l"(b), "l"(c));
    return d;
}
__device__ __forceinline__ u64 f2add(u64 a, u64 b) {
    u64 d; asm("add.rn.f32x2 %0, %1, %2;" : "=l"(d) : "l"(a), "l"(b));
    return d;
}
__device__ __forceinline__ float hsum2(u64 v) {
    float2 f = unpk(v); return f.x + f.y;
}

// 30-block group barrier; leader resets cnt BEFORE bumping gen.
__device__ __forceinline__ void group_barrier(int gslot, unsigned target) {
    __threadfence();
    __syncthreads();
    if (threadIdx.x == 0) {
        unsigned old = atomicAdd(&g_cnt[gslot], 1u);
        if (old == 29u) {
            atomicExch(&g_cnt[gslot], 0u);
            __threadfence();
            atomicAdd(&g_gen[gslot], 1u);
        } else {
            while (*(volatile unsigned*)&g_gen[gslot] < target) __nanosleep(32);
        }
        __threadfence();
    }
    __syncthreads();
}

// ---------------- GEMM v4 (64x64, f32x2, reg double-buffered) ---------------
#define GTM 64
#define GTN 64
#define GTK 16

template<int GATHER>
__global__ __launch_bounds__(256)
void gemm4(const float* __restrict__ A, int lda,
           const float* __restrict__ W,
           const float* __restrict__ bias,
           float* __restrict__ C, int ldc,
           int M, int N, int K,
           const float* __restrict__ emb,
           const int* __restrict__ ids)
{
    __shared__ __align__(16) u64   Ad[GTK][66];
    __shared__ __align__(16) float Bs[GTK][66];
    __shared__ int rowid[GTM];
    const int tid = threadIdx.x;
    const int m0 = blockIdx.y * GTM;
    const int n0 = blockIdx.x * GTN;

    if (GATHER) {
        if (tid < GTM) {
            int m = m0 + tid;
            int t = m >> 7, b = m & 127;
            rowid[tid] = (m < M) ? ids[b * LSEQ + t] : 0;
        }
        __syncthreads();
    }

    int amm[4], akk[4];
#pragma unroll
    for (int i = 0; i < 4; i++) {
        int idx = tid + i * 256;
        amm[i] = idx >> 4; akk[i] = idx & 15;
    }

    float aReg[4], bReg[4];
#pragma unroll
    for (int i = 0; i < 4; i++) {
        int m = m0 + amm[i], k = akk[i];
        float v = 0.f;
        if (m < M && k < K)
            v = GATHER ? emb[(size_t)rowid[amm[i]] * K + k] : A[(size_t)m * lda + k];
        aReg[i] = v;
        int n = n0 + amm[i];
        bReg[i] = (n < N && k < K) ? W[(size_t)n * K + k] : 0.f;
    }

    u64 acc[4][2] = {};
    const int mt = tid >> 4;
    const int nt = tid & 15;

    for (int k0 = 0; k0 < K; k0 += GTK) {
#pragma unroll
        for (int i = 0; i < 4; i++) {
            Ad[akk[i]][amm[i]] = pk2(aReg[i], aReg[i]);
            Bs[akk[i]][amm[i]] = bReg[i];
        }
        __syncthreads();

        int kn = k0 + GTK;
        if (kn < K) {
#pragma unroll
            for (int i = 0; i < 4; i++) {
                int m = m0 + amm[i], k = kn + akk[i];
                float v = 0.f;
                if (m < M && k < K)
                    v = GATHER ? emb[(size_t)rowid[amm[i]] * K + k]
                               : A[(size_t)m * lda + k];
                aReg[i] = v;
                int n = n0 + amm[i];
                bReg[i] = (n < N && k < K) ? W[(size_t)n * K + k] : 0.f;
            }
        }

#pragma unroll
        for (int kk = 0; kk < GTK; kk++) {
            ulonglong2 a01 = *(const ulonglong2*)&Ad[kk][mt * 4];
            ulonglong2 a23 = *(const ulonglong2*)&Ad[kk][mt * 4 + 2];
            u64 b0 = *(const u64*)&Bs[kk][nt * 4];
            u64 b1 = *(const u64*)&Bs[kk][nt * 4 + 2];
            acc[0][0] = f2fma(a01.x, b0, acc[0][0]);
            acc[0][1] = f2fma(a01.x, b1, acc[0][1]);
            acc[1][0] = f2fma(a01.y, b0, acc[1][0]);
            acc[1][1] = f2fma(a01.y, b1, acc[1][1]);
            acc[2][0] = f2fma(a23.x, b0, acc[2][0]);
            acc[2][1] = f2fma(a23.x, b1, acc[2][1]);
            acc[3][0] = f2fma(a23.y, b0, acc[3][0]);
            acc[3][1] = f2fma(a23.y, b1, acc[3][1]);
        }
        __syncthreads();
    }
#pragma unroll
    for (int i = 0; i < 4; i++) {
        int m = m0 + mt * 4 + i;
        if (m >= M) continue;
#pragma unroll
        for (int p = 0; p < 2; p++) {
            float2 v = unpk(acc[i][p]);
            int n = n0 + nt * 4 + 2 * p;
            if (n < N)     C[(size_t)m * ldc + n]     = v.x + bias[n];
            if (n + 1 < N) C[(size_t)m * ldc + n + 1] = v.y + bias[n + 1];
        }
    }
}

// ---------------- GEMM v5 (128x64, f32x2, reg double-buffered) --------------
// Per thread: 8 m x 4 n. Inner kk: 16 f2fma : 6 LDS (2.67:1).
#define G5M 128

template<int GATHER>
__global__ __launch_bounds__(256)
void gemm5(const float* __restrict__ A, int lda,
           const float* __restrict__ W,
           const float* __restrict__ bias,
           float* __restrict__ C, int ldc,
           int M, int N, int K,
           const float* __restrict__ emb,
           const int* __restrict__ ids)
{
    __shared__ __align__(16) u64   Ad[GTK][130];   // 128 + 2 pad
    __shared__ __align__(16) float Bs[GTK][66];
    __shared__ int rowid[G5M];
    const int tid = threadIdx.x;
    const int m0 = blockIdx.y * G5M;
    const int n0 = blockIdx.x * GTN;

    if (GATHER) {
        if (tid < G5M) {
            int m = m0 + tid;
            int t = m >> 7, b = m & 127;
            rowid[tid] = (m < M) ? ids[b * LSEQ + t] : 0;
        }
        __syncthreads();
    }

    // staging coords: A 2048 elems (8/thread), B 1024 elems (4/thread)
    int amm[8], akk[8];
#pragma unroll
    for (int i = 0; i < 8; i++) {
        int idx = tid + i * 256;
        amm[i] = idx >> 4; akk[i] = idx & 15;
    }

    float aReg[8], bReg[4];
#pragma unroll
    for (int i = 0; i < 8; i++) {
        int m = m0 + amm[i], k = akk[i];
        float v = 0.f;
        if (m < M && k < K)
            v = GATHER ? emb[(size_t)rowid[amm[i]] * K + k] : A[(size_t)m * lda + k];
        aReg[i] = v;
    }
#pragma unroll
    for (int i = 0; i < 4; i++) {
        int n = n0 + amm[i], k = akk[i];
        bReg[i] = (n < N && k < K) ? W[(size_t)n * K + k] : 0.f;
    }

    u64 acc[8][2] = {};
    const int mt = tid >> 4;   // 0..15, rows mt*8..mt*8+7
    const int nt = tid & 15;   // 0..15, cols nt*4..nt*4+3

    for (int k0 = 0; k0 < K; k0 += GTK) {
#pragma unroll
        for (int i = 0; i < 8; i++)
            Ad[akk[i]][amm[i]] = pk2(aReg[i], aReg[i]);
#pragma unroll
        for (int i = 0; i < 4; i++)
            Bs[akk[i]][amm[i]] = bReg[i];
        __syncthreads();

        int kn = k0 + GTK;
        if (kn < K) {
#pragma unroll
            for (int i = 0; i < 8; i++) {
                int m = m0 + amm[i], k = kn + akk[i];
                float v = 0.f;
                if (m < M && k < K)
                    v = GATHER ? emb[(size_t)rowid[amm[i]] * K + k]
                               : A[(size_t)m * lda + k];
                aReg[i] = v;
            }
#pragma unroll
            for (int i = 0; i < 4; i++) {
                int n = n0 + amm[i], k = kn + akk[i];
                bReg[i] = (n < N && k < K) ? W[(size_t)n * K + k] : 0.f;
            }
        }

#pragma unroll
        for (int kk = 0; kk < GTK; kk++) {
            ulonglong2 a01 = *(const ulonglong2*)&Ad[kk][mt * 8];
            ulonglong2 a23 = *(const ulonglong2*)&Ad[kk][mt * 8 + 2];
            ulonglong2 a45 = *(const ulonglong2*)&Ad[kk][mt * 8 + 4];
            ulonglong2 a67 = *(const ulonglong2*)&Ad[kk][mt * 8 + 6];
            u64 b0 = *(const u64*)&Bs[kk][nt * 4];
            u64 b1 = *(const u64*)&Bs[kk][nt * 4 + 2];
            acc[0][0] = f2fma(a01.x, b0, acc[0][0]);
            acc[0][1] = f2fma(a01.x, b1, acc[0][1]);
            acc[1][0] = f2fma(a01.y, b0, acc[1][0]);
            acc[1][1] = f2fma(a01.y, b1, acc[1][1]);
            acc[2][0] = f2fma(a23.x, b0, acc[2][0]);
            acc[2][1] = f2fma(a23.x, b1, acc[2][1]);
            acc[3][0] = f2fma(a23.y, b0, acc[3][0]);
            acc[3][1] = f2fma(a23.y, b1, acc[3][1]);
            acc[4][0] = f2fma(a45.x, b0, acc[4][0]);
            acc[4][1] = f2fma(a45.x, b1, acc[4][1]);
            acc[5][0] = f2fma(a45.y, b0, acc[5][0]);
            acc[5][1] = f2fma(a45.y, b1, acc[5][1]);
            acc[6][0] = f2fma(a67.x, b0, acc[6][0]);
            acc[6][1] = f2fma(a67.x, b1, acc[6][1]);
            acc[7][0] = f2fma(a67.y, b0, acc[7][0]);
            acc[7][1] = f2fma(a67.y, b1, acc[7][1]);
        }
        __syncthreads();
    }
#pragma unroll
    for (int i = 0; i < 8; i++) {
        int m = m0 + mt * 8 + i;
        if (m >= M) continue;
#pragma unroll
        for (int p = 0; p < 2; p++) {
            float2 v = unpk(acc[i][p]);
            int n = n0 + nt * 4 + 2 * p;
            if (n < N)     C[(size_t)m * ldc + n]     = v.x + bias[n];
            if (n + 1 < N) C[(size_t)m * ldc + n + 1] = v.y + bias[n + 1];
        }
    }
}

// ---------------- persistent GRU scan v7 (n_j=2, 480 thr, gi prefetch) -----
template<int MODE>
__global__ __launch_bounds__(480, 1)
void gru_scan7(float* __restrict__ h0, float* __restrict__ h1,
               const float* __restrict__ gi,
               const float* __restrict__ Whh,     // [2,900,300]
               const float* __restrict__ bhh,     // [2,900]
               const float* __restrict__ bih,     // [2,900] (MODE 1 only)
               const int*   __restrict__ seq_lens,
               float* __restrict__ maxpool,       // [B, 600]
               float* __restrict__ seqout,        // [2,T,B,300]
               int B, int T)
{
    extern __shared__ float sm[];
    float* Ws = sm;                      // 9000 floats (persists)
    float* Hs = sm + 9000;               // 19200 floats
    u64*   red = (u64*)(sm + 28200);     // 3840 u64

    const int tid    = threadIdx.x;
    const int brow   = tid & 31;
    const int uu     = (tid >> 5) % 5;
    const int kthird = tid / 160;
    const int lig    = tid - kthird * 160;
    const int jgrp = blockIdx.x, bgrp = blockIdx.y, dir = blockIdx.z;
    const int j0 = jgrp * 10 + uu;
    const int j1 = j0 + 5;
    const int dirbase = dir * B * HDIM;
    const int b0 = bgrp * 64;
    const int b_lo = b0 + brow, b_hi = b_lo + 32;
    const int gslot = (dir * 2 + bgrp) * 32;

    const unsigned gen0 = *(volatile unsigned*)&g_gen[gslot];

    for (int idx = tid; idx < 2250; idx += 480) {
        int row = idx / 75, q = idx % 75;
        int g = row / 10, ju = row % 10;
        ((float4*)Ws)[row * 75 + q] = ((const float4*)(Whh +
            ((size_t)dir * 900 + g * 300 + jgrp * 10 + ju) * 300))[q];
    }
    float bh[3][2], bi[3][2];
#pragma unroll
    for (int g = 0; g < 3; g++) {
        bh[g][0] = bhh[dir * 900 + g * 300 + j0];
        bh[g][1] = bhh[dir * 900 + g * 300 + j1];
        if (MODE == 1) {
            bi[g][0] = bih[dir * 900 + g * 300 + j0];
            bi[g][1] = bih[dir * 900 + g * 300 + j1];
        }
    }
    const bool okA = (b_lo < B), okB = (b_hi < B);
    int lenA = T, lenB = T;
    if (MODE == 0) {
        lenA = okA ? seq_lens[b_lo] : 1;
        lenB = okB ? seq_lens[b_hi] : 1;
    }
    float mpA[2] = { -1e30f, -1e30f }, mpB[2] = { -1e30f, -1e30f };

    float gr[2][2][3];
    if (kthird == 0) {
#pragma unroll
        for (int h = 0; h < 2; h++) {
            int b = h ? b_hi : b_lo;
            bool ok = h ? okB : okA;
            int len = h ? lenB : lenA;
            if (!ok) continue;
            if (MODE == 0) {
                int trow = (dir == 0) ? 0 : max(len - 1, 0);
                const float* grp = gi + ((size_t)trow * B + b) * 1800 + dir * 900;
#pragma unroll
                for (int g = 0; g < 3; g++) {
                    gr[h][0][g] = grp[g * 300 + j0];
                    gr[h][1][g] = grp[g * 300 + j1];
                }
            } else {
                int trow = (dir == 0) ? 0 : (T - 1);
                int src = b + 1 - KF + trow;
                if (src >= 0) {
                    const float* grp = gi + (size_t)src * 1800 + dir * 900;
#pragma unroll
                    for (int g = 0; g < 3; g++) {
                        gr[h][0][g] = grp[g * 300 + j0];
                        gr[h][1][g] = grp[g * 300 + j1];
                    }
                } else {
#pragma unroll
                    for (int g = 0; g < 3; g++) {
                        gr[h][0][g] = bi[g][0];
                        gr[h][1][g] = bi[g][1];
                    }
                }
            }
        }
    }

    int cur = 0;
    for (int t = 0; t < T; t++) {
        const float* hp = cur ? h1 : h0;
        float*       hn = cur ? h0 : h1;

        if (t > 0) {
            for (int idx = tid; idx < 4800; idx += 480) {
                int bl = idx / 75, q = idx % 75;
                int b = b0 + bl;
                float4 v = make_float4(0.f, 0.f, 0.f, 0.f);
                if (b < B) v = __ldcg(((const float4*)(hp + dirbase + (size_t)b * 300)) + q);
                ((float4*)Hs)[idx] = v;
            }
        }
        __syncthreads();

        u64 acc[3][2][2] = {};
        float holdA[2] = {0.f, 0.f}, holdB[2] = {0.f, 0.f};
        if (t > 0) {
            const ulonglong2* w0p = (const ulonglong2*)(Ws + (0  + uu) * 300 + kthird * 100);
            const ulonglong2* w1p = (const ulonglong2*)(Ws + (0  + uu + 5) * 300 + kthird * 100);
            const ulonglong2* z0p = (const ulonglong2*)(Ws + (10 + uu) * 300 + kthird * 100);
            const ulonglong2* z1p = (const ulonglong2*)(Ws + (10 + uu + 5) * 300 + kthird * 100);
            const ulonglong2* n0p = (const ulonglong2*)(Ws + (20 + uu) * 300 + kthird * 100);
            const ulonglong2* n1p = (const ulonglong2*)(Ws + (20 + uu + 5) * 300 + kthird * 100);
            const ulonglong2* hA = (const ulonglong2*)(Hs + brow * 300 + kthird * 100);
#pragma unroll 5
            for (int q = 0; q < 25; q++) {
                ulonglong2 ha = hA[q], hb = hA[q + 2400];
                ulonglong2 w;
                w = w0p[q];
                acc[0][0][0] = f2fma(ha.x, w.x, acc[0][0][0]); acc[0][0][0] = f2fma(ha.y, w.y, acc[0][0][0]);
                acc[0][0][1] = f2fma(hb.x, w.x, acc[0][0][1]); acc[0][0][1] = f2fma(hb.y, w.y, acc[0][0][1]);
                w = w1p[q];
                acc[0][1][0] = f2fma(ha.x, w.x, acc[0][1][0]); acc[0][1][0] = f2fma(ha.y, w.y, acc[0][1][0]);
                acc[0][1][1] = f2fma(hb.x, w.x, acc[0][1][1]); acc[0][1][1] = f2fma(hb.y, w.y, acc[0][1][1]);
                w = z0p[q];
                acc[1][0][0] = f2fma(ha.x, w.x, acc[1][0][0]); acc[1][0][0] = f2fma(ha.y, w.y, acc[1][0][0]);
                acc[1][0][1] = f2fma(hb.x, w.x, acc[1][0][1]); acc[1][0][1] = f2fma(hb.y, w.y, acc[1][0][1]);
                w = z1p[q];
                acc[1][1][0] = f2fma(ha.x, w.x, acc[1][1][0]); acc[1][1][0] = f2fma(ha.y, w.y, acc[1][1][0]);
                acc[1][1][1] = f2fma(hb.x, w.x, acc[1][1][1]); acc[1][1][1] = f2fma(hb.y, w.y, acc[1][1][1]);
                w = n0p[q];
                acc[2][0][0] = f2fma(ha.x, w.x, acc[2][0][0]); acc[2][0][0] = f2fma(ha.y, w.y, acc[2][0][0]);
                acc[2][0][1] = f2fma(hb.x, w.x, acc[2][0][1]); acc[2][0][1] = f2fma(hb.y, w.y, acc[2][0][1]);
                w = n1p[q];
                acc[2][1][0] = f2fma(ha.x, w.x, acc[2][1][0]); acc[2][1][0] = f2fma(ha.y, w.y, acc[2][1][0]);
                acc[2][1][1] = f2fma(hb.x, w.x, acc[2][1][1]); acc[2][1][1] = f2fma(hb.y, w.y, acc[2][1][1]);
            }
            if (kthird == 0) {
                holdA[0] = okA ? Hs[brow * 300 + j0] : 0.f;
                holdA[1] = okA ? Hs[brow * 300 + j1] : 0.f;
                holdB[0] = okB ? Hs[(brow + 32) * 300 + j0] : 0.f;
                holdB[1] = okB ? Hs[(brow + 32) * 300 + j1] : 0.f;
            }
            __syncthreads();
            if (kthird > 0) {
                u64* rp = red + ((size_t)(kthird - 1) * 160 + lig) * 12;
#pragma unroll
                for (int g = 0; g < 3; g++)
#pragma unroll
                    for (int uq = 0; uq < 2; uq++) {
                        rp[(g * 2 + uq) * 2 + 0] = acc[g][uq][0];
                        rp[(g * 2 + uq) * 2 + 1] = acc[g][uq][1];
                    }
            }
            __syncthreads();
            if (kthird == 0) {
#pragma unroll
                for (int kt = 0; kt < 2; kt++) {
                    const u64* rp = red + ((size_t)kt * 160 + lig) * 12;
#pragma unroll
                    for (int g = 0; g < 3; g++)
#pragma unroll
                        for (int uq = 0; uq < 2; uq++) {
                            acc[g][uq][0] = f2add(acc[g][uq][0], rp[(g * 2 + uq) * 2 + 0]);
                            acc[g][uq][1] = f2add(acc[g][uq][1], rp[(g * 2 + uq) * 2 + 1]);
                        }
                }
            }
        }

        if (kthird == 0) {
#pragma unroll
            for (int h = 0; h < 2; h++) {
                int b = h ? b_hi : b_lo;
                bool ok = h ? okB : okA;
                if (!ok) continue;
                int len = h ? lenB : lenA;
                bool msk = (MODE != 0) || (t < len);
#pragma unroll
                for (int uq = 0; uq < 2; uq++) {
                    int jj = uq ? j1 : j0;
                    float hold = h ? holdB[uq] : holdA[uq];
                    float r = sigf(gr[h][uq][0] + hsum2(acc[0][uq][h]) + bh[0][uq]);
                    float z = sigf(gr[h][uq][1] + hsum2(acc[1][uq][h]) + bh[1][uq]);
                    float n = tanhf(gr[h][uq][2] + r * (hsum2(acc[2][uq][h]) + bh[2][uq]));
                    float hnew = (1.f - z) * n + z * hold;
                    if (MODE == 0) {
                        hn[dirbase + (size_t)b * 300 + jj] = msk ? hnew : hold;
                        float mp = msk ? hnew : 0.f;
                        if (h) mpB[uq] = fmaxf(mpB[uq], mp);
                        else   mpA[uq] = fmaxf(mpA[uq], mp);
                    } else {
                        hn[dirbase + (size_t)b * 300 + jj] = hnew;
                        seqout[(((size_t)dir * T + t) * B + b) * 300 + jj] = hnew;
                    }
                }
            }
            if (t + 1 < T) {
                int tn = t + 1;
#pragma unroll
                for (int h = 0; h < 2; h++) {
                    int b = h ? b_hi : b_lo;
                    bool ok = h ? okB : okA;
                    int len = h ? lenB : lenA;
                    if (!ok) continue;
                    if (MODE == 0) {
                        int trow = (dir == 0) ? tn : max(len - 1 - tn, 0);
                        const float* grp = gi + ((size_t)trow * B + b) * 1800 + dir * 900;
#pragma unroll
                        for (int g = 0; g < 3; g++) {
                            gr[h][0][g] = grp[g * 300 + j0];
                            gr[h][1][g] = grp[g * 300 + j1];
                        }
                    } else {
                        int trow = (dir == 0) ? tn : (T - 1 - tn);
                        int src = b + 1 - KF + trow;
                        if (src >= 0) {
                            const float* grp = gi + (size_t)src * 1800 + dir * 900;
#pragma unroll
                            for (int g = 0; g < 3; g++) {
                                gr[h][0][g] = grp[g * 300 + j0];
                                gr[h][1][g] = grp[g * 300 + j1];
                            }
                        } else {
#pragma unroll
                            for (int g = 0; g < 3; g++) {
                                gr[h][0][g] = bi[g][0];
                                gr[h][1][g] = bi[g][1];
                            }
                        }
                    }
                }
            }
        }
        cur ^= 1;
        if (t < T - 1) group_barrier(gslot, gen0 + (unsigned)t + 1u);
    }

    if (MODE == 0 && kthird == 0) {
#pragma unroll
        for (int uq = 0; uq < 2; uq++) {
            int jj = uq ? j1 : j0;
            if (okA) maxpool[b_lo * (2 * HDIM) + dir * HDIM + jj] = mpA[uq];
            if (okB) maxpool[b_hi * (2 * HDIM) + dir * HDIM + jj] = mpB[uq];
        }
    }
}

// ---------------- persistent attention-GRU scan v6 (one hop) ----------------
__global__ __launch_bounds__(480, 1)
void att_scan6(float* __restrict__ h0, float* __restrict__ h1,
               const float* __restrict__ xr,
               const float* __restrict__ xw,
               const float* __restrict__ Ur,
               const float* __restrict__ Uw,
               const float* __restrict__ bur,
               const float* __restrict__ bu,
               const float* __restrict__ gates,
               int hop)
{
    extern __shared__ float sm[];
    float* Ws = sm;                      // 6000 floats (persists)
    float* Hs = sm + 6000;               // 19200 floats
    u64*   red = (u64*)(sm + 25200);     // 2560 u64

    const int tid    = threadIdx.x;
    const int brow   = tid & 31;
    const int uu     = (tid >> 5) % 5;
    const int kthird = tid / 160;
    const int lig    = tid - kthird * 160;
    const int jgrp = blockIdx.x, bgrp = blockIdx.y, dir = blockIdx.z;
    const int j0 = jgrp * 10 + uu;
    const int j1 = j0 + 5;
    const int wd = hop * 2 + dir;
    const int dirbase = dir * NQ * HDIM;
    const int b0 = bgrp * 64;
    const int b_lo = b0 + brow, b_hi = b_lo + 32;
    const int gslot = (dir * 2 + bgrp) * 32;

    const unsigned gen0 = *(volatile unsigned*)&g_gen[gslot];

    for (int idx = tid; idx < 1500; idx += 480) {
        int row = idx / 75, q = idx % 75;
        int g = row / 10, ju = row % 10;
        const float* Wsrc = g ? Uw : Ur;
        ((float4*)Ws)[row * 75 + q] = ((const float4*)(Wsrc +
            ((size_t)wd * 300 + jgrp * 10 + ju) * 300))[q];
    }
    float bv[2][2];
    bv[0][0] = bur[wd * 300 + j0]; bv[0][1] = bur[wd * 300 + j1];
    bv[1][0] = bu[wd * 300 + j0];  bv[1][1] = bu[wd * 300 + j1];
    const bool okA = (b_lo < NQ), okB = (b_hi < NQ);

    float xrv[2][2], xwv[2][2], gv[2];
    if (kthird == 0) {
        int tt0 = (dir == 0) ? 0 : (KF - 1);
#pragma unroll
        for (int h = 0; h < 2; h++) {
            int b = h ? b_hi : b_lo;
            bool ok = h ? okB : okA;
            if (ok) {
                size_t base = ((size_t)tt0 * NQ + b) * 1800 + wd * 300;
                xrv[h][0] = xr[base + j0]; xrv[h][1] = xr[base + j1];
                xwv[h][0] = xw[base + j0]; xwv[h][1] = xw[base + j1];
                gv[h] = gates[tt0 * NQ + b];
            }
        }
    }

    int cur = 0;
    for (int t = 0; t < KF; t++) {
        const float* hp = cur ? h1 : h0;
        float*       hn = cur ? h0 : h1;

        if (t > 0) {
            for (int idx = tid; idx < 4800; idx += 480) {
                int bl = idx / 75, q = idx % 75;
                int b = b0 + bl;
                float4 v = make_float4(0.f, 0.f, 0.f, 0.f);
                if (b < NQ) v = __ldcg(((const float4*)(hp + dirbase + (size_t)b * 300)) + q);
                ((float4*)Hs)[idx] = v;
            }
        }
        __syncthreads();

        u64 acc[2][2][2] = {};
        float holdA[2] = {0.f, 0.f}, holdB[2] = {0.f, 0.f};
        if (t > 0) {
            const ulonglong2* r0p = (const ulonglong2*)(Ws + (0  + uu) * 300 + kthird * 100);
            const ulonglong2* r1p = (const ulonglong2*)(Ws + (0  + uu + 5) * 300 + kthird * 100);
            const ulonglong2* w0p = (const ulonglong2*)(Ws + (10 + uu) * 300 + kthird * 100);
            const ulonglong2* w1p = (const ulonglong2*)(Ws + (10 + uu + 5) * 300 + kthird * 100);
            const ulonglong2* hA = (const ulonglong2*)(Hs + brow * 300 + kthird * 100);
#pragma unroll 5
            for (int q = 0; q < 25; q++) {
                ulonglong2 ha = hA[q], hb = hA[q + 2400];
                ulonglong2 w;
                w = r0p[q];
                acc[0][0][0] = f2fma(ha.x, w.x, acc[0][0][0]); acc[0][0][0] = f2fma(ha.y, w.y, acc[0][0][0]);
                acc[0][0][1] = f2fma(hb.x, w.x, acc[0][0][1]); acc[0][0][1] = f2fma(hb.y, w.y, acc[0][0][1]);
                w = r1p[q];
                acc[0][1][0] = f2fma(ha.x, w.x, acc[0][1][0]); acc[0][1][0] = f2fma(ha.y, w.y, acc[0][1][0]);
                acc[0][1][1] = f2fma(hb.x, w.x, acc[0][1][1]); acc[0][1][1] = f2fma(hb.y, w.y, acc[0][1][1]);
                w = w0p[q];
                acc[1][0][0] = f2fma(ha.x, w.x, acc[1][0][0]); acc[1][0][0] = f2fma(ha.y, w.y, acc[1][0][0]);
                acc[1][0][1] = f2fma(hb.x, w.x, acc[1][0][1]); acc[1][0][1] = f2fma(hb.y, w.y, acc[1][0][1]);
                w = w1p[q];
                acc[1][1][0] = f2fma(ha.x, w.x, acc[1][1][0]); acc[1][1][0] = f2fma(ha.y, w.y, acc[1][1][0]);
                acc[1][1][1] = f2fma(hb.x, w.x, acc[1][1][1]); acc[1][1][1] = f2fma(hb.y, w.y, acc[1][1][1]);
            }
            if (kthird == 0) {
                holdA[0] = okA ? Hs[brow * 300 + j0] : 0.f;
                holdA[1] = okA ? Hs[brow * 300 + j1] : 0.f;
                holdB[0] = okB ? Hs[(brow + 32) * 300 + j0] : 0.f;
                holdB[1] = okB ? Hs[(brow + 32) * 300 + j1] : 0.f;
            }
            __syncthreads();
            if (kthird > 0) {
                u64* rp = red + ((size_t)(kthird - 1) * 160 + lig) * 8;
#pragma unroll
                for (int g = 0; g < 2; g++)
#pragma unroll
                    for (int uq = 0; uq < 2; uq++) {
                        rp[(g * 2 + uq) * 2 + 0] = acc[g][uq][0];
                        rp[(g * 2 + uq) * 2 + 1] = acc[g][uq][1];
                    }
            }
            __syncthreads();
            if (kthird == 0) {
#pragma unroll
                for (int kt = 0; kt < 2; kt++) {
                    const u64* rp = red + ((size_t)kt * 160 + lig) * 8;
#pragma unroll
                    for (int g = 0; g < 2; g++)
#pragma unroll
                        for (int uq = 0; uq < 2; uq++) {
                            acc[g][uq][0] = f2add(acc[g][uq][0], rp[(g * 2 + uq) * 2 + 0]);
                            acc[g][uq][1] = f2add(acc[g][uq][1], rp[(g * 2 + uq) * 2 + 1]);
                        }
                }
            }
        }

        if (kthird == 0) {
#pragma unroll
            for (int h = 0; h < 2; h++) {
                int b = h ? b_hi : b_lo;
                bool ok = h ? okB : okA;
                if (!ok) continue;
#pragma unroll
                for (int uq = 0; uq < 2; uq++) {
                    int jj = uq ? j1 : j0;
                    float hold = h ? holdB[uq] : holdA[uq];
                    float r  = sigf(xrv[h][uq] + hsum2(acc[0][uq][h]) + bv[0][uq]);
                    float ht = tanhf(xwv[h][uq] + r * (hsum2(acc[1][uq][h]) + bv[1][uq]));
                    hn[dirbase + (size_t)b * 300 + jj] = gv[h] * ht + (1.f - gv[h]) * hold;
                }
            }
            if (t + 1 < KF) {
                int tn = (dir == 0) ? (t + 1) : (KF - 2 - t);
#pragma unroll
                for (int h = 0; h < 2; h++) {
                    int b = h ? b_hi : b_lo;
                    bool ok = h ? okB : okA;
                    if (ok) {
                        size_t base = ((size_t)tn * NQ + b) * 1800 + wd * 300;
                        xrv[h][0] = xr[base + j0]; xrv[h][1] = xr[base + j1];
                        xwv[h][0] = xw[base + j0]; xwv[h][1] = xw[base + j1];
                        gv[h] = gates[tn * NQ + b];
                    }
                }
            }
        }
        cur ^= 1;
        if (t < KF - 1) group_barrier(gslot, gen0 + (unsigned)t + 1u);
    }
}

// ---------------- small kernels ----------------
__global__ __launch_bounds__(256)
void lin_kernel(const float* __restrict__ mp, const float* __restrict__ w,
                const float* __restrict__ bsc, float* __restrict__ u) {
    int b = blockIdx.x;
    __shared__ float m[600];
    for (int i = threadIdx.x; i < 600; i += 256) m[i] = mp[b * 600 + i];
    __syncthreads();
    int wid = threadIdx.x >> 5, lane = threadIdx.x & 31;
    for (int j = wid; j < HDIM; j += 8) {
        float acc = 0.f;
        const float* wr = w + (size_t)j * 600;
        for (int k = lane; k < 600; k += 32) acc += m[k] * wr[k];
        for (int o = 16; o > 0; o >>= 1) acc += __shfl_xor_sync(0xffffffffu, acc, o);
        if (lane == 0) u[b * HDIM + j] = tanhf(acc + bsc[j]);
    }
}

__global__ void build_inp0(const float* __restrict__ u, float* __restrict__ inp0) {
    int idx = blockIdx.x * blockDim.x + threadIdx.x;
    if (idx >= KF * NQ * HDIM) return;
    int j = idx % HDIM;
    int r = idx / HDIM;
    int i = r % NQ;
    int k = r / NQ;
    int src = (i + 1) - KF + k;
    inp0[idx] = (src >= 0) ? u[src * HDIM + j] : 0.f;
}

__global__ void membank_kernel(const float* __restrict__ inp0,
                               const float* __restrict__ seq,
                               float* __restrict__ mem) {
    int idx = blockIdx.x * blockDim.x + threadIdx.x;
    if (idx >= KF * NQ * HDIM) return;
    int j = idx % HDIM;
    int r = idx / HDIM;
    int i = r % NQ;
    int k = r / NQ;
    float f = seq[((size_t)k) * NQ * HDIM + i * HDIM + j];
    float b = seq[((size_t)KF + (KF - 1 - k)) * NQ * HDIM + i * HDIM + j];
    mem[idx] = inp0[idx] + f + b;
}

__global__ void score_kernel(const float* __restrict__ query,
                             const float* __restrict__ mem,
                             float* __restrict__ gates) {
    int b = blockIdx.x;
    int tid = threadIdx.x;
    int lane = tid & 31, w = tid >> 5;
    __shared__ float q[HDIM];
    __shared__ float logit[KF];
    for (int i = tid; i < HDIM; i += 128) q[i] = query[b * HDIM + i];
    __syncthreads();
    for (int k = w; k < KF; k += 4) {
        const float* mrow = mem + ((size_t)k * NQ + b) * HDIM;
        float s = 0.f;
        for (int i = lane; i < HDIM; i += 32) s += q[i] * mrow[i];
        for (int o = 16; o > 0; o >>= 1) s += __shfl_xor_sync(0xffffffffu, s, o);
        if (lane == 0) logit[k] = (k >= KF - 1 - b) ? s : -1e10f;
    }
    __syncthreads();
    if (w == 0) {
        float m = -INFINITY;
        for (int k = lane; k < KF; k += 32) m = fmaxf(m, logit[k]);
        for (int o = 16; o > 0; o >>= 1) m = fmaxf(m, __shfl_xor_sync(0xffffffffu, m, o));
        float ssum = 0.f;
        for (int k = lane; k < KF; k += 32) { float e = expf(logit[k] - m); logit[k] = e; ssum += e; }
        for (int o = 16; o > 0; o >>= 1) ssum += __shfl_xor_sync(0xffffffffu, ssum, o);
        for (int k = lane; k < KF; k += 32) gates[k * NQ + b] = logit[k] / ssum;
    }
}

__global__ void add2_kernel(float* __restrict__ q,
                            const float* __restrict__ hf,
                            const float* __restrict__ hb, int n) {
    int i = blockIdx.x * blockDim.x + threadIdx.x;
    if (i < n) q[i] += hf[i] + hb[i];
}

__global__ void cls_kernel(const float* __restrict__ u,
                           const float* __restrict__ query,
                           const float* __restrict__ cls_w,
                           const float* __restrict__ cls_b,
                           float* __restrict__ out) {
    int row = blockIdx.x;
    int w = threadIdx.x >> 5, lane = threadIdx.x & 31;
    const float* s = (row == 0) ? u : (query + (row - 1) * HDIM);
    float acc = 0.f;
    for (int i = lane; i < HDIM; i += 32) acc += s[i] * cls_w[w * HDIM + i];
    for (int o = 16; o > 0; o >>= 1) acc += __shfl_xor_sync(0xffffffffu, acc, o);
    if (lane == 0) out[row * NCLS + w] = acc + cls_b[w];
}

// ---------------- host orchestration ----------------
extern "C" void kernel_launch(void* const* d_in, const int* in_sizes, int n_in,
                              void* d_out, int out_size) {
    const int*   ids      = (const int*)d_in[0];
    const int*   seq_lens = (const int*)d_in[1];
    const float* emb      = (const float*)d_in[2];
    const float* utt_Wih  = (const float*)d_in[3];
    const float* utt_Whh  = (const float*)d_in[4];
    const float* utt_bih  = (const float*)d_in[5];
    const float* utt_bhh  = (const float*)d_in[6];
    const float* lin_w    = (const float*)d_in[7];
    const float* lin_b    = (const float*)d_in[8];
    const float* ctx_Wih  = (const float*)d_in[9];
    const float* ctx_Whh  = (const float*)d_in[10];
    const float* ctx_bih  = (const float*)d_in[11];
    const float* ctx_bhh  = (const float*)d_in[12];
    const float* aWr_w    = (const float*)d_in[13];
    const float* aWr_b    = (const float*)d_in[14];
    const float* aUr_w    = (const float*)d_in[15];
    const float* aUr_b    = (const float*)d_in[16];
    const float* aW_w     = (const float*)d_in[17];
    const float* aW_b     = (const float*)d_in[18];
    const float* aU_w     = (const float*)d_in[19];
    const float* aU_b     = (const float*)d_in[20];
    const float* cls_w    = (const float*)d_in[21];
    const float* cls_b    = (const float*)d_in[22];
    float* out = (float*)d_out;

    float *gi_utt, *h_utt, *maxpool, *u, *inp0, *proj, *seq_ctx, *h_ctx;
    float *mem, *xr, *xw, *gates, *query, *h_att;
    cudaGetSymbolAddress((void**)&gi_utt,  g_gi_utt);
    cudaGetSymbolAddress((void**)&h_utt,   g_h_utt);
    cudaGetSymbolAddress((void**)&maxpool, g_maxpool);
    cudaGetSymbolAddress((void**)&u,       g_u);
    cudaGetSymbolAddress((void**)&inp0,    g_inp0);
    cudaGetSymbolAddress((void**)&proj,    g_proj);
    cudaGetSymbolAddress((void**)&seq_ctx, g_seq_ctx);
    cudaGetSymbolAddress((void**)&h_ctx,   g_h_ctx);
    cudaGetSymbolAddress((void**)&mem,     g_mem);
    cudaGetSymbolAddress((void**)&xr,      g_xr);
    cudaGetSymbolAddress((void**)&xw,      g_xw);
    cudaGetSymbolAddress((void**)&gates,   g_gates);
    cudaGetSymbolAddress((void**)&query,   g_query);
    cudaGetSymbolAddress((void**)&h_att,   g_h_att);

    float* hU0 = h_utt;  float* hU1 = h_utt + 2 * NB * HDIM;
    float* hC0 = h_ctx;  float* hC1 = h_ctx + 2 * NQ * HDIM;
    float* hA0 = h_att;  float* hA1 = h_att + 2 * NQ * HDIM;

    const int GRU_SMEM = 28200 * 4 + 3840 * 8;   // 143520 B
    const int ATT_SMEM = 25200 * 4 + 2560 * 8;   // 121280 B
    cudaFuncSetAttribute(gru_scan7<0>, cudaFuncAttributeMaxDynamicSharedMemorySize, GRU_SMEM);
    cudaFuncSetAttribute(gru_scan7<1>, cudaFuncAttributeMaxDynamicSharedMemorySize, GRU_SMEM);
    cudaFuncSetAttribute(att_scan6,    cudaFuncAttributeMaxDynamicSharedMemorySize, ATT_SMEM);

    cudaStream_t s = 0;
    dim3 sg(30, 2, 2);

    // ---- utterance GRU input projection (gathered emb; 128x64 tiles) ----
    {
        dim3 g((1800 + GTN - 1) / GTN, (LSEQ * NB + G5M - 1) / G5M);
        gemm5<1><<<g, 256, 0, s>>>(nullptr, 0, utt_Wih, utt_bih,
                                   gi_utt, 1800, LSEQ * NB, 1800, EDIM, emb, ids);
    }
    // ---- utterance GRU scan (ONE persistent launch) ----
    gru_scan7<0><<<sg, 480, GRU_SMEM, s>>>(hU0, hU1, gi_utt, utt_Whh, utt_bhh,
                                           nullptr, seq_lens, maxpool, nullptr,
                                           NB, LSEQ);

    // ---- u = tanh(maxpool @ lin_w^T + lin_b) ----
    lin_kernel<<<NB, 256, 0, s>>>(maxpool, lin_w, lin_b, u);

    // ---- ctx projection DEDUPED: proj127 = u[0:127] @ ctx_Wih^T + ctx_bih ----
    {
        dim3 g((1800 + GTN - 1) / GTN, (NQ + GTM - 1) / GTM);
        gemm4<0><<<g, 256, 0, s>>>(u, HDIM, ctx_Wih, ctx_bih,
                                   proj, 1800, NQ, 1800, HDIM, nullptr, nullptr);
    }
    build_inp0<<<(KF * NQ * HDIM + 255) / 256, 256, 0, s>>>(u, inp0);

    // ---- ctx GRU scan (gi gathered from proj127 inside the kernel) ----
    gru_scan7<1><<<sg, 480, GRU_SMEM, s>>>(hC0, hC1, proj, ctx_Whh, ctx_bhh,
                                           ctx_bih, nullptr, nullptr, seq_ctx,
                                           NQ, KF);

    membank_kernel<<<(KF * NQ * HDIM + 255) / 256, 256, 0, s>>>(inp0, seq_ctx, mem);

    // ---- attention x-projections (hop-invariant; 128x64 tiles) ----
    {
        dim3 g((1800 + GTN - 1) / GTN, (KF * NQ + G5M - 1) / G5M);
        gemm5<0><<<g, 256, 0, s>>>(mem, HDIM, aWr_w, aWr_b,
                                   xr, 1800, KF * NQ, 1800, HDIM, nullptr, nullptr);
        gemm5<0><<<g, 256, 0, s>>>(mem, HDIM, aW_w, aW_b,
                                   xw, 1800, KF * NQ, 1800, HDIM, nullptr, nullptr);
    }

    // ---- query init + hops ----
    cudaMemcpyAsync(query, u + HDIM, NQ * HDIM * sizeof(float),
                    cudaMemcpyDeviceToDevice, s);
    for (int hop = 0; hop < NHOPS; hop++) {
        score_kernel<<<NQ, 128, 0, s>>>(query, mem, gates);
        att_scan6<<<sg, 480, ATT_SMEM, s>>>(hA0, hA1, xr, xw,
                                            aUr_w, aU_w, aUr_b, aU_b, gates, hop);
        add2_kernel<<<(NQ * HDIM + 255) / 256, 256, 0, s>>>(
            query, hA0, hA0 + NQ * HDIM, NQ * HDIM);
    }

    // ---- classifier ----
    cls_kernel<<<NB, 192, 0, s>>>(u, query, cls_w, cls_b, out);
}

// round 17
// speedup vs baseline: 1.3188x; 1.0074x over previous
#include <cuda_runtime.h>
#include <math.h>

#define NB   128   // N dialogues
#define LSEQ 64    // L
#define EDIM 300
#define HDIM 300
#define KF   40    // KEFF
#define NQ   127   // N-1
#define NHOPS 3
#define NCLS 6

typedef unsigned long long u64;

// ---------------- scratch (device globals; no allocation) ----------------
__device__ float g_gi_utt[(size_t)LSEQ * NB * 1800];     // [t*128+b, 1800]
__device__ float g_h_utt[2][2 * NB * HDIM];
__device__ float g_maxpool[NB * 2 * HDIM];
__device__ float g_u[NB * HDIM];
__device__ float g_inp0[KF * NQ * HDIM];                 // ctx_t time-major
__device__ float g_proj[NQ * 1800];                      // u[0:127] @ ctx_Wih^T + bih
__device__ float g_seq_ctx[2 * KF * NQ * HDIM];          // [dir, t, i, j]
__device__ float g_h_ctx[2][2 * NQ * HDIM];
__device__ float g_mem[KF * NQ * HDIM];                  // time-major [k,i,j]
__device__ float g_xr[(size_t)KF * NQ * 1800];
__device__ float g_xw[(size_t)KF * NQ * 1800];
__device__ float g_gates[KF * NQ];
__device__ float g_query[NQ * HDIM];
__device__ float g_h_att[2][2 * NQ * HDIM];

// barrier state: group slots 0/32/64/96, full-grid slot 160 (own 128B line)
__device__ unsigned g_cnt[192];
__device__ unsigned g_gen[192];
#define FULLSLOT 160

__device__ __forceinline__ float sigf(float x) { return 1.f / (1.f + expf(-x)); }

// ---------------- packed f32x2 helpers ----------------
__device__ __forceinline__ u64 pk2(float x, float y) {
    u64 r; asm("mov.b64 %0, {%1, %2};" : "=l"(r) : "f"(x), "f"(y)); return r;
}
__device__ __forceinline__ float2 unpk(u64 v) {
    float2 f; asm("mov.b64 {%0, %1}, %2;" : "=f"(f.x), "=f"(f.y) : "l"(v)); return f;
}
__device__ __forceinline__ u64 f2fma(u64 a, u64 b, u64 c) {
    u64 d; asm("fma.rn.f32x2 %0, %1, %2, %3;" : "=l"(d) : "l"(a), "l"(b), "l"(c));
    return d;
}
__device__ __forceinline__ u64 f2add(u64 a, u64 b) {
    u64 d; asm("add.rn.f32x2 %0, %1, %2;" : "=l"(d) : "l"(a), "l"(b));
    return d;
}
__device__ __forceinline__ float hsum2(u64 v) {
    float2 f = unpk(v); return f.x + f.y;
}

// N-block barrier; leader resets cnt BEFORE bumping gen.
__device__ __forceinline__ void blk_barrier(int gslot, unsigned nb, unsigned target) {
    __threadfence();
    __syncthreads();
    if (threadIdx.x == 0) {
        unsigned old = atomicAdd(&g_cnt[gslot], 1u);
        if (old == nb - 1u) {
            atomicExch(&g_cnt[gslot], 0u);
            __threadfence();
            atomicAdd(&g_gen[gslot], 1u);
        } else {
            while (*(volatile unsigned*)&g_gen[gslot] < target) __nanosleep(32);
        }
        __threadfence();
    }
    __syncthreads();
}

// ---------------- GEMM v4 (64x64, f32x2, reg double-buffered) ---------------
#define GTM 64
#define GTN 64
#define GTK 16

template<int GATHER>
__global__ __launch_bounds__(256)
void gemm4(const float* __restrict__ A, int lda,
           const float* __restrict__ W,
           const float* __restrict__ bias,
           float* __restrict__ C, int ldc,
           int M, int N, int K,
           const float* __restrict__ emb,
           const int* __restrict__ ids)
{
    __shared__ __align__(16) u64   Ad[GTK][66];
    __shared__ __align__(16) float Bs[GTK][66];
    __shared__ int rowid[GTM];
    const int tid = threadIdx.x;
    const int m0 = blockIdx.y * GTM;
    const int n0 = blockIdx.x * GTN;

    if (GATHER) {
        if (tid < GTM) {
            int m = m0 + tid;
            int t = m >> 7, b = m & 127;
            rowid[tid] = (m < M) ? ids[b * LSEQ + t] : 0;
        }
        __syncthreads();
    }

    int amm[4], akk[4];
#pragma unroll
    for (int i = 0; i < 4; i++) {
        int idx = tid + i * 256;
        amm[i] = idx >> 4; akk[i] = idx & 15;
    }

    float aReg[4], bReg[4];
#pragma unroll
    for (int i = 0; i < 4; i++) {
        int m = m0 + amm[i], k = akk[i];
        float v = 0.f;
        if (m < M && k < K)
            v = GATHER ? emb[(size_t)rowid[amm[i]] * K + k] : A[(size_t)m * lda + k];
        aReg[i] = v;
        int n = n0 + amm[i];
        bReg[i] = (n < N && k < K) ? W[(size_t)n * K + k] : 0.f;
    }

    u64 acc[4][2] = {};
    const int mt = tid >> 4;
    const int nt = tid & 15;

    for (int k0 = 0; k0 < K; k0 += GTK) {
#pragma unroll
        for (int i = 0; i < 4; i++) {
            Ad[akk[i]][amm[i]] = pk2(aReg[i], aReg[i]);
            Bs[akk[i]][amm[i]] = bReg[i];
        }
        __syncthreads();

        int kn = k0 + GTK;
        if (kn < K) {
#pragma unroll
            for (int i = 0; i < 4; i++) {
                int m = m0 + amm[i], k = kn + akk[i];
                float v = 0.f;
                if (m < M && k < K)
                    v = GATHER ? emb[(size_t)rowid[amm[i]] * K + k]
                               : A[(size_t)m * lda + k];
                aReg[i] = v;
                int n = n0 + amm[i];
                bReg[i] = (n < N && k < K) ? W[(size_t)n * K + k] : 0.f;
            }
        }

#pragma unroll
        for (int kk = 0; kk < GTK; kk++) {
            ulonglong2 a01 = *(const ulonglong2*)&Ad[kk][mt * 4];
            ulonglong2 a23 = *(const ulonglong2*)&Ad[kk][mt * 4 + 2];
            u64 b0 = *(const u64*)&Bs[kk][nt * 4];
            u64 b1 = *(const u64*)&Bs[kk][nt * 4 + 2];
            acc[0][0] = f2fma(a01.x, b0, acc[0][0]);
            acc[0][1] = f2fma(a01.x, b1, acc[0][1]);
            acc[1][0] = f2fma(a01.y, b0, acc[1][0]);
            acc[1][1] = f2fma(a01.y, b1, acc[1][1]);
            acc[2][0] = f2fma(a23.x, b0, acc[2][0]);
            acc[2][1] = f2fma(a23.x, b1, acc[2][1]);
            acc[3][0] = f2fma(a23.y, b0, acc[3][0]);
            acc[3][1] = f2fma(a23.y, b1, acc[3][1]);
        }
        __syncthreads();
    }
#pragma unroll
    for (int i = 0; i < 4; i++) {
        int m = m0 + mt * 4 + i;
        if (m >= M) continue;
#pragma unroll
        for (int p = 0; p < 2; p++) {
            float2 v = unpk(acc[i][p]);
            int n = n0 + nt * 4 + 2 * p;
            if (n < N)     C[(size_t)m * ldc + n]     = v.x + bias[n];
            if (n + 1 < N) C[(size_t)m * ldc + n + 1] = v.y + bias[n + 1];
        }
    }
}

// ---------------- GEMM v4n (32x64) for small-M grid-starved cases -----------
__global__ __launch_bounds__(256)
void gemm4n(const float* __restrict__ A, int lda,
            const float* __restrict__ W,
            const float* __restrict__ bias,
            float* __restrict__ C, int ldc,
            int M, int N, int K)
{
    __shared__ __align__(16) u64   Ad[GTK][34];
    __shared__ __align__(16) float Bs[GTK][66];
    const int tid = threadIdx.x;
    const int m0 = blockIdx.y * 32;
    const int n0 = blockIdx.x * GTN;

    int amm[2], akk[2], bnn[4], bkk[4];
#pragma unroll
    for (int i = 0; i < 2; i++) {
        int idx = tid + i * 256;
        amm[i] = idx >> 4; akk[i] = idx & 15;
    }
#pragma unroll
    for (int i = 0; i < 4; i++) {
        int idx = tid + i * 256;
        bnn[i] = idx >> 4; bkk[i] = idx & 15;
    }

    float aReg[2], bReg[4];
#pragma unroll
    for (int i = 0; i < 2; i++) {
        int m = m0 + amm[i], k = akk[i];
        aReg[i] = (m < M && k < K) ? A[(size_t)m * lda + k] : 0.f;
    }
#pragma unroll
    for (int i = 0; i < 4; i++) {
        int n = n0 + bnn[i], k = bkk[i];
        bReg[i] = (n < N && k < K) ? W[(size_t)n * K + k] : 0.f;
    }

    u64 acc[2][2] = {};
    const int mt = tid >> 4;
    const int nt = tid & 15;

    for (int k0 = 0; k0 < K; k0 += GTK) {
#pragma unroll
        for (int i = 0; i < 2; i++)
            Ad[akk[i]][amm[i]] = pk2(aReg[i], aReg[i]);
#pragma unroll
        for (int i = 0; i < 4; i++)
            Bs[bkk[i]][bnn[i]] = bReg[i];
        __syncthreads();

        int kn = k0 + GTK;
        if (kn < K) {
#pragma unroll
            for (int i = 0; i < 2; i++) {
                int m = m0 + amm[i], k = kn + akk[i];
                aReg[i] = (m < M && k < K) ? A[(size_t)m * lda + k] : 0.f;
            }
#pragma unroll
            for (int i = 0; i < 4; i++) {
                int n = n0 + bnn[i], k = kn + bkk[i];
                bReg[i] = (n < N && k < K) ? W[(size_t)n * K + k] : 0.f;
            }
        }

#pragma unroll
        for (int kk = 0; kk < GTK; kk++) {
            ulonglong2 a01 = *(const ulonglong2*)&Ad[kk][mt * 2];
            u64 b0 = *(const u64*)&Bs[kk][nt * 4];
            u64 b1 = *(const u64*)&Bs[kk][nt * 4 + 2];
            acc[0][0] = f2fma(a01.x, b0, acc[0][0]);
            acc[0][1] = f2fma(a01.x, b1, acc[0][1]);
            acc[1][0] = f2fma(a01.y, b0, acc[1][0]);
            acc[1][1] = f2fma(a01.y, b1, acc[1][1]);
        }
        __syncthreads();
    }
#pragma unroll
    for (int i = 0; i < 2; i++) {
        int m = m0 + mt * 2 + i;
        if (m >= M) continue;
#pragma unroll
        for (int p = 0; p < 2; p++) {
            float2 v = unpk(acc[i][p]);
            int n = n0 + nt * 4 + 2 * p;
            if (n < N)     C[(size_t)m * ldc + n]     = v.x + bias[n];
            if (n + 1 < N) C[(size_t)m * ldc + n + 1] = v.y + bias[n + 1];
        }
    }
}

// ---------------- GEMM v5 (128x64, f32x2, reg double-buffered) --------------
#define G5M 128

template<int GATHER>
__global__ __launch_bounds__(256)
void gemm5(const float* __restrict__ A, int lda,
           const float* __restrict__ W,
           const float* __restrict__ bias,
           float* __restrict__ C, int ldc,
           int M, int N, int K,
           const float* __restrict__ emb,
           const int* __restrict__ ids)
{
    __shared__ __align__(16) u64   Ad[GTK][130];
    __shared__ __align__(16) float Bs[GTK][66];
    __shared__ int rowid[G5M];
    const int tid = threadIdx.x;
    const int m0 = blockIdx.y * G5M;
    const int n0 = blockIdx.x * GTN;

    if (GATHER) {
        if (tid < G5M) {
            int m = m0 + tid;
            int t = m >> 7, b = m & 127;
            rowid[tid] = (m < M) ? ids[b * LSEQ + t] : 0;
        }
        __syncthreads();
    }

    int amm[8], akk[8];
#pragma unroll
    for (int i = 0; i < 8; i++) {
        int idx = tid + i * 256;
        amm[i] = idx >> 4; akk[i] = idx & 15;
    }

    float aReg[8], bReg[4];
#pragma unroll
    for (int i = 0; i < 8; i++) {
        int m = m0 + amm[i], k = akk[i];
        float v = 0.f;
        if (m < M && k < K)
            v = GATHER ? emb[(size_t)rowid[amm[i]] * K + k] : A[(size_t)m * lda + k];
        aReg[i] = v;
    }
#pragma unroll
    for (int i = 0; i < 4; i++) {
        int n = n0 + amm[i], k = akk[i];
        bReg[i] = (n < N && k < K) ? W[(size_t)n * K + k] : 0.f;
    }

    u64 acc[8][2] = {};
    const int mt = tid >> 4;
    const int nt = tid & 15;

    for (int k0 = 0; k0 < K; k0 += GTK) {
#pragma unroll
        for (int i = 0; i < 8; i++)
            Ad[akk[i]][amm[i]] = pk2(aReg[i], aReg[i]);
#pragma unroll
        for (int i = 0; i < 4; i++)
            Bs[akk[i]][amm[i]] = bReg[i];
        __syncthreads();

        int kn = k0 + GTK;
        if (kn < K) {
#pragma unroll
            for (int i = 0; i < 8; i++) {
                int m = m0 + amm[i], k = kn + akk[i];
                float v = 0.f;
                if (m < M && k < K)
                    v = GATHER ? emb[(size_t)rowid[amm[i]] * K + k]
                               : A[(size_t)m * lda + k];
                aReg[i] = v;
            }
#pragma unroll
            for (int i = 0; i < 4; i++) {
                int n = n0 + amm[i], k = kn + akk[i];
                bReg[i] = (n < N && k < K) ? W[(size_t)n * K + k] : 0.f;
            }
        }

#pragma unroll
        for (int kk = 0; kk < GTK; kk++) {
            ulonglong2 a01 = *(const ulonglong2*)&Ad[kk][mt * 8];
            ulonglong2 a23 = *(const ulonglong2*)&Ad[kk][mt * 8 + 2];
            ulonglong2 a45 = *(const ulonglong2*)&Ad[kk][mt * 8 + 4];
            ulonglong2 a67 = *(const ulonglong2*)&Ad[kk][mt * 8 + 6];
            u64 b0 = *(const u64*)&Bs[kk][nt * 4];
            u64 b1 = *(const u64*)&Bs[kk][nt * 4 + 2];
            acc[0][0] = f2fma(a01.x, b0, acc[0][0]);
            acc[0][1] = f2fma(a01.x, b1, acc[0][1]);
            acc[1][0] = f2fma(a01.y, b0, acc[1][0]);
            acc[1][1] = f2fma(a01.y, b1, acc[1][1]);
            acc[2][0] = f2fma(a23.x, b0, acc[2][0]);
            acc[2][1] = f2fma(a23.x, b1, acc[2][1]);
            acc[3][0] = f2fma(a23.y, b0, acc[3][0]);
            acc[3][1] = f2fma(a23.y, b1, acc[3][1]);
            acc[4][0] = f2fma(a45.x, b0, acc[4][0]);
            acc[4][1] = f2fma(a45.x, b1, acc[4][1]);
            acc[5][0] = f2fma(a45.y, b0, acc[5][0]);
            acc[5][1] = f2fma(a45.y, b1, acc[5][1]);
            acc[6][0] = f2fma(a67.x, b0, acc[6][0]);
            acc[6][1] = f2fma(a67.x, b1, acc[6][1]);
            acc[7][0] = f2fma(a67.y, b0, acc[7][0]);
            acc[7][1] = f2fma(a67.y, b1, acc[7][1]);
        }
        __syncthreads();
    }
#pragma unroll
    for (int i = 0; i < 8; i++) {
        int m = m0 + mt * 8 + i;
        if (m >= M) continue;
#pragma unroll
        for (int p = 0; p < 2; p++) {
            float2 v = unpk(acc[i][p]);
            int n = n0 + nt * 4 + 2 * p;
            if (n < N)     C[(size_t)m * ldc + n]     = v.x + bias[n];
            if (n + 1 < N) C[(size_t)m * ldc + n + 1] = v.y + bias[n + 1];
        }
    }
}

// ---------------- persistent GRU scan v7 (n_j=2, 480 thr, gi prefetch) -----
template<int MODE>
__global__ __launch_bounds__(480, 1)
void gru_scan7(float* __restrict__ h0, float* __restrict__ h1,
               const float* __restrict__ gi,
               const float* __restrict__ Whh,
               const float* __restrict__ bhh,
               const float* __restrict__ bih,
               const int*   __restrict__ seq_lens,
               float* __restrict__ maxpool,
               float* __restrict__ seqout,
               int B, int T)
{
    extern __shared__ float sm[];
    float* Ws = sm;                      // 9000 floats (persists)
    float* Hs = sm + 9000;               // 19200 floats
    u64*   red = (u64*)(sm + 28200);     // 3840 u64

    const int tid    = threadIdx.x;
    const int brow   = tid & 31;
    const int uu     = (tid >> 5) % 5;
    const int kthird = tid / 160;
    const int lig    = tid - kthird * 160;
    const int jgrp = blockIdx.x, bgrp = blockIdx.y, dir = blockIdx.z;
    const int j0 = jgrp * 10 + uu;
    const int j1 = j0 + 5;
    const int dirbase = dir * B * HDIM;
    const int b0 = bgrp * 64;
    const int b_lo = b0 + brow, b_hi = b_lo + 32;
    const int gslot = (dir * 2 + bgrp) * 32;

    const unsigned gen0 = *(volatile unsigned*)&g_gen[gslot];

    for (int idx = tid; idx < 2250; idx += 480) {
        int row = idx / 75, q = idx % 75;
        int g = row / 10, ju = row % 10;
        ((float4*)Ws)[row * 75 + q] = ((const float4*)(Whh +
            ((size_t)dir * 900 + g * 300 + jgrp * 10 + ju) * 300))[q];
    }
    float bh[3][2], bi[3][2];
#pragma unroll
    for (int g = 0; g < 3; g++) {
        bh[g][0] = bhh[dir * 900 + g * 300 + j0];
        bh[g][1] = bhh[dir * 900 + g * 300 + j1];
        if (MODE == 1) {
            bi[g][0] = bih[dir * 900 + g * 300 + j0];
            bi[g][1] = bih[dir * 900 + g * 300 + j1];
        }
    }
    const bool okA = (b_lo < B), okB = (b_hi < B);
    int lenA = T, lenB = T;
    if (MODE == 0) {
        lenA = okA ? seq_lens[b_lo] : 1;
        lenB = okB ? seq_lens[b_hi] : 1;
    }
    float mpA[2] = { -1e30f, -1e30f }, mpB[2] = { -1e30f, -1e30f };

    float gr[2][2][3];
    if (kthird == 0) {
#pragma unroll
        for (int h = 0; h < 2; h++) {
            int b = h ? b_hi : b_lo;
            bool ok = h ? okB : okA;
            int len = h ? lenB : lenA;
            if (!ok) continue;
            if (MODE == 0) {
                int trow = (dir == 0) ? 0 : max(len - 1, 0);
                const float* grp = gi + ((size_t)trow * B + b) * 1800 + dir * 900;
#pragma unroll
                for (int g = 0; g < 3; g++) {
                    gr[h][0][g] = grp[g * 300 + j0];
                    gr[h][1][g] = grp[g * 300 + j1];
                }
            } else {
                int trow = (dir == 0) ? 0 : (T - 1);
                int src = b + 1 - KF + trow;
                if (src >= 0) {
                    const float* grp = gi + (size_t)src * 1800 + dir * 900;
#pragma unroll
                    for (int g = 0; g < 3; g++) {
                        gr[h][0][g] = grp[g * 300 + j0];
                        gr[h][1][g] = grp[g * 300 + j1];
                    }
                } else {
#pragma unroll
                    for (int g = 0; g < 3; g++) {
                        gr[h][0][g] = bi[g][0];
                        gr[h][1][g] = bi[g][1];
                    }
                }
            }
        }
    }

    int cur = 0;
    for (int t = 0; t < T; t++) {
        const float* hp = cur ? h1 : h0;
        float*       hn = cur ? h0 : h1;

        if (t > 0) {
            for (int idx = tid; idx < 4800; idx += 480) {
                int bl = idx / 75, q = idx % 75;
                int b = b0 + bl;
                float4 v = make_float4(0.f, 0.f, 0.f, 0.f);
                if (b < B) v = __ldcg(((const float4*)(hp + dirbase + (size_t)b * 300)) + q);
                ((float4*)Hs)[idx] = v;
            }
        }
        __syncthreads();

        u64 acc[3][2][2] = {};
        float holdA[2] = {0.f, 0.f}, holdB[2] = {0.f, 0.f};
        if (t > 0) {
            const ulonglong2* w0p = (const ulonglong2*)(Ws + (0  + uu) * 300 + kthird * 100);
            const ulonglong2* w1p = (const ulonglong2*)(Ws + (0  + uu + 5) * 300 + kthird * 100);
            const ulonglong2* z0p = (const ulonglong2*)(Ws + (10 + uu) * 300 + kthird * 100);
            const ulonglong2* z1p = (const ulonglong2*)(Ws + (10 + uu + 5) * 300 + kthird * 100);
            const ulonglong2* n0p = (const ulonglong2*)(Ws + (20 + uu) * 300 + kthird * 100);
            const ulonglong2* n1p = (const ulonglong2*)(Ws + (20 + uu + 5) * 300 + kthird * 100);
            const ulonglong2* hA = (const ulonglong2*)(Hs + brow * 300 + kthird * 100);
#pragma unroll 5
            for (int q = 0; q < 25; q++) {
                ulonglong2 ha = hA[q], hb = hA[q + 2400];
                ulonglong2 w;
                w = w0p[q];
                acc[0][0][0] = f2fma(ha.x, w.x, acc[0][0][0]); acc[0][0][0] = f2fma(ha.y, w.y, acc[0][0][0]);
                acc[0][0][1] = f2fma(hb.x, w.x, acc[0][0][1]); acc[0][0][1] = f2fma(hb.y, w.y, acc[0][0][1]);
                w = w1p[q];
                acc[0][1][0] = f2fma(ha.x, w.x, acc[0][1][0]); acc[0][1][0] = f2fma(ha.y, w.y, acc[0][1][0]);
                acc[0][1][1] = f2fma(hb.x, w.x, acc[0][1][1]); acc[0][1][1] = f2fma(hb.y, w.y, acc[0][1][1]);
                w = z0p[q];
                acc[1][0][0] = f2fma(ha.x, w.x, acc[1][0][0]); acc[1][0][0] = f2fma(ha.y, w.y, acc[1][0][0]);
                acc[1][0][1] = f2fma(hb.x, w.x, acc[1][0][1]); acc[1][0][1] = f2fma(hb.y, w.y, acc[1][0][1]);
                w = z1p[q];
                acc[1][1][0] = f2fma(ha.x, w.x, acc[1][1][0]); acc[1][1][0] = f2fma(ha.y, w.y, acc[1][1][0]);
                acc[1][1][1] = f2fma(hb.x, w.x, acc[1][1][1]); acc[1][1][1] = f2fma(hb.y, w.y, acc[1][1][1]);
                w = n0p[q];
                acc[2][0][0] = f2fma(ha.x, w.x, acc[2][0][0]); acc[2][0][0] = f2fma(ha.y, w.y, acc[2][0][0]);
                acc[2][0][1] = f2fma(hb.x, w.x, acc[2][0][1]); acc[2][0][1] = f2fma(hb.y, w.y, acc[2][0][1]);
                w = n1p[q];
                acc[2][1][0] = f2fma(ha.x, w.x, acc[2][1][0]); acc[2][1][0] = f2fma(ha.y, w.y, acc[2][1][0]);
                acc[2][1][1] = f2fma(hb.x, w.x, acc[2][1][1]); acc[2][1][1] = f2fma(hb.y, w.y, acc[2][1][1]);
            }
            if (kthird == 0) {
                holdA[0] = okA ? Hs[brow * 300 + j0] : 0.f;
                holdA[1] = okA ? Hs[brow * 300 + j1] : 0.f;
                holdB[0] = okB ? Hs[(brow + 32) * 300 + j0] : 0.f;
                holdB[1] = okB ? Hs[(brow + 32) * 300 + j1] : 0.f;
            }
            __syncthreads();
            if (kthird > 0) {
                u64* rp = red + ((size_t)(kthird - 1) * 160 + lig) * 12;
#pragma unroll
                for (int g = 0; g < 3; g++)
#pragma unroll
                    for (int uq = 0; uq < 2; uq++) {
                        rp[(g * 2 + uq) * 2 + 0] = acc[g][uq][0];
                        rp[(g * 2 + uq) * 2 + 1] = acc[g][uq][1];
                    }
            }
            __syncthreads();
            if (kthird == 0) {
#pragma unroll
                for (int kt = 0; kt < 2; kt++) {
                    const u64* rp = red + ((size_t)kt * 160 + lig) * 12;
#pragma unroll
                    for (int g = 0; g < 3; g++)
#pragma unroll
                        for (int uq = 0; uq < 2; uq++) {
                            acc[g][uq][0] = f2add(acc[g][uq][0], rp[(g * 2 + uq) * 2 + 0]);
                            acc[g][uq][1] = f2add(acc[g][uq][1], rp[(g * 2 + uq) * 2 + 1]);
                        }
                }
            }
        }

        if (kthird == 0) {
#pragma unroll
            for (int h = 0; h < 2; h++) {
                int b = h ? b_hi : b_lo;
                bool ok = h ? okB : okA;
                if (!ok) continue;
                int len = h ? lenB : lenA;
                bool msk = (MODE != 0) || (t < len);
#pragma unroll
                for (int uq = 0; uq < 2; uq++) {
                    int jj = uq ? j1 : j0;
                    float hold = h ? holdB[uq] : holdA[uq];
                    float r = sigf(gr[h][uq][0] + hsum2(acc[0][uq][h]) + bh[0][uq]);
                    float z = sigf(gr[h][uq][1] + hsum2(acc[1][uq][h]) + bh[1][uq]);
                    float n = tanhf(gr[h][uq][2] + r * (hsum2(acc[2][uq][h]) + bh[2][uq]));
                    float hnew = (1.f - z) * n + z * hold;
                    if (MODE == 0) {
                        hn[dirbase + (size_t)b * 300 + jj] = msk ? hnew : hold;
                        float mp = msk ? hnew : 0.f;
                        if (h) mpB[uq] = fmaxf(mpB[uq], mp);
                        else   mpA[uq] = fmaxf(mpA[uq], mp);
                    } else {
                        hn[dirbase + (size_t)b * 300 + jj] = hnew;
                        seqout[(((size_t)dir * T + t) * B + b) * 300 + jj] = hnew;
                    }
                }
            }
            if (t + 1 < T) {
                int tn = t + 1;
#pragma unroll
                for (int h = 0; h < 2; h++) {
                    int b = h ? b_hi : b_lo;
                    bool ok = h ? okB : okA;
                    int len = h ? lenB : lenA;
                    if (!ok) continue;
                    if (MODE == 0) {
                        int trow = (dir == 0) ? tn : max(len - 1 - tn, 0);
                        const float* grp = gi + ((size_t)trow * B + b) * 1800 + dir * 900;
#pragma unroll
                        for (int g = 0; g < 3; g++) {
                            gr[h][0][g] = grp[g * 300 + j0];
                            gr[h][1][g] = grp[g * 300 + j1];
                        }
                    } else {
                        int trow = (dir == 0) ? tn : (T - 1 - tn);
                        int src = b + 1 - KF + trow;
                        if (src >= 0) {
                            const float* grp = gi + (size_t)src * 1800 + dir * 900;
#pragma unroll
                            for (int g = 0; g < 3; g++) {
                                gr[h][0][g] = grp[g * 300 + j0];
                                gr[h][1][g] = grp[g * 300 + j1];
                            }
                        } else {
#pragma unroll
                            for (int g = 0; g < 3; g++) {
                                gr[h][0][g] = bi[g][0];
                                gr[h][1][g] = bi[g][1];
                            }
                        }
                    }
                }
            }
        }
        cur ^= 1;
        if (t < T - 1) blk_barrier(gslot, 30u, gen0 + (unsigned)t + 1u);
    }

    if (MODE == 0 && kthird == 0) {
#pragma unroll
        for (int uq = 0; uq < 2; uq++) {
            int jj = uq ? j1 : j0;
            if (okA) maxpool[b_lo * (2 * HDIM) + dir * HDIM + jj] = mpA[uq];
            if (okB) maxpool[b_hi * (2 * HDIM) + dir * HDIM + jj] = mpB[uq];
        }
    }
}

// ---------------- fused attention: score + 3 hop scans + query update -------
__global__ __launch_bounds__(480, 1)
void att_scan7(float* __restrict__ h0, float* __restrict__ h1,
               const float* __restrict__ xr,
               const float* __restrict__ xw,
               const float* __restrict__ Ur,
               const float* __restrict__ Uw,
               const float* __restrict__ bur,
               const float* __restrict__ bu,
               float* __restrict__ gates,
               const float* __restrict__ mem,
               float* __restrict__ query)
{
    extern __shared__ float sm[];
    float* Ws = sm;                      // 6000 floats (persists per hop)
    float* Hs = sm + 6000;               // 19200 floats (score scratch too)
    u64*   red = (u64*)(sm + 25200);     // 2560 u64

    const int tid    = threadIdx.x;
    const int brow   = tid & 31;
    const int uu     = (tid >> 5) % 5;
    const int kthird = tid / 160;
    const int lig    = tid - kthird * 160;
    const int jgrp = blockIdx.x, bgrp = blockIdx.y, dir = blockIdx.z;
    const int flat = (dir * 2 + bgrp) * 30 + jgrp;   // 0..119
    const int j0 = jgrp * 10 + uu;
    const int j1 = j0 + 5;
    const int dirbase = dir * NQ * HDIM;
    const int b0 = bgrp * 64;
    const int b_lo = b0 + brow, b_hi = b_lo + 32;
    const int gslot = (dir * 2 + bgrp) * 32;

    // base generations captured before ANY arrival (first arrivals happen
    // after full barrier #1, which requires every block to have entered)
    unsigned grp_t  = *(volatile unsigned*)&g_gen[gslot];
    unsigned full_t = *(volatile unsigned*)&g_gen[FULLSLOT];

    const bool okA = (b_lo < NQ), okB = (b_hi < NQ);
    const int lane = tid & 31, wrp = tid >> 5;       // for score phase

    for (int hop = 0; hop < NHOPS; hop++) {
        const int wd = hop * 2 + dir;

        // ---- stage weights for this hop ----
        for (int idx = tid; idx < 1500; idx += 480) {
            int row = idx / 75, q = idx % 75;
            int g = row / 10, ju = row % 10;
            const float* Wsrc = g ? Uw : Ur;
            ((float4*)Ws)[row * 75 + q] = ((const float4*)(Wsrc +
                ((size_t)wd * 300 + jgrp * 10 + ju) * 300))[q];
        }
        float bv[2][2];
        bv[0][0] = bur[wd * 300 + j0]; bv[0][1] = bur[wd * 300 + j1];
        bv[1][0] = bu[wd * 300 + j0];  bv[1][1] = bu[wd * 300 + j1];

        // ---- SCORE phase: rows ii = flat, flat+120 (Hs region as scratch) ----
        {
            float* qb = Hs;           // 300 floats
            float* lg = Hs + 304;     // 40 floats
            for (int ii = flat; ii < NQ; ii += 120) {
                __syncthreads();
                for (int i = tid; i < HDIM; i += 480) qb[i] = query[ii * HDIM + i];
                __syncthreads();
                for (int k = wrp; k < KF; k += 15) {
                    const float* mrow = mem + ((size_t)k * NQ + ii) * HDIM;
                    float s = 0.f;
                    for (int i = lane; i < HDIM; i += 32) s += qb[i] * mrow[i];
                    for (int o = 16; o > 0; o >>= 1) s += __shfl_xor_sync(0xffffffffu, s, o);
                    if (lane == 0) lg[k] = (k >= KF - 1 - ii) ? s : -1e10f;
                }
                __syncthreads();
                if (wrp == 0) {
                    float m = -INFINITY;
                    for (int k = lane; k < KF; k += 32) m = fmaxf(m, lg[k]);
                    for (int o = 16; o > 0; o >>= 1) m = fmaxf(m, __shfl_xor_sync(0xffffffffu, m, o));
                    float ssum = 0.f;
                    for (int k = lane; k < KF; k += 32) { float e = expf(lg[k] - m); lg[k] = e; ssum += e; }
                    for (int o = 16; o > 0; o >>= 1) ssum += __shfl_xor_sync(0xffffffffu, ssum, o);
                    for (int k = lane; k < KF; k += 32) gates[k * NQ + ii] = lg[k] / ssum;
                }
            }
        }
        blk_barrier(FULLSLOT, 120u, ++full_t);   // gates visible everywhere

        // ---- prefetch step-0 inputs ----
        float xrv[2][2], xwv[2][2], gv[2];
        if (kthird == 0) {
            int tt0 = (dir == 0) ? 0 : (KF - 1);
#pragma unroll
            for (int h = 0; h < 2; h++) {
                int b = h ? b_hi : b_lo;
                bool ok = h ? okB : okA;
                if (ok) {
                    size_t base = ((size_t)tt0 * NQ + b) * 1800 + wd * 300;
                    xrv[h][0] = xr[base + j0]; xrv[h][1] = xr[base + j1];
                    xwv[h][0] = xw[base + j0]; xwv[h][1] = xw[base + j1];
                    gv[h] = gates[tt0 * NQ + b];
                }
            }
        }

        // ---- SCAN phase: 40 steps ----
        int cur = 0;
        for (int t = 0; t < KF; t++) {
            const float* hp = cur ? h1 : h0;
            float*       hn = cur ? h0 : h1;

            if (t > 0) {
                for (int idx = tid; idx < 4800; idx += 480) {
                    int bl = idx / 75, q = idx % 75;
                    int b = b0 + bl;
                    float4 v = make_float4(0.f, 0.f, 0.f, 0.f);
                    if (b < NQ) v = __ldcg(((const float4*)(hp + dirbase + (size_t)b * 300)) + q);
                    ((float4*)Hs)[idx] = v;
                }
            }
            __syncthreads();

            u64 acc[2][2][2] = {};
            float holdA[2] = {0.f, 0.f}, holdB[2] = {0.f, 0.f};
            if (t > 0) {
                const ulonglong2* r0p = (const ulonglong2*)(Ws + (0  + uu) * 300 + kthird * 100);
                const ulonglong2* r1p = (const ulonglong2*)(Ws + (0  + uu + 5) * 300 + kthird * 100);
                const ulonglong2* w0p = (const ulonglong2*)(Ws + (10 + uu) * 300 + kthird * 100);
                const ulonglong2* w1p = (const ulonglong2*)(Ws + (10 + uu + 5) * 300 + kthird * 100);
                const ulonglong2* hA = (const ulonglong2*)(Hs + brow * 300 + kthird * 100);
#pragma unroll 5
                for (int q = 0; q < 25; q++) {
                    ulonglong2 ha = hA[q], hb = hA[q + 2400];
                    ulonglong2 w;
                    w = r0p[q];
                    acc[0][0][0] = f2fma(ha.x, w.x, acc[0][0][0]); acc[0][0][0] = f2fma(ha.y, w.y, acc[0][0][0]);
                    acc[0][0][1] = f2fma(hb.x, w.x, acc[0][0][1]); acc[0][0][1] = f2fma(hb.y, w.y, acc[0][0][1]);
                    w = r1p[q];
                    acc[0][1][0] = f2fma(ha.x, w.x, acc[0][1][0]); acc[0][1][0] = f2fma(ha.y, w.y, acc[0][1][0]);
                    acc[0][1][1] = f2fma(hb.x, w.x, acc[0][1][1]); acc[0][1][1] = f2fma(hb.y, w.y, acc[0][1][1]);
                    w = w0p[q];
                    acc[1][0][0] = f2fma(ha.x, w.x, acc[1][0][0]); acc[1][0][0] = f2fma(ha.y, w.y, acc[1][0][0]);
                    acc[1][0][1] = f2fma(hb.x, w.x, acc[1][0][1]); acc[1][0][1] = f2fma(hb.y, w.y, acc[1][0][1]);
                    w = w1p[q];
                    acc[1][1][0] = f2fma(ha.x, w.x, acc[1][1][0]); acc[1][1][0] = f2fma(ha.y, w.y, acc[1][1][0]);
                    acc[1][1][1] = f2fma(hb.x, w.x, acc[1][1][1]); acc[1][1][1] = f2fma(hb.y, w.y, acc[1][1][1]);
                }
                if (kthird == 0) {
                    holdA[0] = okA ? Hs[brow * 300 + j0] : 0.f;
                    holdA[1] = okA ? Hs[brow * 300 + j1] : 0.f;
                    holdB[0] = okB ? Hs[(brow + 32) * 300 + j0] : 0.f;
                    holdB[1] = okB ? Hs[(brow + 32) * 300 + j1] : 0.f;
                }
                __syncthreads();
                if (kthird > 0) {
                    u64* rp = red + ((size_t)(kthird - 1) * 160 + lig) * 8;
#pragma unroll
                    for (int g = 0; g < 2; g++)
#pragma unroll
                        for (int uq = 0; uq < 2; uq++) {
                            rp[(g * 2 + uq) * 2 + 0] = acc[g][uq][0];
                            rp[(g * 2 + uq) * 2 + 1] = acc[g][uq][1];
                        }
                }
                __syncthreads();
                if (kthird == 0) {
#pragma unroll
                    for (int kt = 0; kt < 2; kt++) {
                        const u64* rp = red + ((size_t)kt * 160 + lig) * 8;
#pragma unroll
                        for (int g = 0; g < 2; g++)
#pragma unroll
                            for (int uq = 0; uq < 2; uq++) {
                                acc[g][uq][0] = f2add(acc[g][uq][0], rp[(g * 2 + uq) * 2 + 0]);
                                acc[g][uq][1] = f2add(acc[g][uq][1], rp[(g * 2 + uq) * 2 + 1]);
                            }
                    }
                }
            }

            if (kthird == 0) {
#pragma unroll
                for (int h = 0; h < 2; h++) {
                    int b = h ? b_hi : b_lo;
                    bool ok = h ? okB : okA;
                    if (!ok) continue;
#pragma unroll
                    for (int uq = 0; uq < 2; uq++) {
                        int jj = uq ? j1 : j0;
                        float hold = h ? holdB[uq] : holdA[uq];
                        float r  = sigf(xrv[h][uq] + hsum2(acc[0][uq][h]) + bv[0][uq]);
                        float ht = tanhf(xwv[h][uq] + r * (hsum2(acc[1][uq][h]) + bv[1][uq]));
                        hn[dirbase + (size_t)b * 300 + jj] = gv[h] * ht + (1.f - gv[h]) * hold;
                    }
                }
                if (t + 1 < KF) {
                    int tn = (dir == 0) ? (t + 1) : (KF - 2 - t);
#pragma unroll
                    for (int h = 0; h < 2; h++) {
                        int b = h ? b_hi : b_lo;
                        bool ok = h ? okB : okA;
                        if (ok) {
                            size_t base = ((size_t)tn * NQ + b) * 1800 + wd * 300;
                            xrv[h][0] = xr[base + j0]; xrv[h][1] = xr[base + j1];
                            xwv[h][0] = xw[base + j0]; xwv[h][1] = xw[base + j1];
                            gv[h] = gates[tn * NQ + b];
                        }
                    }
                }
            }
            cur ^= 1;
            if (t < KF - 1) blk_barrier(gslot, 30u, ++grp_t);
        }
        blk_barrier(FULLSLOT, 120u, ++full_t);   // hA (in h0) visible everywhere

        // ---- ADD2 phase: query += hAf + hAb ----
        for (int idx = flat * 480 + tid; idx < NQ * HDIM; idx += 120 * 480)
            query[idx] += __ldcg(h0 + idx) + __ldcg(h0 + NQ * HDIM + idx);
        blk_barrier(FULLSLOT, 120u, ++full_t);   // query visible for next hop
    }
}

// ---------------- small kernels ----------------
__global__ __launch_bounds__(256)
void lin_kernel(const float* __restrict__ mp, const float* __restrict__ w,
                const float* __restrict__ bsc, float* __restrict__ u) {
    int b = blockIdx.x;
    __shared__ float m[600];
    for (int i = threadIdx.x; i < 600; i += 256) m[i] = mp[b * 600 + i];
    __syncthreads();
    int wid = threadIdx.x >> 5, lane = threadIdx.x & 31;
    for (int j = wid; j < HDIM; j += 8) {
        float acc = 0.f;
        const float* wr = w + (size_t)j * 600;
        for (int k = lane; k < 600; k += 32) acc += m[k] * wr[k];
        for (int o = 16; o > 0; o >>= 1) acc += __shfl_xor_sync(0xffffffffu, acc, o);
        if (lane == 0) u[b * HDIM + j] = tanhf(acc + bsc[j]);
    }
}

__global__ void build_inp0(const float* __restrict__ u, float* __restrict__ inp0) {
    int idx = blockIdx.x * blockDim.x + threadIdx.x;
    if (idx >= KF * NQ * HDIM) return;
    int j = idx % HDIM;
    int r = idx / HDIM;
    int i = r % NQ;
    int k = r / NQ;
    int src = (i + 1) - KF + k;
    inp0[idx] = (src >= 0) ? u[src * HDIM + j] : 0.f;
}

__global__ void membank_kernel(const float* __restrict__ inp0,
                               const float* __restrict__ seq,
                               float* __restrict__ mem) {
    int idx = blockIdx.x * blockDim.x + threadIdx.x;
    if (idx >= KF * NQ * HDIM) return;
    int j = idx % HDIM;
    int r = idx / HDIM;
    int i = r % NQ;
    int k = r / NQ;
    float f = seq[((size_t)k) * NQ * HDIM + i * HDIM + j];
    float b = seq[((size_t)KF + (KF - 1 - k)) * NQ * HDIM + i * HDIM + j];
    mem[idx] = inp0[idx] + f + b;
}

__global__ void cls_kernel(const float* __restrict__ u,
                           const float* __restrict__ query,
                           const float* __restrict__ cls_w,
                           const float* __restrict__ cls_b,
                           float* __restrict__ out) {
    int row = blockIdx.x;
    int w = threadIdx.x >> 5, lane = threadIdx.x & 31;
    const float* s = (row == 0) ? u : (query + (row - 1) * HDIM);
    float acc = 0.f;
    for (int i = lane; i < HDIM; i += 32) acc += s[i] * cls_w[w * HDIM + i];
    for (int o = 16; o > 0; o >>= 1) acc += __shfl_xor_sync(0xffffffffu, acc, o);
    if (lane == 0) out[row * NCLS + w] = acc + cls_b[w];
}

// ---------------- host orchestration ----------------
extern "C" void kernel_launch(void* const* d_in, const int* in_sizes, int n_in,
                              void* d_out, int out_size) {
    const int*   ids      = (const int*)d_in[0];
    const int*   seq_lens = (const int*)d_in[1];
    const float* emb      = (const float*)d_in[2];
    const float* utt_Wih  = (const float*)d_in[3];
    const float* utt_Whh  = (const float*)d_in[4];
    const float* utt_bih  = (const float*)d_in[5];
    const float* utt_bhh  = (const float*)d_in[6];
    const float* lin_w    = (const float*)d_in[7];
    const float* lin_b    = (const float*)d_in[8];
    const float* ctx_Wih  = (const float*)d_in[9];
    const float* ctx_Whh  = (const float*)d_in[10];
    const float* ctx_bih  = (const float*)d_in[11];
    const float* ctx_bhh  = (const float*)d_in[12];
    const float* aWr_w    = (const float*)d_in[13];
    const float* aWr_b    = (const float*)d_in[14];
    const float* aUr_w    = (const float*)d_in[15];
    const float* aUr_b    = (const float*)d_in[16];
    const float* aW_w     = (const float*)d_in[17];
    const float* aW_b     = (const float*)d_in[18];
    const float* aU_w     = (const float*)d_in[19];
    const float* aU_b     = (const float*)d_in[20];
    const float* cls_w    = (const float*)d_in[21];
    const float* cls_b    = (const float*)d_in[22];
    float* out = (float*)d_out;

    float *gi_utt, *h_utt, *maxpool, *u, *inp0, *proj, *seq_ctx, *h_ctx;
    float *mem, *xr, *xw, *gates, *query, *h_att;
    cudaGetSymbolAddress((void**)&gi_utt,  g_gi_utt);
    cudaGetSymbolAddress((void**)&h_utt,   g_h_utt);
    cudaGetSymbolAddress((void**)&maxpool, g_maxpool);
    cudaGetSymbolAddress((void**)&u,       g_u);
    cudaGetSymbolAddress((void**)&inp0,    g_inp0);
    cudaGetSymbolAddress((void**)&proj,    g_proj);
    cudaGetSymbolAddress((void**)&seq_ctx, g_seq_ctx);
    cudaGetSymbolAddress((void**)&h_ctx,   g_h_ctx);
    cudaGetSymbolAddress((void**)&mem,     g_mem);
    cudaGetSymbolAddress((void**)&xr,      g_xr);
    cudaGetSymbolAddress((void**)&xw,      g_xw);
    cudaGetSymbolAddress((void**)&gates,   g_gates);
    cudaGetSymbolAddress((void**)&query,   g_query);
    cudaGetSymbolAddress((void**)&h_att,   g_h_att);

    float* hU0 = h_utt;  float* hU1 = h_utt + 2 * NB * HDIM;
    float* hC0 = h_ctx;  float* hC1 = h_ctx + 2 * NQ * HDIM;
    float* hA0 = h_att;  float* hA1 = h_att + 2 * NQ * HDIM;

    const int GRU_SMEM = 28200 * 4 + 3840 * 8;   // 143520 B
    const int ATT_SMEM = 25200 * 4 + 2560 * 8;   // 121280 B
    cudaFuncSetAttribute(gru_scan7<0>, cudaFuncAttributeMaxDynamicSharedMemorySize, GRU_SMEM);
    cudaFuncSetAttribute(gru_scan7<1>, cudaFuncAttributeMaxDynamicSharedMemorySize, GRU_SMEM);
    cudaFuncSetAttribute(att_scan7,    cudaFuncAttributeMaxDynamicSharedMemorySize, ATT_SMEM);

    cudaStream_t s = 0;
    dim3 sg(30, 2, 2);

    // ---- utterance GRU input projection (gathered emb; 128x64 tiles) ----
    {
        dim3 g((1800 + GTN - 1) / GTN, (LSEQ * NB + G5M - 1) / G5M);
        gemm5<1><<<g, 256, 0, s>>>(nullptr, 0, utt_Wih, utt_bih,
                                   gi_utt, 1800, LSEQ * NB, 1800, EDIM, emb, ids);
    }
    // ---- utterance GRU scan (ONE persistent launch) ----
    gru_scan7<0><<<sg, 480, GRU_SMEM, s>>>(hU0, hU1, gi_utt, utt_Whh, utt_bhh,
                                           nullptr, seq_lens, maxpool, nullptr,
                                           NB, LSEQ);

    // ---- u = tanh(maxpool @ lin_w^T + lin_b) ----
    lin_kernel<<<NB, 256, 0, s>>>(maxpool, lin_w, lin_b, u);

    // ---- ctx projection DEDUPED (32-row tiles -> 116 blocks) ----
    {
        dim3 g((1800 + GTN - 1) / GTN, (NQ + 31) / 32);
        gemm4n<<<g, 256, 0, s>>>(u, HDIM, ctx_Wih, ctx_bih,
                                 proj, 1800, NQ, 1800, HDIM);
    }
    build_inp0<<<(KF * NQ * HDIM + 255) / 256, 256, 0, s>>>(u, inp0);

    // ---- ctx GRU scan (gi gathered from proj127 inside the kernel) ----
    gru_scan7<1><<<sg, 480, GRU_SMEM, s>>>(hC0, hC1, proj, ctx_Whh, ctx_bhh,
                                           ctx_bih, nullptr, nullptr, seq_ctx,
                                           NQ, KF);

    membank_kernel<<<(KF * NQ * HDIM + 255) / 256, 256, 0, s>>>(inp0, seq_ctx, mem);

    // ---- attention x-projections (hop-invariant; 128x64 tiles) ----
    {
        dim3 g((1800 + GTN - 1) / GTN, (KF * NQ + G5M - 1) / G5M);
        gemm5<0><<<g, 256, 0, s>>>(mem, HDIM, aWr_w, aWr_b,
                                   xr, 1800, KF * NQ, 1800, HDIM, nullptr, nullptr);
        gemm5<0><<<g, 256, 0, s>>>(mem, HDIM, aW_w, aW_b,
                                   xw, 1800, KF * NQ, 1800, HDIM, nullptr, nullptr);
    }

    // ---- fused attention: query init, then ONE persistent kernel ----
    cudaMemcpyAsync(query, u + HDIM, NQ * HDIM * sizeof(float),
                    cudaMemcpyDeviceToDevice, s);
    att_scan7<<<sg, 480, ATT_SMEM, s>>>(hA0, hA1, xr, xw,
                                        aUr_w, aU_w, aUr_b, aU_b,
                                        gates, mem, query);

    // ---- classifier ----
    cls_kernel<<<NB, 192, 0, s>>>(u, query, cls_w, cls_b, out);
}